// round 2
// baseline (speedup 1.0000x reference)
#include <cuda_runtime.h>
#include <cuda_bf16.h>
#include <math.h>

// Problem constants
#define Dm   1024
#define Hh   16
#define DKk  64
#define Ee   8
#define DFFf 4096
#define Ss   2048
#define Bb   2
#define Tt   (Bb * Ss)      // 4096 tokens
#define NPAIR (Tt * 2)      // 8192 (token, slot) pairs
#define LISTCAP 8192        // worst case: all pairs to one expert

// ---------------------------------------------------------------------------
// Static device scratch (allocation-free rule: __device__ globals)
// ---------------------------------------------------------------------------
__device__ float g_h1[(size_t)Tt * Dm];            // LN1 output           16 MB
__device__ float g_qkv[(size_t)Tt * 3 * Dm];       // QKV                  48 MB
__device__ float g_attno[(size_t)Tt * Dm];         // attention out        16 MB
__device__ float g_h2[(size_t)Tt * Dm];            // LN2 output           16 MB
__device__ float g_hid[(size_t)NPAIR * DFFf];      // MoE hidden          128 MB
__device__ float g_moeo[(size_t)NPAIR * Dm];       // MoE per-pair out     32 MB
__device__ int   g_cnt[Ee];
__device__ int   g_tok[Ee * LISTCAP];              // token index per pair
__device__ int   g_dst[Ee * LISTCAP];              // pair row (= t*2+k)
__device__ float g_gw[NPAIR];                      // combine weight per pair

// ---------------------------------------------------------------------------
// LayerNorm: one block per token
// ---------------------------------------------------------------------------
__global__ void ln_kernel(const float* __restrict__ x,
                          const float* __restrict__ g,
                          const float* __restrict__ b,
                          float* __restrict__ out)
{
    int t = blockIdx.x;
    const float* xr = x + (size_t)t * Dm;
    float s = 0.f, s2 = 0.f;
    for (int d = threadIdx.x; d < Dm; d += 256) {
        float v = xr[d];
        s += v; s2 += v * v;
    }
    #pragma unroll
    for (int off = 16; off; off >>= 1) {
        s  += __shfl_xor_sync(0xffffffffu, s, off);
        s2 += __shfl_xor_sync(0xffffffffu, s2, off);
    }
    __shared__ float sh[18];
    int w = threadIdx.x >> 5;
    if ((threadIdx.x & 31) == 0) { sh[w] = s; sh[w + 8] = s2; }
    __syncthreads();
    if (threadIdx.x == 0) {
        float ts = 0.f, ts2 = 0.f;
        #pragma unroll
        for (int i = 0; i < 8; i++) { ts += sh[i]; ts2 += sh[i + 8]; }
        sh[16] = ts; sh[17] = ts2;
    }
    __syncthreads();
    float mean = sh[16] * (1.0f / Dm);
    float var  = sh[17] * (1.0f / Dm) - mean * mean;
    float rstd = rsqrtf(var + 1e-5f);
    float* orow = out + (size_t)t * Dm;
    for (int d = threadIdx.x; d < Dm; d += 256)
        orow[d] = (xr[d] - mean) * rstd * g[d] + b[d];
}

// ---------------------------------------------------------------------------
// Tiled SGEMM, 128x128x8 tile, 256 threads, 8x8 micro-tile.
// C[M,N] = op(A@B + bias) (+resid). MOE: per-expert (blockIdx.z) with
// dynamic M = cnt[z], gathered A rows (a_idx) and scattered C rows (c_idx).
// ---------------------------------------------------------------------------
template<bool MOE, bool RELU, bool RESID>
__global__ __launch_bounds__(256, 2)
void sgemm_kernel(const float* __restrict__ A,
                  const float* __restrict__ B,
                  float* __restrict__ C,
                  const float* __restrict__ bias,
                  const float* __restrict__ resid,
                  const int* __restrict__ a_idx,
                  const int* __restrict__ c_idx,
                  const int* __restrict__ cnt,
                  int M, int K, int N)
{
    int z = 0;
    if (MOE) {
        z = blockIdx.z;
        M = cnt[z];
        B    += (size_t)z * K * N;
        bias += (size_t)z * N;
        a_idx += z * LISTCAP;
        c_idx += z * LISTCAP;
    }
    int m0 = blockIdx.y * 128;
    if (m0 >= M) return;
    int n0 = blockIdx.x * 128;

    __shared__ float As[8][128];
    __shared__ float Bs[8][128];

    int tid = threadIdx.x;
    int tx = tid & 15, ty = tid >> 4;

    float acc[8][8] = {};

    // A loader: each thread loads one float4 of a 128x8 tile
    int la_r = tid >> 1;
    int la_k = (tid & 1) * 4;
    int arow = m0 + la_r;
    bool a_valid = arow < M;
    const float* Aptr = nullptr;
    if (a_valid) {
        int gr = MOE ? a_idx[arow] : arow;
        Aptr = A + (size_t)gr * K + la_k;
    }
    // B loader: each thread loads one float4 of an 8x128 tile
    int lb_k = tid >> 5;
    int lb_n = (tid & 31) * 4;
    const float* Bptr = B + (size_t)lb_k * N + n0 + lb_n;

    for (int k0 = 0; k0 < K; k0 += 8) {
        float4 av = a_valid ? *(const float4*)(Aptr + k0)
                            : make_float4(0.f, 0.f, 0.f, 0.f);
        float4 bv = *(const float4*)(Bptr + (size_t)k0 * N);
        __syncthreads();
        As[la_k + 0][la_r] = av.x;
        As[la_k + 1][la_r] = av.y;
        As[la_k + 2][la_r] = av.z;
        As[la_k + 3][la_r] = av.w;
        *(float4*)&Bs[lb_k][lb_n] = bv;
        __syncthreads();
        #pragma unroll
        for (int kk = 0; kk < 8; kk++) {
            float ar[8], br[8];
            *(float4*)&ar[0] = *(const float4*)&As[kk][ty * 8];
            *(float4*)&ar[4] = *(const float4*)&As[kk][ty * 8 + 4];
            *(float4*)&br[0] = *(const float4*)&Bs[kk][tx * 8];
            *(float4*)&br[4] = *(const float4*)&Bs[kk][tx * 8 + 4];
            #pragma unroll
            for (int i = 0; i < 8; i++)
                #pragma unroll
                for (int j = 0; j < 8; j++)
                    acc[i][j] = fmaf(ar[i], br[j], acc[i][j]);
        }
    }

    #pragma unroll
    for (int i = 0; i < 8; i++) {
        int r = m0 + ty * 8 + i;
        if (r >= M) break;
        int cr = MOE ? c_idx[r] : r;
        float* Crow = C + (size_t)cr * N;
        const float* Rrow = RESID ? (resid + (size_t)r * N) : nullptr;
        #pragma unroll
        for (int j = 0; j < 8; j++) {
            int c = n0 + tx * 8 + j;
            float v = acc[i][j] + bias[c];
            if (RELU) v = fmaxf(v, 0.f);
            if (RESID) v += Rrow[c];
            Crow[c] = v;
        }
    }
}

// ---------------------------------------------------------------------------
// Flash attention: one CTA per (q-block 64, head, batch). fp32 online softmax.
// qkv layout: [T, 3*D], q cols [0,D), k [D,2D), v [2D,3D); head h -> h*64.
// Dynamic smem: Qs/Ks/Vs each 64x65 floats (49,920 B total, > 48KB static cap).
// ---------------------------------------------------------------------------
#define ATT_STRIDE 65
#define ATT_SMEM_BYTES (3 * 64 * ATT_STRIDE * 4)

__global__ __launch_bounds__(256)
void attn_kernel(const float* __restrict__ qkv, float* __restrict__ obuf)
{
    extern __shared__ float smem[];
    float* Qs = smem;                        // [64][65]
    float* Ks = smem + 64 * ATT_STRIDE;      // [64][65], reused as P
    float* Vs = smem + 2 * 64 * ATT_STRIDE;  // [64][65]
    #define QS(r, c) Qs[(r) * ATT_STRIDE + (c)]
    #define KS(r, c) Ks[(r) * ATT_STRIDE + (c)]
    #define VS(r, c) Vs[(r) * ATT_STRIDE + (c)]

    const int qb = blockIdx.x, h = blockIdx.y, b = blockIdx.z;
    const int tid = threadIdx.x;
    const int tx = tid & 15, ty = tid >> 4;

    const size_t base = (size_t)b * Ss * (3 * Dm);
    const int q0 = qb * 64;
    const float scale = 0.125f; // 1/sqrt(64)

    // load Q tile (scaled)
    #pragma unroll
    for (int r4 = 0; r4 < 4; r4++) {
        int idx = r4 * 256 + tid;          // 1024 float4 slots
        int row = idx >> 4;
        int c4  = (idx & 15) * 4;
        float4 v = *(const float4*)(qkv + base + (size_t)(q0 + row) * (3 * Dm) + h * 64 + c4);
        QS(row, c4 + 0) = v.x * scale;
        QS(row, c4 + 1) = v.y * scale;
        QS(row, c4 + 2) = v.z * scale;
        QS(row, c4 + 3) = v.w * scale;
    }

    float m[4] = {-1e30f, -1e30f, -1e30f, -1e30f};
    float l[4] = {0.f, 0.f, 0.f, 0.f};
    float o[4][4] = {};

    for (int kt = 0; kt < Ss; kt += 64) {
        __syncthreads();
        #pragma unroll
        for (int r4 = 0; r4 < 4; r4++) {
            int idx = r4 * 256 + tid;
            int row = idx >> 4;
            int c4  = (idx & 15) * 4;
            size_t g = base + (size_t)(kt + row) * (3 * Dm) + h * 64 + c4;
            float4 kv = *(const float4*)(qkv + g + Dm);
            float4 vv = *(const float4*)(qkv + g + 2 * Dm);
            KS(row, c4 + 0) = kv.x; KS(row, c4 + 1) = kv.y;
            KS(row, c4 + 2) = kv.z; KS(row, c4 + 3) = kv.w;
            VS(row, c4 + 0) = vv.x; VS(row, c4 + 1) = vv.y;
            VS(row, c4 + 2) = vv.z; VS(row, c4 + 3) = vv.w;
        }
        __syncthreads();

        // s = Q @ K^T (4x4 per thread)
        float s[4][4] = {};
        #pragma unroll 8
        for (int d = 0; d < 64; d++) {
            float qv[4], kv[4];
            #pragma unroll
            for (int i = 0; i < 4; i++) qv[i] = QS(ty * 4 + i, d);
            #pragma unroll
            for (int j = 0; j < 4; j++) kv[j] = KS(tx * 4 + j, d);
            #pragma unroll
            for (int i = 0; i < 4; i++)
                #pragma unroll
                for (int j = 0; j < 4; j++)
                    s[i][j] = fmaf(qv[i], kv[j], s[i][j]);
        }

        // online softmax (row stats shared across the 16-lane tx group)
        float newm[4], psum[4];
        #pragma unroll
        for (int i = 0; i < 4; i++) {
            float tm = fmaxf(fmaxf(s[i][0], s[i][1]), fmaxf(s[i][2], s[i][3]));
            #pragma unroll
            for (int off = 1; off < 16; off <<= 1)
                tm = fmaxf(tm, __shfl_xor_sync(0xffffffffu, tm, off));
            newm[i] = fmaxf(m[i], tm);
            float ps = 0.f;
            #pragma unroll
            for (int j = 0; j < 4; j++) {
                s[i][j] = __expf(s[i][j] - newm[i]);
                ps += s[i][j];
            }
            #pragma unroll
            for (int off = 1; off < 16; off <<= 1)
                ps += __shfl_xor_sync(0xffffffffu, ps, off);
            psum[i] = ps;
        }

        __syncthreads();   // everyone done reading Ks
        #pragma unroll
        for (int i = 0; i < 4; i++)
            #pragma unroll
            for (int j = 0; j < 4; j++)
                KS(ty * 4 + i, tx * 4 + j) = s[i][j];
        __syncthreads();

        #pragma unroll
        for (int i = 0; i < 4; i++) {
            float corr = __expf(m[i] - newm[i]);
            l[i] = l[i] * corr + psum[i];
            m[i] = newm[i];
            #pragma unroll
            for (int dd = 0; dd < 4; dd++) o[i][dd] *= corr;
        }

        // O += P @ V
        #pragma unroll 8
        for (int j = 0; j < 64; j++) {
            float pv[4], vv[4];
            #pragma unroll
            for (int i = 0; i < 4; i++) pv[i] = KS(ty * 4 + i, j);
            #pragma unroll
            for (int dd = 0; dd < 4; dd++) vv[dd] = VS(j, tx * 4 + dd);
            #pragma unroll
            for (int i = 0; i < 4; i++)
                #pragma unroll
                for (int dd = 0; dd < 4; dd++)
                    o[i][dd] = fmaf(pv[i], vv[dd], o[i][dd]);
        }
    }

    #pragma unroll
    for (int i = 0; i < 4; i++) {
        float inv = 1.0f / l[i];
        int t = b * Ss + q0 + ty * 4 + i;
        #pragma unroll
        for (int dd = 0; dd < 4; dd++)
            obuf[(size_t)t * Dm + h * 64 + tx * 4 + dd] = o[i][dd] * inv;
    }
}

// ---------------------------------------------------------------------------
// Gating + routing: one warp per token. Top-2 (lower index wins ties, matching
// lax.top_k), softmax over the two, atomic list append per expert.
// ---------------------------------------------------------------------------
__global__ void gate_route_kernel(const float* __restrict__ h2,
                                  const float* __restrict__ gw,
                                  const float* __restrict__ gb,
                                  int* __restrict__ cnt,
                                  int* __restrict__ tok,
                                  int* __restrict__ dst,
                                  float* __restrict__ gw2)
{
    int t = blockIdx.x * 8 + (threadIdx.x >> 5);
    int lane = threadIdx.x & 31;
    const float* xr = h2 + (size_t)t * Dm;
    float acc[Ee] = {};
    for (int d = lane; d < Dm; d += 32) {
        float xv = xr[d];
        #pragma unroll
        for (int e = 0; e < Ee; e++)
            acc[e] = fmaf(xv, gw[d * Ee + e], acc[e]);
    }
    #pragma unroll
    for (int e = 0; e < Ee; e++)
        #pragma unroll
        for (int off = 16; off; off >>= 1)
            acc[e] += __shfl_xor_sync(0xffffffffu, acc[e], off);

    if (lane == 0) {
        float lg[Ee];
        #pragma unroll
        for (int e = 0; e < Ee; e++) lg[e] = acc[e] + gb[e];
        int i0 = 0;
        #pragma unroll
        for (int e = 1; e < Ee; e++) if (lg[e] > lg[i0]) i0 = e;
        int i1 = -1;
        #pragma unroll
        for (int e = 0; e < Ee; e++) {
            if (e == i0) continue;
            if (i1 < 0 || lg[e] > lg[i1]) i1 = e;
        }
        float e1 = expf(lg[i1] - lg[i0]);
        float denom = 1.0f / (1.0f + e1);
        float g0 = denom, g1 = e1 * denom;
        int p0 = atomicAdd(&cnt[i0], 1);
        tok[i0 * LISTCAP + p0] = t;
        dst[i0 * LISTCAP + p0] = t * 2;
        int p1 = atomicAdd(&cnt[i1], 1);
        tok[i1 * LISTCAP + p1] = t;
        dst[i1 * LISTCAP + p1] = t * 2 + 1;
        gw2[t * 2]     = g0;
        gw2[t * 2 + 1] = g1;
    }
}

// ---------------------------------------------------------------------------
// Final combine: out[t] += g0*moe_out[t,0] + g1*moe_out[t,1] (fixed order)
// ---------------------------------------------------------------------------
__global__ void combine_kernel(float* __restrict__ out,
                               const float* __restrict__ moeo,
                               const float* __restrict__ gw2)
{
    int t = blockIdx.x;
    float g0 = gw2[t * 2], g1 = gw2[t * 2 + 1];
    const float* r0 = moeo + (size_t)(t * 2) * Dm;
    const float* r1 = r0 + Dm;
    float* orow = out + (size_t)t * Dm;
    for (int d = threadIdx.x; d < Dm; d += 256)
        orow[d] += g0 * r0[d] + g1 * r1[d];
}

// ---------------------------------------------------------------------------
// Launch
// ---------------------------------------------------------------------------
extern "C" void kernel_launch(void* const* d_in, const int* in_sizes, int n_in,
                              void* d_out, int out_size)
{
    const float* x      = (const float*)d_in[0];
    const float* ln1_g  = (const float*)d_in[1];
    const float* ln1_b  = (const float*)d_in[2];
    const float* w_qkv  = (const float*)d_in[3];
    const float* b_qkv  = (const float*)d_in[4];
    const float* w_o    = (const float*)d_in[5];
    const float* b_o    = (const float*)d_in[6];
    const float* ln2_g  = (const float*)d_in[7];
    const float* ln2_b  = (const float*)d_in[8];
    const float* gate_w = (const float*)d_in[9];
    const float* gate_b = (const float*)d_in[10];
    const float* W1     = (const float*)d_in[11];
    const float* b1     = (const float*)d_in[12];
    const float* W2     = (const float*)d_in[13];
    const float* b2     = (const float*)d_in[14];
    float* out = (float*)d_out;

    float *h1, *qkv, *attno, *h2, *hid, *moeo, *gwp;
    int *cnt, *tok, *dst;
    cudaGetSymbolAddress((void**)&h1,    g_h1);
    cudaGetSymbolAddress((void**)&qkv,   g_qkv);
    cudaGetSymbolAddress((void**)&attno, g_attno);
    cudaGetSymbolAddress((void**)&h2,    g_h2);
    cudaGetSymbolAddress((void**)&hid,   g_hid);
    cudaGetSymbolAddress((void**)&moeo,  g_moeo);
    cudaGetSymbolAddress((void**)&cnt,   g_cnt);
    cudaGetSymbolAddress((void**)&tok,   g_tok);
    cudaGetSymbolAddress((void**)&dst,   g_dst);
    cudaGetSymbolAddress((void**)&gwp,   g_gw);

    // opt attention kernel into >48KB dynamic smem (non-stream API; runs
    // immediately even under graph capture, deterministic)
    static bool attr_done = false;
    if (!attr_done) {
        cudaFuncSetAttribute(attn_kernel,
                             cudaFuncAttributeMaxDynamicSharedMemorySize,
                             ATT_SMEM_BYTES);
        attr_done = true;
    }

    // zero the routing counters (memset node is graph-capturable)
    cudaMemsetAsync(cnt, 0, Ee * sizeof(int));

    // 1) LN1
    ln_kernel<<<Tt, 256>>>(x, ln1_g, ln1_b, h1);

    // 2) QKV = h1 @ w_qkv + b_qkv      [4096,1024]x[1024,3072]
    sgemm_kernel<false, false, false><<<dim3(3 * Dm / 128, Tt / 128), 256>>>(
        h1, w_qkv, qkv, b_qkv, nullptr, nullptr, nullptr, nullptr,
        Tt, Dm, 3 * Dm);

    // 3) attention
    attn_kernel<<<dim3(Ss / 64, Hh, Bb), 256, ATT_SMEM_BYTES>>>(qkv, attno);

    // 4) x1 = x + attno @ w_o + b_o  -> d_out
    sgemm_kernel<false, false, true><<<dim3(Dm / 128, Tt / 128), 256>>>(
        attno, w_o, out, b_o, x, nullptr, nullptr, nullptr,
        Tt, Dm, Dm);

    // 5) LN2 on x1
    ln_kernel<<<Tt, 256>>>(out, ln2_g, ln2_b, h2);

    // 6) gating + routing
    gate_route_kernel<<<Tt / 8, 256>>>(h2, gate_w, gate_b, cnt, tok, dst, gwp);

    // 7) MoE FFN1: hid[pair] = relu(h2[tok] @ W1[e] + b1[e])
    sgemm_kernel<true, true, false><<<dim3(DFFf / 128, LISTCAP / 128, Ee), 256>>>(
        h2, W1, hid, b1, nullptr, tok, dst, cnt,
        0, Dm, DFFf);

    // 8) MoE FFN2: moeo[pair] = hid[pair] @ W2[e] + b2[e]
    sgemm_kernel<true, false, false><<<dim3(Dm / 128, LISTCAP / 128, Ee), 256>>>(
        hid, W2, moeo, b2, nullptr, dst, dst, cnt,
        0, DFFf, Dm);

    // 9) combine: d_out += g0*moeo[t,0] + g1*moeo[t,1]
    combine_kernel<<<Tt, 256>>>(out, moeo, gwp);
}

// round 4
// speedup vs baseline: 1.8050x; 1.8050x over previous
#include <cuda_runtime.h>
#include <cuda_bf16.h>
#include <math.h>
#include <stdint.h>

// Problem constants
#define Dm   1024
#define Hh   16
#define DKk  64
#define Ee   8
#define DFFf 4096
#define Ss   2048
#define Bb   2
#define Tt   (Bb * Ss)
#define NPAIR (Tt * 2)
#define LISTCAP 8192

// ---------------------------------------------------------------------------
// Static device scratch
// ---------------------------------------------------------------------------
__device__ float g_h1[(size_t)Tt * Dm];
__device__ float g_qkv[(size_t)Tt * 3 * Dm];
__device__ float g_attno[(size_t)Tt * Dm];
__device__ float g_h2[(size_t)Tt * Dm];
__device__ float g_hid[(size_t)NPAIR * DFFf];
__device__ float g_moeo[(size_t)NPAIR * Dm];
__device__ int   g_cnt[Ee];
__device__ int   g_tok[Ee * LISTCAP];
__device__ int   g_dst[Ee * LISTCAP];
__device__ float g_gw[NPAIR];

// ---------------------------------------------------------------------------
// LayerNorm
// ---------------------------------------------------------------------------
__global__ void ln_kernel(const float* __restrict__ x,
                          const float* __restrict__ g,
                          const float* __restrict__ b,
                          float* __restrict__ out)
{
    int t = blockIdx.x;
    const float* xr = x + (size_t)t * Dm;
    float s = 0.f, s2 = 0.f;
    for (int d = threadIdx.x; d < Dm; d += 256) {
        float v = xr[d];
        s += v; s2 += v * v;
    }
    #pragma unroll
    for (int off = 16; off; off >>= 1) {
        s  += __shfl_xor_sync(0xffffffffu, s, off);
        s2 += __shfl_xor_sync(0xffffffffu, s2, off);
    }
    __shared__ float sh[18];
    int w = threadIdx.x >> 5;
    if ((threadIdx.x & 31) == 0) { sh[w] = s; sh[w + 8] = s2; }
    __syncthreads();
    if (threadIdx.x == 0) {
        float ts = 0.f, ts2 = 0.f;
        #pragma unroll
        for (int i = 0; i < 8; i++) { ts += sh[i]; ts2 += sh[i + 8]; }
        sh[16] = ts; sh[17] = ts2;
    }
    __syncthreads();
    float mean = sh[16] * (1.0f / Dm);
    float var  = sh[17] * (1.0f / Dm) - mean * mean;
    float rstd = rsqrtf(var + 1e-5f);
    float* orow = out + (size_t)t * Dm;
    for (int d = threadIdx.x; d < Dm; d += 256)
        orow[d] = (xr[d] - mean) * rstd * g[d] + b[d];
}

// ---------------------------------------------------------------------------
// bf16x3 tensor-core GEMM (fp32-accurate via hi/lo split, 3 MMAs/pair).
// 128x128x32 CTA tile, 256 threads (8 warps, each 64x32 via m16n8k16).
// cp.async double-buffered fp32 smem.
// ---------------------------------------------------------------------------
#define GBM 128
#define GBN 128
#define GBK 32
#define AS_STRIDE 36
#define BS_STRIDE 136
#define AS_SIZE (GBM * AS_STRIDE)
#define BS_SIZE (GBK * BS_STRIDE)
#define GEMM_SMEM_BYTES ((2 * (AS_SIZE + BS_SIZE)) * 4)   // 71,680 B

__device__ __forceinline__ void cp16(uint32_t dst, const void* src, int src_bytes) {
    asm volatile("cp.async.cg.shared.global [%0], [%1], 16, %2;"
                 :: "r"(dst), "l"(src), "r"(src_bytes));
}
__device__ __forceinline__ void cp_commit() {
    asm volatile("cp.async.commit_group;");
}
template<int N>
__device__ __forceinline__ void cp_wait() {
    asm volatile("cp.async.wait_group %0;" :: "n"(N));
}
// Split two floats (consecutive k: f0=k, f1=k+1) into packed bf16x2 hi & lo.
__device__ __forceinline__ void split2(float f0, float f1,
                                       uint32_t& hi, uint32_t& lo) {
    uint32_t h;
    asm("cvt.rn.bf16x2.f32 %0, %1, %2;" : "=r"(h) : "f"(f1), "f"(f0));
    float h0 = __uint_as_float(h << 16);
    float h1 = __uint_as_float(h & 0xffff0000u);
    float r0 = f0 - h0;
    float r1 = f1 - h1;
    uint32_t l;
    asm("cvt.rn.bf16x2.f32 %0, %1, %2;" : "=r"(l) : "f"(r1), "f"(r0));
    hi = h; lo = l;
}
__device__ __forceinline__ void mma_bf16(float* c, const uint32_t* a, const uint32_t* b) {
    asm volatile(
        "mma.sync.aligned.m16n8k16.row.col.f32.bf16.bf16.f32 "
        "{%0,%1,%2,%3}, {%4,%5,%6,%7}, {%8,%9}, {%0,%1,%2,%3};"
        : "+f"(c[0]), "+f"(c[1]), "+f"(c[2]), "+f"(c[3])
        : "r"(a[0]), "r"(a[1]), "r"(a[2]), "r"(a[3]), "r"(b[0]), "r"(b[1]));
}

template<bool MOE, bool RELU, bool RESID>
__global__ __launch_bounds__(256, 2)
void gemm_bf16x3(const float* __restrict__ A,
                 const float* __restrict__ B,
                 float* __restrict__ C,
                 const float* __restrict__ bias,
                 const float* __restrict__ resid,
                 const int* __restrict__ a_idx,
                 const int* __restrict__ c_idx,
                 const int* __restrict__ cnt,
                 int M, int K, int N)
{
    if (MOE) {
        int z = blockIdx.z;
        M = cnt[z];
        B    += (size_t)z * K * N;
        bias += (size_t)z * N;
        a_idx += z * LISTCAP;
        c_idx += z * LISTCAP;
    }
    const int m0 = blockIdx.y * GBM;
    if (m0 >= M) return;
    const int n0 = blockIdx.x * GBN;

    extern __shared__ float gsm[];
    float* Asm0 = gsm;
    float* Bsm0 = gsm + 2 * AS_SIZE;

    const int tid = threadIdx.x;
    const int wid = tid >> 5;
    const int lane = tid & 31;
    const int g = lane >> 2;
    const int q = lane & 3;
    const int wm = wid & 1;
    const int wn = wid >> 1;

    // --- cp.async assignments -------------------------------------------
    const int a_c4 = (tid & 7) * 4;
    const float* a_src[4];
    int a_bytes[4];
    uint32_t a_dst[4];
    #pragma unroll
    for (int i = 0; i < 4; i++) {
        int rl = (tid >> 3) + i * 32;
        int r = m0 + rl;
        bool valid = r < M;
        int gr = valid ? (MOE ? a_idx[r] : r) : 0;
        a_src[i] = A + (size_t)gr * K + a_c4;
        a_bytes[i] = valid ? 16 : 0;
        a_dst[i] = (uint32_t)__cvta_generic_to_shared(&Asm0[rl * AS_STRIDE + a_c4]);
    }
    const int b_c4 = (tid & 31) * 4;
    const float* b_src0 = B + (size_t)(tid >> 5) * N + n0 + b_c4;
    uint32_t b_dst[4];
    #pragma unroll
    for (int i = 0; i < 4; i++)
        b_dst[i] = (uint32_t)__cvta_generic_to_shared(
            &Bsm0[((tid >> 5) + i * 8) * BS_STRIDE + b_c4]);

    const uint32_t aoff = (uint32_t)(AS_SIZE * sizeof(float));
    const uint32_t boff = (uint32_t)(BS_SIZE * sizeof(float));

    const int nk = K / GBK;

    #pragma unroll
    for (int i = 0; i < 4; i++) cp16(a_dst[i], a_src[i], a_bytes[i]);
    #pragma unroll
    for (int i = 0; i < 4; i++)
        cp16(b_dst[i], b_src0 + (size_t)(i * 8) * N, 16);
    cp_commit();

    float acc[4][4][4] = {};

    int buf = 0;
    for (int kt = 0; kt < nk; kt++) {
        if (kt + 1 < nk) {
            int k0 = (kt + 1) * GBK;
            uint32_t ao = (buf ^ 1) ? aoff : 0;
            uint32_t bo = (buf ^ 1) ? boff : 0;
            #pragma unroll
            for (int i = 0; i < 4; i++) cp16(a_dst[i] + ao, a_src[i] + k0, a_bytes[i]);
            #pragma unroll
            for (int i = 0; i < 4; i++)
                cp16(b_dst[i] + bo, b_src0 + (size_t)(k0 + i * 8) * N, 16);
            cp_commit();
            cp_wait<1>();
        } else {
            cp_wait<0>();
        }
        __syncthreads();

        const float* As = Asm0 + (buf ? AS_SIZE : 0);
        const float* Bs = Bsm0 + (buf ? BS_SIZE : 0);

        #pragma unroll
        for (int ks = 0; ks < 2; ks++) {
            const int kb = ks * 16;
            // B fragments (hi+lo) for all 4 n-tiles
            uint32_t bhi[4][2], blo[4][2];
            #pragma unroll
            for (int nt = 0; nt < 4; nt++) {
                int nc = wn * 32 + nt * 8 + g;
                float f0 = Bs[(kb + 2 * q)     * BS_STRIDE + nc];
                float f1 = Bs[(kb + 2 * q + 1) * BS_STRIDE + nc];
                float f2 = Bs[(kb + 2 * q + 8) * BS_STRIDE + nc];
                float f3 = Bs[(kb + 2 * q + 9) * BS_STRIDE + nc];
                split2(f0, f1, bhi[nt][0], blo[nt][0]);
                split2(f2, f3, bhi[nt][1], blo[nt][1]);
            }
            #pragma unroll
            for (int mt = 0; mt < 4; mt++) {
                int r0 = wm * 64 + mt * 16 + g;
                int r1 = r0 + 8;
                float2 a00 = *(const float2*)&As[r0 * AS_STRIDE + kb + 2 * q];
                float2 a10 = *(const float2*)&As[r1 * AS_STRIDE + kb + 2 * q];
                float2 a01 = *(const float2*)&As[r0 * AS_STRIDE + kb + 2 * q + 8];
                float2 a11 = *(const float2*)&As[r1 * AS_STRIDE + kb + 2 * q + 8];
                uint32_t ahi[4], alo[4];
                split2(a00.x, a00.y, ahi[0], alo[0]);
                split2(a10.x, a10.y, ahi[1], alo[1]);
                split2(a01.x, a01.y, ahi[2], alo[2]);
                split2(a11.x, a11.y, ahi[3], alo[3]);
                #pragma unroll
                for (int nt = 0; nt < 4; nt++) {
                    mma_bf16(acc[mt][nt], ahi, bhi[nt]);
                    mma_bf16(acc[mt][nt], ahi, blo[nt]);
                    mma_bf16(acc[mt][nt], alo, bhi[nt]);
                }
            }
        }
        __syncthreads();
        buf ^= 1;
    }

    // --- epilogue --------------------------------------------------------
    #pragma unroll
    for (int mt = 0; mt < 4; mt++) {
        #pragma unroll
        for (int half = 0; half < 2; half++) {
            int r = m0 + wm * 64 + mt * 16 + g + half * 8;
            if (MOE && r >= M) continue;
            int cr = MOE ? c_idx[r] : r;
            float* Crow = C + (size_t)cr * N;
            const float* Rrow = RESID ? (resid + (size_t)r * N) : nullptr;
            #pragma unroll
            for (int nt = 0; nt < 4; nt++) {
                int c = n0 + wn * 32 + nt * 8 + 2 * q;
                float v0 = acc[mt][nt][half * 2 + 0] + bias[c];
                float v1 = acc[mt][nt][half * 2 + 1] + bias[c + 1];
                if (RELU) { v0 = fmaxf(v0, 0.f); v1 = fmaxf(v1, 0.f); }
                if (RESID) {
                    float2 rr = *(const float2*)(Rrow + c);
                    v0 += rr.x; v1 += rr.y;
                }
                float2 vv = make_float2(v0, v1);
                *(float2*)(Crow + c) = vv;
            }
        }
    }
}

// ---------------------------------------------------------------------------
// Flash attention (fp32, dynamic smem)
// ---------------------------------------------------------------------------
#define ATT_STRIDE 65
#define ATT_SMEM_BYTES (3 * 64 * ATT_STRIDE * 4)

__global__ __launch_bounds__(256)
void attn_kernel(const float* __restrict__ qkv, float* __restrict__ obuf)
{
    extern __shared__ float smem[];
    float* Qs = smem;
    float* Ks = smem + 64 * ATT_STRIDE;
    float* Vs = smem + 2 * 64 * ATT_STRIDE;
    #define QS(r, c) Qs[(r) * ATT_STRIDE + (c)]
    #define KS(r, c) Ks[(r) * ATT_STRIDE + (c)]
    #define VS(r, c) Vs[(r) * ATT_STRIDE + (c)]

    const int qb = blockIdx.x, h = blockIdx.y, b = blockIdx.z;
    const int tid = threadIdx.x;
    const int tx = tid & 15, ty = tid >> 4;

    const size_t base = (size_t)b * Ss * (3 * Dm);
    const int q0 = qb * 64;
    const float scale = 0.125f;

    #pragma unroll
    for (int r4 = 0; r4 < 4; r4++) {
        int idx = r4 * 256 + tid;
        int row = idx >> 4;
        int c4  = (idx & 15) * 4;
        float4 v = *(const float4*)(qkv + base + (size_t)(q0 + row) * (3 * Dm) + h * 64 + c4);
        QS(row, c4 + 0) = v.x * scale;
        QS(row, c4 + 1) = v.y * scale;
        QS(row, c4 + 2) = v.z * scale;
        QS(row, c4 + 3) = v.w * scale;
    }

    float m[4] = {-1e30f, -1e30f, -1e30f, -1e30f};
    float l[4] = {0.f, 0.f, 0.f, 0.f};
    float o[4][4] = {};

    for (int kt = 0; kt < Ss; kt += 64) {
        __syncthreads();
        #pragma unroll
        for (int r4 = 0; r4 < 4; r4++) {
            int idx = r4 * 256 + tid;
            int row = idx >> 4;
            int c4  = (idx & 15) * 4;
            size_t gg = base + (size_t)(kt + row) * (3 * Dm) + h * 64 + c4;
            float4 kv = *(const float4*)(qkv + gg + Dm);
            float4 vv = *(const float4*)(qkv + gg + 2 * Dm);
            KS(row, c4 + 0) = kv.x; KS(row, c4 + 1) = kv.y;
            KS(row, c4 + 2) = kv.z; KS(row, c4 + 3) = kv.w;
            VS(row, c4 + 0) = vv.x; VS(row, c4 + 1) = vv.y;
            VS(row, c4 + 2) = vv.z; VS(row, c4 + 3) = vv.w;
        }
        __syncthreads();

        float s[4][4] = {};
        #pragma unroll 8
        for (int d = 0; d < 64; d++) {
            float qv[4], kv[4];
            #pragma unroll
            for (int i = 0; i < 4; i++) qv[i] = QS(ty * 4 + i, d);
            #pragma unroll
            for (int j = 0; j < 4; j++) kv[j] = KS(tx * 4 + j, d);
            #pragma unroll
            for (int i = 0; i < 4; i++)
                #pragma unroll
                for (int j = 0; j < 4; j++)
                    s[i][j] = fmaf(qv[i], kv[j], s[i][j]);
        }

        float newm[4], psum[4];
        #pragma unroll
        for (int i = 0; i < 4; i++) {
            float tm = fmaxf(fmaxf(s[i][0], s[i][1]), fmaxf(s[i][2], s[i][3]));
            #pragma unroll
            for (int off = 1; off < 16; off <<= 1)
                tm = fmaxf(tm, __shfl_xor_sync(0xffffffffu, tm, off));
            newm[i] = fmaxf(m[i], tm);
            float ps = 0.f;
            #pragma unroll
            for (int j = 0; j < 4; j++) {
                s[i][j] = __expf(s[i][j] - newm[i]);
                ps += s[i][j];
            }
            #pragma unroll
            for (int off = 1; off < 16; off <<= 1)
                ps += __shfl_xor_sync(0xffffffffu, ps, off);
            psum[i] = ps;
        }

        __syncthreads();
        #pragma unroll
        for (int i = 0; i < 4; i++)
            #pragma unroll
            for (int j = 0; j < 4; j++)
                KS(ty * 4 + i, tx * 4 + j) = s[i][j];
        __syncthreads();

        #pragma unroll
        for (int i = 0; i < 4; i++) {
            float corr = __expf(m[i] - newm[i]);
            l[i] = l[i] * corr + psum[i];
            m[i] = newm[i];
            #pragma unroll
            for (int dd = 0; dd < 4; dd++) o[i][dd] *= corr;
        }

        #pragma unroll 8
        for (int j = 0; j < 64; j++) {
            float pv[4], vv[4];
            #pragma unroll
            for (int i = 0; i < 4; i++) pv[i] = KS(ty * 4 + i, j);
            #pragma unroll
            for (int dd = 0; dd < 4; dd++) vv[dd] = VS(j, tx * 4 + dd);
            #pragma unroll
            for (int i = 0; i < 4; i++)
                #pragma unroll
                for (int dd = 0; dd < 4; dd++)
                    o[i][dd] = fmaf(pv[i], vv[dd], o[i][dd]);
        }
    }

    #pragma unroll
    for (int i = 0; i < 4; i++) {
        float inv = 1.0f / l[i];
        int t = b * Ss + q0 + ty * 4 + i;
        #pragma unroll
        for (int dd = 0; dd < 4; dd++)
            obuf[(size_t)t * Dm + h * 64 + tx * 4 + dd] = o[i][dd] * inv;
    }
}

// ---------------------------------------------------------------------------
// Gating + routing
// ---------------------------------------------------------------------------
__global__ void gate_route_kernel(const float* __restrict__ h2,
                                  const float* __restrict__ gw,
                                  const float* __restrict__ gb,
                                  int* __restrict__ cnt,
                                  int* __restrict__ tok,
                                  int* __restrict__ dst,
                                  float* __restrict__ gw2)
{
    int t = blockIdx.x * 8 + (threadIdx.x >> 5);
    int lane = threadIdx.x & 31;
    const float* xr = h2 + (size_t)t * Dm;
    float acc[Ee] = {};
    for (int d = lane; d < Dm; d += 32) {
        float xv = xr[d];
        #pragma unroll
        for (int e = 0; e < Ee; e++)
            acc[e] = fmaf(xv, gw[d * Ee + e], acc[e]);
    }
    #pragma unroll
    for (int e = 0; e < Ee; e++)
        #pragma unroll
        for (int off = 16; off; off >>= 1)
            acc[e] += __shfl_xor_sync(0xffffffffu, acc[e], off);

    if (lane == 0) {
        float lg[Ee];
        #pragma unroll
        for (int e = 0; e < Ee; e++) lg[e] = acc[e] + gb[e];
        int i0 = 0;
        #pragma unroll
        for (int e = 1; e < Ee; e++) if (lg[e] > lg[i0]) i0 = e;
        int i1 = -1;
        #pragma unroll
        for (int e = 0; e < Ee; e++) {
            if (e == i0) continue;
            if (i1 < 0 || lg[e] > lg[i1]) i1 = e;
        }
        float e1 = expf(lg[i1] - lg[i0]);
        float denom = 1.0f / (1.0f + e1);
        float g0 = denom, g1 = e1 * denom;
        int p0 = atomicAdd(&cnt[i0], 1);
        tok[i0 * LISTCAP + p0] = t;
        dst[i0 * LISTCAP + p0] = t * 2;
        int p1 = atomicAdd(&cnt[i1], 1);
        tok[i1 * LISTCAP + p1] = t;
        dst[i1 * LISTCAP + p1] = t * 2 + 1;
        gw2[t * 2]     = g0;
        gw2[t * 2 + 1] = g1;
    }
}

// ---------------------------------------------------------------------------
// Final combine
// ---------------------------------------------------------------------------
__global__ void combine_kernel(float* __restrict__ out,
                               const float* __restrict__ moeo,
                               const float* __restrict__ gw2)
{
    int t = blockIdx.x;
    float g0 = gw2[t * 2], g1 = gw2[t * 2 + 1];
    const float* r0 = moeo + (size_t)(t * 2) * Dm;
    const float* r1 = r0 + Dm;
    float* orow = out + (size_t)t * Dm;
    for (int d = threadIdx.x; d < Dm; d += 256)
        orow[d] += g0 * r0[d] + g1 * r1[d];
}

// ---------------------------------------------------------------------------
// Launch
// ---------------------------------------------------------------------------
extern "C" void kernel_launch(void* const* d_in, const int* in_sizes, int n_in,
                              void* d_out, int out_size)
{
    const float* x      = (const float*)d_in[0];
    const float* ln1_g  = (const float*)d_in[1];
    const float* ln1_b  = (const float*)d_in[2];
    const float* w_qkv  = (const float*)d_in[3];
    const float* b_qkv  = (const float*)d_in[4];
    const float* w_o    = (const float*)d_in[5];
    const float* b_o    = (const float*)d_in[6];
    const float* ln2_g  = (const float*)d_in[7];
    const float* ln2_b  = (const float*)d_in[8];
    const float* gate_w = (const float*)d_in[9];
    const float* gate_b = (const float*)d_in[10];
    const float* W1     = (const float*)d_in[11];
    const float* b1     = (const float*)d_in[12];
    const float* W2     = (const float*)d_in[13];
    const float* b2     = (const float*)d_in[14];
    float* out = (float*)d_out;

    float *h1, *qkv, *attno, *h2, *hid, *moeo, *gwp;
    int *cnt, *tok, *dst;
    cudaGetSymbolAddress((void**)&h1,    g_h1);
    cudaGetSymbolAddress((void**)&qkv,   g_qkv);
    cudaGetSymbolAddress((void**)&attno, g_attno);
    cudaGetSymbolAddress((void**)&h2,    g_h2);
    cudaGetSymbolAddress((void**)&hid,   g_hid);
    cudaGetSymbolAddress((void**)&moeo,  g_moeo);
    cudaGetSymbolAddress((void**)&cnt,   g_cnt);
    cudaGetSymbolAddress((void**)&tok,   g_tok);
    cudaGetSymbolAddress((void**)&dst,   g_dst);
    cudaGetSymbolAddress((void**)&gwp,   g_gw);

    static bool attr_done = false;
    if (!attr_done) {
        cudaFuncSetAttribute(attn_kernel,
                             cudaFuncAttributeMaxDynamicSharedMemorySize,
                             ATT_SMEM_BYTES);
        cudaFuncSetAttribute(gemm_bf16x3<false, false, false>,
                             cudaFuncAttributeMaxDynamicSharedMemorySize,
                             GEMM_SMEM_BYTES);
        cudaFuncSetAttribute(gemm_bf16x3<false, false, true>,
                             cudaFuncAttributeMaxDynamicSharedMemorySize,
                             GEMM_SMEM_BYTES);
        cudaFuncSetAttribute(gemm_bf16x3<true, true, false>,
                             cudaFuncAttributeMaxDynamicSharedMemorySize,
                             GEMM_SMEM_BYTES);
        cudaFuncSetAttribute(gemm_bf16x3<true, false, false>,
                             cudaFuncAttributeMaxDynamicSharedMemorySize,
                             GEMM_SMEM_BYTES);
        attr_done = true;
    }

    cudaMemsetAsync(cnt, 0, Ee * sizeof(int));

    // 1) LN1
    ln_kernel<<<Tt, 256>>>(x, ln1_g, ln1_b, h1);

    // 2) QKV
    gemm_bf16x3<false, false, false><<<dim3(3 * Dm / 128, Tt / 128), 256, GEMM_SMEM_BYTES>>>(
        h1, w_qkv, qkv, b_qkv, nullptr, nullptr, nullptr, nullptr,
        Tt, Dm, 3 * Dm);

    // 3) attention
    attn_kernel<<<dim3(Ss / 64, Hh, Bb), 256, ATT_SMEM_BYTES>>>(qkv, attno);

    // 4) x1 = x + attno @ w_o + b_o
    gemm_bf16x3<false, false, true><<<dim3(Dm / 128, Tt / 128), 256, GEMM_SMEM_BYTES>>>(
        attno, w_o, out, b_o, x, nullptr, nullptr, nullptr,
        Tt, Dm, Dm);

    // 5) LN2
    ln_kernel<<<Tt, 256>>>(out, ln2_g, ln2_b, h2);

    // 6) gating + routing
    gate_route_kernel<<<Tt / 8, 256>>>(h2, gate_w, gate_b, cnt, tok, dst, gwp);

    // 7) MoE FFN1
    gemm_bf16x3<true, true, false><<<dim3(DFFf / 128, LISTCAP / 128, Ee), 256, GEMM_SMEM_BYTES>>>(
        h2, W1, hid, b1, nullptr, tok, dst, cnt,
        0, Dm, DFFf);

    // 8) MoE FFN2
    gemm_bf16x3<true, false, false><<<dim3(Dm / 128, LISTCAP / 128, Ee), 256, GEMM_SMEM_BYTES>>>(
        hid, W2, moeo, b2, nullptr, dst, dst, cnt,
        0, DFFf, Dm);

    // 9) combine
    combine_kernel<<<Tt, 256>>>(out, moeo, gwp);
}

// round 5
// speedup vs baseline: 1.8176x; 1.0070x over previous
#include <cuda_runtime.h>
#include <cuda_bf16.h>
#include <math.h>
#include <stdint.h>

// Problem constants
#define Dm   1024
#define Hh   16
#define DKk  64
#define Ee   8
#define DFFf 4096
#define Ss   2048
#define Bb   2
#define Tt   (Bb * Ss)
#define NPAIR (Tt * 2)
#define LISTCAP 8192

// ---------------------------------------------------------------------------
// Static device scratch
// ---------------------------------------------------------------------------
__device__ float g_qkv[(size_t)Tt * 3 * Dm];       // fp32 QKV (attention reads)
__device__ float g_h2[(size_t)Tt * Dm];            // fp32 LN2 (gate reads)
__device__ float g_moeo[(size_t)NPAIR * Dm];
__device__ int   g_cnt[Ee];
__device__ int   g_tok[Ee * LISTCAP];
__device__ int   g_dst[Ee * LISTCAP];
__device__ float g_gw[NPAIR];

// bf16 hi/lo split operands
__device__ __nv_bfloat16 g_h1hi[(size_t)Tt * Dm],  g_h1lo[(size_t)Tt * Dm];
__device__ __nv_bfloat16 g_atthi[(size_t)Tt * Dm], g_attlo[(size_t)Tt * Dm];
__device__ __nv_bfloat16 g_h2hi[(size_t)Tt * Dm],  g_h2lo[(size_t)Tt * Dm];
__device__ __nv_bfloat16 g_hidhi[(size_t)NPAIR * DFFf], g_hidlo[(size_t)NPAIR * DFFf];
// transposed bf16 weights [N,K]
__device__ __nv_bfloat16 g_wqkvThi[(size_t)3 * Dm * Dm], g_wqkvTlo[(size_t)3 * Dm * Dm];
__device__ __nv_bfloat16 g_woThi[(size_t)Dm * Dm],       g_woTlo[(size_t)Dm * Dm];
__device__ __nv_bfloat16 g_W1Thi[(size_t)Ee * DFFf * Dm], g_W1Tlo[(size_t)Ee * DFFf * Dm];
__device__ __nv_bfloat16 g_W2Thi[(size_t)Ee * Dm * DFFf], g_W2Tlo[(size_t)Ee * Dm * DFFf];

// ---------------------------------------------------------------------------
// helpers
// ---------------------------------------------------------------------------
__device__ __forceinline__ void split2(float f0, float f1,
                                       uint32_t& hi, uint32_t& lo) {
    uint32_t h;
    asm("cvt.rn.bf16x2.f32 %0, %1, %2;" : "=r"(h) : "f"(f1), "f"(f0));
    float h0 = __uint_as_float(h << 16);
    float h1 = __uint_as_float(h & 0xffff0000u);
    float r0 = f0 - h0;
    float r1 = f1 - h1;
    uint32_t l;
    asm("cvt.rn.bf16x2.f32 %0, %1, %2;" : "=r"(l) : "f"(r1), "f"(r0));
    hi = h; lo = l;
}
__device__ __forceinline__ void cp16(uint32_t dst, const void* src, int src_bytes) {
    asm volatile("cp.async.cg.shared.global [%0], [%1], 16, %2;"
                 :: "r"(dst), "l"(src), "r"(src_bytes));
}
__device__ __forceinline__ void cp_commit() {
    asm volatile("cp.async.commit_group;");
}
template<int N>
__device__ __forceinline__ void cp_wait() {
    asm volatile("cp.async.wait_group %0;" :: "n"(N));
}
__device__ __forceinline__ void mma_bf16(float* c, const uint32_t* a, const uint32_t* b) {
    asm volatile(
        "mma.sync.aligned.m16n8k16.row.col.f32.bf16.bf16.f32 "
        "{%0,%1,%2,%3}, {%4,%5,%6,%7}, {%8,%9}, {%0,%1,%2,%3};"
        : "+f"(c[0]), "+f"(c[1]), "+f"(c[2]), "+f"(c[3])
        : "r"(a[0]), "r"(a[1]), "r"(a[2]), "r"(a[3]), "r"(b[0]), "r"(b[1]));
}
__device__ __forceinline__ uint32_t lds32(const __nv_bfloat16* p) {
    return *(const uint32_t*)p;
}

// ---------------------------------------------------------------------------
// Weight transpose + split: fp32 [K,N] -> bf16 hi/lo [N,K]  (per expert z)
// ---------------------------------------------------------------------------
__global__ void convT_kernel(const float* __restrict__ src,
                             __nv_bfloat16* __restrict__ hi,
                             __nv_bfloat16* __restrict__ lo,
                             int K, int N)
{
    __shared__ float tile[32][33];
    int z = blockIdx.z;
    src += (size_t)z * K * N;
    hi  += (size_t)z * K * N;
    lo  += (size_t)z * K * N;
    int k0 = blockIdx.y * 32, n0 = blockIdx.x * 32;
    int tx = threadIdx.x, ty = threadIdx.y;   // 32 x 8
    #pragma unroll
    for (int i = 0; i < 4; i++)
        tile[ty + 8 * i][tx] = src[(size_t)(k0 + ty + 8 * i) * N + n0 + tx];
    __syncthreads();
    #pragma unroll
    for (int i = 0; i < 4; i++) {
        float v = tile[tx][ty + 8 * i];
        __nv_bfloat16 h = __float2bfloat16_rn(v);
        float r = v - __bfloat162float(h);
        size_t o = (size_t)(n0 + ty + 8 * i) * K + k0 + tx;
        hi[o] = h;
        lo[o] = __float2bfloat16_rn(r);
    }
}

// ---------------------------------------------------------------------------
// LayerNorm: writes bf16 hi/lo, optional fp32
// ---------------------------------------------------------------------------
__global__ void ln_kernel(const float* __restrict__ x,
                          const float* __restrict__ g,
                          const float* __restrict__ b,
                          float* __restrict__ outf,           // may be null
                          __nv_bfloat16* __restrict__ ohi,
                          __nv_bfloat16* __restrict__ olo)
{
    int t = blockIdx.x;
    const float* xr = x + (size_t)t * Dm;
    float s = 0.f, s2 = 0.f;
    for (int d = threadIdx.x; d < Dm; d += 256) {
        float v = xr[d];
        s += v; s2 += v * v;
    }
    #pragma unroll
    for (int off = 16; off; off >>= 1) {
        s  += __shfl_xor_sync(0xffffffffu, s, off);
        s2 += __shfl_xor_sync(0xffffffffu, s2, off);
    }
    __shared__ float sh[18];
    int w = threadIdx.x >> 5;
    if ((threadIdx.x & 31) == 0) { sh[w] = s; sh[w + 8] = s2; }
    __syncthreads();
    if (threadIdx.x == 0) {
        float ts = 0.f, ts2 = 0.f;
        #pragma unroll
        for (int i = 0; i < 8; i++) { ts += sh[i]; ts2 += sh[i + 8]; }
        sh[16] = ts; sh[17] = ts2;
    }
    __syncthreads();
    float mean = sh[16] * (1.0f / Dm);
    float var  = sh[17] * (1.0f / Dm) - mean * mean;
    float rstd = rsqrtf(var + 1e-5f);
    for (int d = threadIdx.x; d < Dm; d += 256) {
        float v = (xr[d] - mean) * rstd * g[d] + b[d];
        if (outf) outf[(size_t)t * Dm + d] = v;
        __nv_bfloat16 h = __float2bfloat16_rn(v);
        float r = v - __bfloat162float(h);
        ohi[(size_t)t * Dm + d] = h;
        olo[(size_t)t * Dm + d] = __float2bfloat16_rn(r);
    }
}

// ---------------------------------------------------------------------------
// bf16x3 GEMM with PRE-SPLIT operands. A: bf16 hi/lo [M,K]. B: bf16 hi/lo
// [N,K] (transposed). 128x128x32 tile, 256 threads, double-buffered cp.async.
// Conflict-free smem stride 40 bf16 (20 words).
// ---------------------------------------------------------------------------
#define ASTR 40
#define TILE_BF (128 * ASTR)            // 5120 bf16 units per tile
#define BUF_UNITS (4 * TILE_BF)         // Ahi,Alo,Bhi,Blo
#define GEMM_SMEM (2 * BUF_UNITS * 2)   // 81,920 bytes

template<bool MOE, bool RELU, bool RESID, bool WBF16>
__global__ __launch_bounds__(256, 2)
void gemm_split(const __nv_bfloat16* __restrict__ Ahi,
                const __nv_bfloat16* __restrict__ Alo,
                const __nv_bfloat16* __restrict__ BThi,   // [N,K]
                const __nv_bfloat16* __restrict__ BTlo,
                float* __restrict__ C,
                __nv_bfloat16* __restrict__ Chi,
                __nv_bfloat16* __restrict__ Clo,
                const float* __restrict__ bias,
                const float* __restrict__ resid,
                const int* __restrict__ a_idx,
                const int* __restrict__ c_idx,
                const int* __restrict__ cnt,
                int M, int K, int N)
{
    if (MOE) {
        int z = blockIdx.z;
        M = cnt[z];
        BThi += (size_t)z * K * N;
        BTlo += (size_t)z * K * N;
        bias += (size_t)z * N;
        a_idx += z * LISTCAP;
        c_idx += z * LISTCAP;
    }
    const int m0 = blockIdx.y * 128;
    if (m0 >= M) return;
    const int n0 = blockIdx.x * 128;

    extern __shared__ __nv_bfloat16 bsm[];

    const int tid = threadIdx.x;
    const int wid = tid >> 5;
    const int lane = tid & 31;
    const int g = lane >> 2;
    const int q = lane & 3;
    const int wm = wid & 1;
    const int wn = wid >> 1;

    // --- cp.async assignments: 2 rows per thread per array ---------------
    const int kc = (tid & 3) * 8;            // bf16 col offset within 32-k tile
    int rl[2];
    rl[0] = tid >> 2;
    rl[1] = (tid >> 2) + 64;

    const __nv_bfloat16* a_srchi[2];
    const __nv_bfloat16* a_srclo[2];
    int a_bytes[2];
    #pragma unroll
    for (int i = 0; i < 2; i++) {
        int r = m0 + rl[i];
        bool valid = r < M;
        int gr = valid ? (MOE ? a_idx[r] : r) : 0;
        a_srchi[i] = Ahi + (size_t)gr * K + kc;
        a_srclo[i] = Alo + (size_t)gr * K + kc;
        a_bytes[i] = valid ? 16 : 0;
    }
    const __nv_bfloat16* b_srchi[2];
    const __nv_bfloat16* b_srclo[2];
    #pragma unroll
    for (int i = 0; i < 2; i++) {
        int n = n0 + rl[i];
        b_srchi[i] = BThi + (size_t)n * K + kc;
        b_srclo[i] = BTlo + (size_t)n * K + kc;
    }

    uint32_t dA[2], dB[2];
    #pragma unroll
    for (int i = 0; i < 2; i++) {
        dA[i] = (uint32_t)__cvta_generic_to_shared(&bsm[rl[i] * ASTR + kc]);
        dB[i] = dA[i] + 2 * TILE_BF * 2;
    }
    const uint32_t LO_OFF = TILE_BF * 2;         // bytes to lo tile
    const uint32_t BUFB   = BUF_UNITS * 2;       // bytes to buffer 1

    const int nk = K / 32;

    // prefetch tile 0
    #pragma unroll
    for (int i = 0; i < 2; i++) {
        cp16(dA[i],          a_srchi[i], a_bytes[i]);
        cp16(dA[i] + LO_OFF, a_srclo[i], a_bytes[i]);
        cp16(dB[i],          b_srchi[i], 16);
        cp16(dB[i] + LO_OFF, b_srclo[i], 16);
    }
    cp_commit();

    float acc[4][4][4] = {};

    int buf = 0;
    for (int kt = 0; kt < nk; kt++) {
        if (kt + 1 < nk) {
            int k0 = (kt + 1) * 32;
            uint32_t bo = (buf ^ 1) ? BUFB : 0;
            #pragma unroll
            for (int i = 0; i < 2; i++) {
                cp16(dA[i] + bo,          a_srchi[i] + k0, a_bytes[i]);
                cp16(dA[i] + bo + LO_OFF, a_srclo[i] + k0, a_bytes[i]);
                cp16(dB[i] + bo,          b_srchi[i] + k0, 16);
                cp16(dB[i] + bo + LO_OFF, b_srclo[i] + k0, 16);
            }
            cp_commit();
            cp_wait<1>();
        } else {
            cp_wait<0>();
        }
        __syncthreads();

        const __nv_bfloat16* As_hi = bsm + buf * BUF_UNITS;
        const __nv_bfloat16* As_lo = As_hi + TILE_BF;
        const __nv_bfloat16* Bs_hi = As_hi + 2 * TILE_BF;
        const __nv_bfloat16* Bs_lo = As_hi + 3 * TILE_BF;

        #pragma unroll
        for (int ks = 0; ks < 2; ks++) {
            const int kb = ks * 16;
            uint32_t bhi[4][2], blo[4][2];
            #pragma unroll
            for (int nt = 0; nt < 4; nt++) {
                int nc = wn * 32 + nt * 8 + g;
                bhi[nt][0] = lds32(&Bs_hi[nc * ASTR + kb + 2 * q]);
                bhi[nt][1] = lds32(&Bs_hi[nc * ASTR + kb + 2 * q + 8]);
                blo[nt][0] = lds32(&Bs_lo[nc * ASTR + kb + 2 * q]);
                blo[nt][1] = lds32(&Bs_lo[nc * ASTR + kb + 2 * q + 8]);
            }
            #pragma unroll
            for (int mt = 0; mt < 4; mt++) {
                int r0 = wm * 64 + mt * 16 + g;
                int r1 = r0 + 8;
                uint32_t ahi[4], alo[4];
                ahi[0] = lds32(&As_hi[r0 * ASTR + kb + 2 * q]);
                ahi[1] = lds32(&As_hi[r1 * ASTR + kb + 2 * q]);
                ahi[2] = lds32(&As_hi[r0 * ASTR + kb + 2 * q + 8]);
                ahi[3] = lds32(&As_hi[r1 * ASTR + kb + 2 * q + 8]);
                alo[0] = lds32(&As_lo[r0 * ASTR + kb + 2 * q]);
                alo[1] = lds32(&As_lo[r1 * ASTR + kb + 2 * q]);
                alo[2] = lds32(&As_lo[r0 * ASTR + kb + 2 * q + 8]);
                alo[3] = lds32(&As_lo[r1 * ASTR + kb + 2 * q + 8]);
                #pragma unroll
                for (int nt = 0; nt < 4; nt++) {
                    mma_bf16(acc[mt][nt], ahi, bhi[nt]);
                    mma_bf16(acc[mt][nt], ahi, blo[nt]);
                    mma_bf16(acc[mt][nt], alo, bhi[nt]);
                }
            }
        }
        __syncthreads();
        buf ^= 1;
    }

    // --- epilogue --------------------------------------------------------
    #pragma unroll
    for (int mt = 0; mt < 4; mt++) {
        #pragma unroll
        for (int half = 0; half < 2; half++) {
            int r = m0 + wm * 64 + mt * 16 + g + half * 8;
            if (MOE && r >= M) continue;
            int cr = MOE ? c_idx[r] : r;
            #pragma unroll
            for (int nt = 0; nt < 4; nt++) {
                int c = n0 + wn * 32 + nt * 8 + 2 * q;
                float v0 = acc[mt][nt][half * 2 + 0] + bias[c];
                float v1 = acc[mt][nt][half * 2 + 1] + bias[c + 1];
                if (RELU) { v0 = fmaxf(v0, 0.f); v1 = fmaxf(v1, 0.f); }
                if (RESID) {
                    float2 rr = *(const float2*)(resid + (size_t)r * N + c);
                    v0 += rr.x; v1 += rr.y;
                }
                if (WBF16) {
                    uint32_t h, l;
                    split2(v0, v1, h, l);
                    *(uint32_t*)&Chi[(size_t)cr * N + c] = h;
                    *(uint32_t*)&Clo[(size_t)cr * N + c] = l;
                } else {
                    *(float2*)(C + (size_t)cr * N + c) = make_float2(v0, v1);
                }
            }
        }
    }
}

// ---------------------------------------------------------------------------
// Flash attention (fp32) — epilogue writes bf16 hi/lo
// ---------------------------------------------------------------------------
#define ATT_STRIDE 65
#define ATT_SMEM_BYTES (3 * 64 * ATT_STRIDE * 4)

__global__ __launch_bounds__(256)
void attn_kernel(const float* __restrict__ qkv,
                 __nv_bfloat16* __restrict__ ohi,
                 __nv_bfloat16* __restrict__ olo)
{
    extern __shared__ float smem[];
    float* Qs = smem;
    float* Ks = smem + 64 * ATT_STRIDE;
    float* Vs = smem + 2 * 64 * ATT_STRIDE;
    #define QS(r, c) Qs[(r) * ATT_STRIDE + (c)]
    #define KS(r, c) Ks[(r) * ATT_STRIDE + (c)]
    #define VS(r, c) Vs[(r) * ATT_STRIDE + (c)]

    const int qb = blockIdx.x, h = blockIdx.y, b = blockIdx.z;
    const int tid = threadIdx.x;
    const int tx = tid & 15, ty = tid >> 4;

    const size_t base = (size_t)b * Ss * (3 * Dm);
    const int q0 = qb * 64;
    const float scale = 0.125f;

    #pragma unroll
    for (int r4 = 0; r4 < 4; r4++) {
        int idx = r4 * 256 + tid;
        int row = idx >> 4;
        int c4  = (idx & 15) * 4;
        float4 v = *(const float4*)(qkv + base + (size_t)(q0 + row) * (3 * Dm) + h * 64 + c4);
        QS(row, c4 + 0) = v.x * scale;
        QS(row, c4 + 1) = v.y * scale;
        QS(row, c4 + 2) = v.z * scale;
        QS(row, c4 + 3) = v.w * scale;
    }

    float m[4] = {-1e30f, -1e30f, -1e30f, -1e30f};
    float l[4] = {0.f, 0.f, 0.f, 0.f};
    float o[4][4] = {};

    for (int kt = 0; kt < Ss; kt += 64) {
        __syncthreads();
        #pragma unroll
        for (int r4 = 0; r4 < 4; r4++) {
            int idx = r4 * 256 + tid;
            int row = idx >> 4;
            int c4  = (idx & 15) * 4;
            size_t gg = base + (size_t)(kt + row) * (3 * Dm) + h * 64 + c4;
            float4 kv = *(const float4*)(qkv + gg + Dm);
            float4 vv = *(const float4*)(qkv + gg + 2 * Dm);
            KS(row, c4 + 0) = kv.x; KS(row, c4 + 1) = kv.y;
            KS(row, c4 + 2) = kv.z; KS(row, c4 + 3) = kv.w;
            VS(row, c4 + 0) = vv.x; VS(row, c4 + 1) = vv.y;
            VS(row, c4 + 2) = vv.z; VS(row, c4 + 3) = vv.w;
        }
        __syncthreads();

        float s[4][4] = {};
        #pragma unroll 8
        for (int d = 0; d < 64; d++) {
            float qv[4], kv[4];
            #pragma unroll
            for (int i = 0; i < 4; i++) qv[i] = QS(ty * 4 + i, d);
            #pragma unroll
            for (int j = 0; j < 4; j++) kv[j] = KS(tx * 4 + j, d);
            #pragma unroll
            for (int i = 0; i < 4; i++)
                #pragma unroll
                for (int j = 0; j < 4; j++)
                    s[i][j] = fmaf(qv[i], kv[j], s[i][j]);
        }

        float newm[4], psum[4];
        #pragma unroll
        for (int i = 0; i < 4; i++) {
            float tm = fmaxf(fmaxf(s[i][0], s[i][1]), fmaxf(s[i][2], s[i][3]));
            #pragma unroll
            for (int off = 1; off < 16; off <<= 1)
                tm = fmaxf(tm, __shfl_xor_sync(0xffffffffu, tm, off));
            newm[i] = fmaxf(m[i], tm);
            float ps = 0.f;
            #pragma unroll
            for (int j = 0; j < 4; j++) {
                s[i][j] = __expf(s[i][j] - newm[i]);
                ps += s[i][j];
            }
            #pragma unroll
            for (int off = 1; off < 16; off <<= 1)
                ps += __shfl_xor_sync(0xffffffffu, ps, off);
            psum[i] = ps;
        }

        __syncthreads();
        #pragma unroll
        for (int i = 0; i < 4; i++)
            #pragma unroll
            for (int j = 0; j < 4; j++)
                KS(ty * 4 + i, tx * 4 + j) = s[i][j];
        __syncthreads();

        #pragma unroll
        for (int i = 0; i < 4; i++) {
            float corr = __expf(m[i] - newm[i]);
            l[i] = l[i] * corr + psum[i];
            m[i] = newm[i];
            #pragma unroll
            for (int dd = 0; dd < 4; dd++) o[i][dd] *= corr;
        }

        #pragma unroll 8
        for (int j = 0; j < 64; j++) {
            float pv[4], vv[4];
            #pragma unroll
            for (int i = 0; i < 4; i++) pv[i] = KS(ty * 4 + i, j);
            #pragma unroll
            for (int dd = 0; dd < 4; dd++) vv[dd] = VS(j, tx * 4 + dd);
            #pragma unroll
            for (int i = 0; i < 4; i++)
                #pragma unroll
                for (int dd = 0; dd < 4; dd++)
                    o[i][dd] = fmaf(pv[i], vv[dd], o[i][dd]);
        }
    }

    #pragma unroll
    for (int i = 0; i < 4; i++) {
        float inv = 1.0f / l[i];
        int t = b * Ss + q0 + ty * 4 + i;
        size_t off = (size_t)t * Dm + h * 64 + tx * 4;
        uint32_t h01, l01, h23, l23;
        split2(o[i][0] * inv, o[i][1] * inv, h01, l01);
        split2(o[i][2] * inv, o[i][3] * inv, h23, l23);
        *(uint32_t*)&ohi[off]     = h01;
        *(uint32_t*)&ohi[off + 2] = h23;
        *(uint32_t*)&olo[off]     = l01;
        *(uint32_t*)&olo[off + 2] = l23;
    }
}

// ---------------------------------------------------------------------------
// Gating + routing
// ---------------------------------------------------------------------------
__global__ void gate_route_kernel(const float* __restrict__ h2,
                                  const float* __restrict__ gw,
                                  const float* __restrict__ gb,
                                  int* __restrict__ cnt,
                                  int* __restrict__ tok,
                                  int* __restrict__ dst,
                                  float* __restrict__ gw2)
{
    int t = blockIdx.x * 8 + (threadIdx.x >> 5);
    int lane = threadIdx.x & 31;
    const float* xr = h2 + (size_t)t * Dm;
    float acc[Ee] = {};
    for (int d = lane; d < Dm; d += 32) {
        float xv = xr[d];
        #pragma unroll
        for (int e = 0; e < Ee; e++)
            acc[e] = fmaf(xv, gw[d * Ee + e], acc[e]);
    }
    #pragma unroll
    for (int e = 0; e < Ee; e++)
        #pragma unroll
        for (int off = 16; off; off >>= 1)
            acc[e] += __shfl_xor_sync(0xffffffffu, acc[e], off);

    if (lane == 0) {
        float lg[Ee];
        #pragma unroll
        for (int e = 0; e < Ee; e++) lg[e] = acc[e] + gb[e];
        int i0 = 0;
        #pragma unroll
        for (int e = 1; e < Ee; e++) if (lg[e] > lg[i0]) i0 = e;
        int i1 = -1;
        #pragma unroll
        for (int e = 0; e < Ee; e++) {
            if (e == i0) continue;
            if (i1 < 0 || lg[e] > lg[i1]) i1 = e;
        }
        float e1 = expf(lg[i1] - lg[i0]);
        float denom = 1.0f / (1.0f + e1);
        float g0 = denom, g1 = e1 * denom;
        int p0 = atomicAdd(&cnt[i0], 1);
        tok[i0 * LISTCAP + p0] = t;
        dst[i0 * LISTCAP + p0] = t * 2;
        int p1 = atomicAdd(&cnt[i1], 1);
        tok[i1 * LISTCAP + p1] = t;
        dst[i1 * LISTCAP + p1] = t * 2 + 1;
        gw2[t * 2]     = g0;
        gw2[t * 2 + 1] = g1;
    }
}

// ---------------------------------------------------------------------------
// Final combine
// ---------------------------------------------------------------------------
__global__ void combine_kernel(float* __restrict__ out,
                               const float* __restrict__ moeo,
                               const float* __restrict__ gw2)
{
    int t = blockIdx.x;
    float g0 = gw2[t * 2], g1 = gw2[t * 2 + 1];
    const float* r0 = moeo + (size_t)(t * 2) * Dm;
    const float* r1 = r0 + Dm;
    float* orow = out + (size_t)t * Dm;
    for (int d = threadIdx.x; d < Dm; d += 256)
        orow[d] += g0 * r0[d] + g1 * r1[d];
}

// ---------------------------------------------------------------------------
// Launch
// ---------------------------------------------------------------------------
extern "C" void kernel_launch(void* const* d_in, const int* in_sizes, int n_in,
                              void* d_out, int out_size)
{
    const float* x      = (const float*)d_in[0];
    const float* ln1_g  = (const float*)d_in[1];
    const float* ln1_b  = (const float*)d_in[2];
    const float* w_qkv  = (const float*)d_in[3];
    const float* b_qkv  = (const float*)d_in[4];
    const float* w_o    = (const float*)d_in[5];
    const float* b_o    = (const float*)d_in[6];
    const float* ln2_g  = (const float*)d_in[7];
    const float* ln2_b  = (const float*)d_in[8];
    const float* gate_w = (const float*)d_in[9];
    const float* gate_b = (const float*)d_in[10];
    const float* W1     = (const float*)d_in[11];
    const float* b1     = (const float*)d_in[12];
    const float* W2     = (const float*)d_in[13];
    const float* b2     = (const float*)d_in[14];
    float* out = (float*)d_out;

    float *qkv, *h2, *moeo, *gwp;
    int *cnt, *tok, *dst;
    __nv_bfloat16 *h1hi, *h1lo, *atthi, *attlo, *h2hi, *h2lo, *hidhi, *hidlo;
    __nv_bfloat16 *wqkvThi, *wqkvTlo, *woThi, *woTlo, *W1Thi, *W1Tlo, *W2Thi, *W2Tlo;
    cudaGetSymbolAddress((void**)&qkv,   g_qkv);
    cudaGetSymbolAddress((void**)&h2,    g_h2);
    cudaGetSymbolAddress((void**)&moeo,  g_moeo);
    cudaGetSymbolAddress((void**)&cnt,   g_cnt);
    cudaGetSymbolAddress((void**)&tok,   g_tok);
    cudaGetSymbolAddress((void**)&dst,   g_dst);
    cudaGetSymbolAddress((void**)&gwp,   g_gw);
    cudaGetSymbolAddress((void**)&h1hi,  g_h1hi);
    cudaGetSymbolAddress((void**)&h1lo,  g_h1lo);
    cudaGetSymbolAddress((void**)&atthi, g_atthi);
    cudaGetSymbolAddress((void**)&attlo, g_attlo);
    cudaGetSymbolAddress((void**)&h2hi,  g_h2hi);
    cudaGetSymbolAddress((void**)&h2lo,  g_h2lo);
    cudaGetSymbolAddress((void**)&hidhi, g_hidhi);
    cudaGetSymbolAddress((void**)&hidlo, g_hidlo);
    cudaGetSymbolAddress((void**)&wqkvThi, g_wqkvThi);
    cudaGetSymbolAddress((void**)&wqkvTlo, g_wqkvTlo);
    cudaGetSymbolAddress((void**)&woThi, g_woThi);
    cudaGetSymbolAddress((void**)&woTlo, g_woTlo);
    cudaGetSymbolAddress((void**)&W1Thi, g_W1Thi);
    cudaGetSymbolAddress((void**)&W1Tlo, g_W1Tlo);
    cudaGetSymbolAddress((void**)&W2Thi, g_W2Thi);
    cudaGetSymbolAddress((void**)&W2Tlo, g_W2Tlo);

    static bool attr_done = false;
    if (!attr_done) {
        cudaFuncSetAttribute(attn_kernel,
                             cudaFuncAttributeMaxDynamicSharedMemorySize, ATT_SMEM_BYTES);
        cudaFuncSetAttribute(gemm_split<false, false, false, false>,
                             cudaFuncAttributeMaxDynamicSharedMemorySize, GEMM_SMEM);
        cudaFuncSetAttribute(gemm_split<false, false, true, false>,
                             cudaFuncAttributeMaxDynamicSharedMemorySize, GEMM_SMEM);
        cudaFuncSetAttribute(gemm_split<true, true, false, true>,
                             cudaFuncAttributeMaxDynamicSharedMemorySize, GEMM_SMEM);
        cudaFuncSetAttribute(gemm_split<true, false, false, false>,
                             cudaFuncAttributeMaxDynamicSharedMemorySize, GEMM_SMEM);
        attr_done = true;
    }

    cudaMemsetAsync(cnt, 0, Ee * sizeof(int));

    // 0) weight transpose + split (per launch; graph-capturable kernels)
    dim3 cvtb(32, 8);
    convT_kernel<<<dim3(3 * Dm / 32, Dm / 32, 1), cvtb>>>(w_qkv, wqkvThi, wqkvTlo, Dm, 3 * Dm);
    convT_kernel<<<dim3(Dm / 32, Dm / 32, 1), cvtb>>>(w_o, woThi, woTlo, Dm, Dm);
    convT_kernel<<<dim3(DFFf / 32, Dm / 32, Ee), cvtb>>>(W1, W1Thi, W1Tlo, Dm, DFFf);
    convT_kernel<<<dim3(Dm / 32, DFFf / 32, Ee), cvtb>>>(W2, W2Thi, W2Tlo, DFFf, Dm);

    // 1) LN1 -> bf16 hi/lo
    ln_kernel<<<Tt, 256>>>(x, ln1_g, ln1_b, nullptr, h1hi, h1lo);

    // 2) QKV = h1 @ w_qkv + b_qkv (fp32 out for attention)
    gemm_split<false, false, false, false><<<dim3(3 * Dm / 128, Tt / 128), 256, GEMM_SMEM>>>(
        h1hi, h1lo, wqkvThi, wqkvTlo, qkv, nullptr, nullptr,
        b_qkv, nullptr, nullptr, nullptr, nullptr, Tt, Dm, 3 * Dm);

    // 3) attention -> bf16 hi/lo
    attn_kernel<<<dim3(Ss / 64, Hh, Bb), 256, ATT_SMEM_BYTES>>>(qkv, atthi, attlo);

    // 4) x1 = x + attno @ w_o + b_o  (fp32 -> d_out)
    gemm_split<false, false, true, false><<<dim3(Dm / 128, Tt / 128), 256, GEMM_SMEM>>>(
        atthi, attlo, woThi, woTlo, out, nullptr, nullptr,
        b_o, x, nullptr, nullptr, nullptr, Tt, Dm, Dm);

    // 5) LN2 -> fp32 (gate) + bf16 hi/lo (FFN1 A)
    ln_kernel<<<Tt, 256>>>(out, ln2_g, ln2_b, h2, h2hi, h2lo);

    // 6) gating + routing
    gate_route_kernel<<<Tt / 8, 256>>>(h2, gate_w, gate_b, cnt, tok, dst, gwp);

    // 7) MoE FFN1: hid = relu(h2[tok] @ W1[e] + b1[e]) -> bf16 hi/lo
    gemm_split<true, true, false, true><<<dim3(DFFf / 128, LISTCAP / 128, Ee), 256, GEMM_SMEM>>>(
        h2hi, h2lo, W1Thi, W1Tlo, nullptr, hidhi, hidlo,
        b1, nullptr, tok, dst, cnt, 0, Dm, DFFf);

    // 8) MoE FFN2: moeo = hid @ W2[e] + b2[e] (fp32)
    gemm_split<true, false, false, false><<<dim3(Dm / 128, LISTCAP / 128, Ee), 256, GEMM_SMEM>>>(
        hidhi, hidlo, W2Thi, W2Tlo, moeo, nullptr, nullptr,
        b2, nullptr, dst, dst, cnt, 0, DFFf, Dm);

    // 9) combine
    combine_kernel<<<Tt, 256>>>(out, moeo, gwp);
}

// round 7
// speedup vs baseline: 1.9146x; 1.0533x over previous
#include <cuda_runtime.h>
#include <cuda_bf16.h>
#include <math.h>
#include <stdint.h>

// Problem constants
#define Dm   1024
#define Hh   16
#define DKk  64
#define Ee   8
#define DFFf 4096
#define Ss   2048
#define Bb   2
#define Tt   (Bb * Ss)
#define NPAIR (Tt * 2)
#define LISTCAP 8192

// ---------------------------------------------------------------------------
// Static device scratch
// ---------------------------------------------------------------------------
__device__ float g_qkv[(size_t)Tt * 3 * Dm];
__device__ float g_h2[(size_t)Tt * Dm];
__device__ float g_moeo[(size_t)NPAIR * Dm];
__device__ int   g_cnt[Ee];
__device__ int   g_tok[Ee * LISTCAP];
__device__ int   g_dst[Ee * LISTCAP];
__device__ float g_gw[NPAIR];

__device__ __nv_bfloat16 g_h1hi[(size_t)Tt * Dm],  g_h1lo[(size_t)Tt * Dm];
__device__ __nv_bfloat16 g_atthi[(size_t)Tt * Dm], g_attlo[(size_t)Tt * Dm];
__device__ __nv_bfloat16 g_h2hi[(size_t)Tt * Dm],  g_h2lo[(size_t)Tt * Dm];
__device__ __nv_bfloat16 g_hidhi[(size_t)NPAIR * DFFf], g_hidlo[(size_t)NPAIR * DFFf];
__device__ __nv_bfloat16 g_wqkvThi[(size_t)3 * Dm * Dm], g_wqkvTlo[(size_t)3 * Dm * Dm];
__device__ __nv_bfloat16 g_woThi[(size_t)Dm * Dm],       g_woTlo[(size_t)Dm * Dm];
__device__ __nv_bfloat16 g_W1Thi[(size_t)Ee * DFFf * Dm], g_W1Tlo[(size_t)Ee * DFFf * Dm];
__device__ __nv_bfloat16 g_W2Thi[(size_t)Ee * Dm * DFFf], g_W2Tlo[(size_t)Ee * Dm * DFFf];

// ---------------------------------------------------------------------------
// helpers
// ---------------------------------------------------------------------------
__device__ __forceinline__ void split2(float f0, float f1,
                                       uint32_t& hi, uint32_t& lo) {
    uint32_t h;
    asm("cvt.rn.bf16x2.f32 %0, %1, %2;" : "=r"(h) : "f"(f1), "f"(f0));
    float h0 = __uint_as_float(h << 16);
    float h1 = __uint_as_float(h & 0xffff0000u);
    float r0 = f0 - h0;
    float r1 = f1 - h1;
    uint32_t l;
    asm("cvt.rn.bf16x2.f32 %0, %1, %2;" : "=r"(l) : "f"(r1), "f"(r0));
    hi = h; lo = l;
}
__device__ __forceinline__ void cp16(uint32_t dst, const void* src, int src_bytes) {
    asm volatile("cp.async.cg.shared.global [%0], [%1], 16, %2;"
                 :: "r"(dst), "l"(src), "r"(src_bytes));
}
__device__ __forceinline__ void cp_commit() {
    asm volatile("cp.async.commit_group;");
}
template<int N>
__device__ __forceinline__ void cp_wait() {
    asm volatile("cp.async.wait_group %0;" :: "n"(N));
}
__device__ __forceinline__ void mma_bf16(float* c, const uint32_t* a, const uint32_t* b) {
    asm volatile(
        "mma.sync.aligned.m16n8k16.row.col.f32.bf16.bf16.f32 "
        "{%0,%1,%2,%3}, {%4,%5,%6,%7}, {%8,%9}, {%0,%1,%2,%3};"
        : "+f"(c[0]), "+f"(c[1]), "+f"(c[2]), "+f"(c[3])
        : "r"(a[0]), "r"(a[1]), "r"(a[2]), "r"(a[3]), "r"(b[0]), "r"(b[1]));
}
__device__ __forceinline__ void ldmx4(uint32_t* r, uint32_t addr) {
    asm volatile("ldmatrix.sync.aligned.m8n8.x4.shared.b16 {%0,%1,%2,%3}, [%4];"
                 : "=r"(r[0]), "=r"(r[1]), "=r"(r[2]), "=r"(r[3]) : "r"(addr));
}

// ---------------------------------------------------------------------------
// Weight transpose + split: fp32 [K,N] -> bf16 hi/lo [N,K]  (per expert z)
// ---------------------------------------------------------------------------
__global__ void convT_kernel(const float* __restrict__ src,
                             __nv_bfloat16* __restrict__ hi,
                             __nv_bfloat16* __restrict__ lo,
                             int K, int N)
{
    __shared__ float tile[32][33];
    int z = blockIdx.z;
    src += (size_t)z * K * N;
    hi  += (size_t)z * K * N;
    lo  += (size_t)z * K * N;
    int k0 = blockIdx.y * 32, n0 = blockIdx.x * 32;
    int tx = threadIdx.x, ty = threadIdx.y;   // 32 x 8
    #pragma unroll
    for (int i = 0; i < 4; i++)
        tile[ty + 8 * i][tx] = src[(size_t)(k0 + ty + 8 * i) * N + n0 + tx];
    __syncthreads();
    #pragma unroll
    for (int i = 0; i < 4; i++) {
        float v = tile[tx][ty + 8 * i];
        __nv_bfloat16 h = __float2bfloat16_rn(v);
        float r = v - __bfloat162float(h);
        size_t o = (size_t)(n0 + ty + 8 * i) * K + k0 + tx;
        hi[o] = h;
        lo[o] = __float2bfloat16_rn(r);
    }
}

// ---------------------------------------------------------------------------
// LayerNorm: writes bf16 hi/lo, optional fp32
// ---------------------------------------------------------------------------
__global__ void ln_kernel(const float* __restrict__ x,
                          const float* __restrict__ g,
                          const float* __restrict__ b,
                          float* __restrict__ outf,           // may be null
                          __nv_bfloat16* __restrict__ ohi,
                          __nv_bfloat16* __restrict__ olo)
{
    int t = blockIdx.x;
    const float* xr = x + (size_t)t * Dm;
    float s = 0.f, s2 = 0.f;
    for (int d = threadIdx.x; d < Dm; d += 256) {
        float v = xr[d];
        s += v; s2 += v * v;
    }
    #pragma unroll
    for (int off = 16; off; off >>= 1) {
        s  += __shfl_xor_sync(0xffffffffu, s, off);
        s2 += __shfl_xor_sync(0xffffffffu, s2, off);
    }
    __shared__ float sh[18];
    int w = threadIdx.x >> 5;
    if ((threadIdx.x & 31) == 0) { sh[w] = s; sh[w + 8] = s2; }
    __syncthreads();
    if (threadIdx.x == 0) {
        float ts = 0.f, ts2 = 0.f;
        #pragma unroll
        for (int i = 0; i < 8; i++) { ts += sh[i]; ts2 += sh[i + 8]; }
        sh[16] = ts; sh[17] = ts2;
    }
    __syncthreads();
    float mean = sh[16] * (1.0f / Dm);
    float var  = sh[17] * (1.0f / Dm) - mean * mean;
    float rstd = rsqrtf(var + 1e-5f);
    for (int d = threadIdx.x; d < Dm; d += 256) {
        float v = (xr[d] - mean) * rstd * g[d] + b[d];
        if (outf) outf[(size_t)t * Dm + d] = v;
        __nv_bfloat16 h = __float2bfloat16_rn(v);
        float r = v - __bfloat162float(h);
        ohi[(size_t)t * Dm + d] = h;
        olo[(size_t)t * Dm + d] = __float2bfloat16_rn(r);
    }
}

// ---------------------------------------------------------------------------
// bf16x3 GEMM, PRE-SPLIT operands + ldmatrix fragment loads.
// A: bf16 hi/lo [M,K]. B: bf16 hi/lo [N,K]. 128x128x32 tile, 256 threads,
// double-buffered cp.async. smem stride 40 bf16 (80 B) => ldmatrix
// conflict-free and 16B-aligned.
// ---------------------------------------------------------------------------
#define ASTR 40
#define TILE_BF (128 * ASTR)            // 5120 bf16 units per tile
#define BUF_UNITS (4 * TILE_BF)         // Ahi,Alo,Bhi,Blo
#define GEMM_SMEM (2 * BUF_UNITS * 2)   // 81,920 bytes

template<bool MOE, bool RELU, bool RESID, bool WBF16>
__global__ __launch_bounds__(256, 2)
void gemm_split(const __nv_bfloat16* __restrict__ Ahi,
                const __nv_bfloat16* __restrict__ Alo,
                const __nv_bfloat16* __restrict__ BThi,   // [N,K]
                const __nv_bfloat16* __restrict__ BTlo,
                float* __restrict__ C,
                __nv_bfloat16* __restrict__ Chi,
                __nv_bfloat16* __restrict__ Clo,
                const float* __restrict__ bias,
                const float* __restrict__ resid,
                const int* __restrict__ a_idx,
                const int* __restrict__ c_idx,
                const int* __restrict__ cnt,
                int M, int K, int N)
{
    if (MOE) {
        int z = blockIdx.z;
        M = cnt[z];
        BThi += (size_t)z * K * N;
        BTlo += (size_t)z * K * N;
        bias += (size_t)z * N;
        a_idx += z * LISTCAP;
        c_idx += z * LISTCAP;
    }
    const int m0 = blockIdx.y * 128;
    if (m0 >= M) return;
    const int n0 = blockIdx.x * 128;

    extern __shared__ __nv_bfloat16 bsm[];

    const int tid = threadIdx.x;
    const int wid = tid >> 5;
    const int lane = tid & 31;
    const int g = lane >> 2;
    const int q = lane & 3;
    const int wm = wid & 1;
    const int wn = wid >> 1;

    // --- cp.async assignments: 2 rows per thread per array ---------------
    const int kc = (tid & 3) * 8;            // bf16 col offset within 32-k tile
    int rl[2];
    rl[0] = tid >> 2;
    rl[1] = (tid >> 2) + 64;

    const __nv_bfloat16* a_srchi[2];
    const __nv_bfloat16* a_srclo[2];
    int a_bytes[2];
    #pragma unroll
    for (int i = 0; i < 2; i++) {
        int r = m0 + rl[i];
        bool valid = r < M;
        int gr = valid ? (MOE ? a_idx[r] : r) : 0;
        a_srchi[i] = Ahi + (size_t)gr * K + kc;
        a_srclo[i] = Alo + (size_t)gr * K + kc;
        a_bytes[i] = valid ? 16 : 0;
    }
    const __nv_bfloat16* b_srchi[2];
    const __nv_bfloat16* b_srclo[2];
    #pragma unroll
    for (int i = 0; i < 2; i++) {
        int n = n0 + rl[i];
        b_srchi[i] = BThi + (size_t)n * K + kc;
        b_srclo[i] = BTlo + (size_t)n * K + kc;
    }

    uint32_t dA[2], dB[2];
    #pragma unroll
    for (int i = 0; i < 2; i++) {
        dA[i] = (uint32_t)__cvta_generic_to_shared(&bsm[rl[i] * ASTR + kc]);
        dB[i] = dA[i] + 2 * TILE_BF * 2;
    }
    const uint32_t LO_OFF = TILE_BF * 2;         // bytes to lo tile
    const uint32_t BUFB   = BUF_UNITS * 2;       // bytes to buffer 1

    const int nk = K / 32;

    // prefetch tile 0
    #pragma unroll
    for (int i = 0; i < 2; i++) {
        cp16(dA[i],          a_srchi[i], a_bytes[i]);
        cp16(dA[i] + LO_OFF, a_srclo[i], a_bytes[i]);
        cp16(dB[i],          b_srchi[i], 16);
        cp16(dB[i] + LO_OFF, b_srclo[i], 16);
    }
    cp_commit();

    float acc[4][4][4] = {};

    // ldmatrix per-lane offsets (bytes, relative to tile base)
    // A frag (m16k16): rows base+(lane&15), k + ((lane>>4)*8)
    const uint32_t la_off = (uint32_t)(((wm * 64 + (lane & 15)) * ASTR
                                        + ((lane >> 4) << 3)) * 2);
    // B frag pair (two n8k16 tiles): n = nb + (lane&7) + ((lane>>4)*8),
    // k + (((lane>>3)&1)*8)
    const uint32_t lb_off = (uint32_t)(((wn * 32 + (lane & 7) + ((lane >> 4) << 3)) * ASTR
                                        + (((lane >> 3) & 1) << 3)) * 2);
    const uint32_t sm_base = (uint32_t)__cvta_generic_to_shared(bsm);

    int buf = 0;
    for (int kt = 0; kt < nk; kt++) {
        if (kt + 1 < nk) {
            int k0 = (kt + 1) * 32;
            uint32_t bo = (buf ^ 1) ? BUFB : 0;
            #pragma unroll
            for (int i = 0; i < 2; i++) {
                cp16(dA[i] + bo,          a_srchi[i] + k0, a_bytes[i]);
                cp16(dA[i] + bo + LO_OFF, a_srclo[i] + k0, a_bytes[i]);
                cp16(dB[i] + bo,          b_srchi[i] + k0, 16);
                cp16(dB[i] + bo + LO_OFF, b_srclo[i] + k0, 16);
            }
            cp_commit();
            cp_wait<1>();
        } else {
            cp_wait<0>();
        }
        __syncthreads();

        const uint32_t sA   = sm_base + buf * BUFB;
        const uint32_t sAlo = sA + LO_OFF;
        const uint32_t sB   = sA + 2 * LO_OFF;
        const uint32_t sBlo = sA + 3 * LO_OFF;

        #pragma unroll
        for (int ks = 0; ks < 2; ks++) {
            const uint32_t kbb = (uint32_t)(ks * 16 * 2);   // byte offset along k
            uint32_t bhi[2][4], blo[2][4];
            #pragma unroll
            for (int p = 0; p < 2; p++) {
                uint32_t po = (uint32_t)(p * 16 * ASTR * 2);
                ldmx4(bhi[p], sB   + lb_off + kbb + po);
                ldmx4(blo[p], sBlo + lb_off + kbb + po);
            }
            #pragma unroll
            for (int mt = 0; mt < 4; mt++) {
                uint32_t mo = (uint32_t)(mt * 16 * ASTR * 2);
                uint32_t ah[4], al[4];
                ldmx4(ah, sA   + la_off + kbb + mo);
                ldmx4(al, sAlo + la_off + kbb + mo);
                #pragma unroll
                for (int nt = 0; nt < 4; nt++) {
                    const uint32_t* bh = &bhi[nt >> 1][(nt & 1) * 2];
                    const uint32_t* bl = &blo[nt >> 1][(nt & 1) * 2];
                    mma_bf16(acc[mt][nt], ah, bh);
                    mma_bf16(acc[mt][nt], ah, bl);
                    mma_bf16(acc[mt][nt], al, bh);
                }
            }
        }
        __syncthreads();
        buf ^= 1;
    }

    // --- epilogue --------------------------------------------------------
    #pragma unroll
    for (int mt = 0; mt < 4; mt++) {
        #pragma unroll
        for (int half = 0; half < 2; half++) {
            int r = m0 + wm * 64 + mt * 16 + g + half * 8;
            if (MOE && r >= M) continue;
            int cr = MOE ? c_idx[r] : r;
            #pragma unroll
            for (int nt = 0; nt < 4; nt++) {
                int c = n0 + wn * 32 + nt * 8 + 2 * q;
                float v0 = acc[mt][nt][half * 2 + 0] + bias[c];
                float v1 = acc[mt][nt][half * 2 + 1] + bias[c + 1];
                if (RELU) { v0 = fmaxf(v0, 0.f); v1 = fmaxf(v1, 0.f); }
                if (RESID) {
                    float2 rr = *(const float2*)(resid + (size_t)r * N + c);
                    v0 += rr.x; v1 += rr.y;
                }
                if (WBF16) {
                    uint32_t h, l;
                    split2(v0, v1, h, l);
                    *(uint32_t*)&Chi[(size_t)cr * N + c] = h;
                    *(uint32_t*)&Clo[(size_t)cr * N + c] = l;
                } else {
                    *(float2*)(C + (size_t)cr * N + c) = make_float2(v0, v1);
                }
            }
        }
    }
}

// ---------------------------------------------------------------------------
// Flash attention (fp32) — epilogue writes bf16 hi/lo
// ---------------------------------------------------------------------------
#define ATT_STRIDE 65
#define ATT_SMEM_BYTES (3 * 64 * ATT_STRIDE * 4)

__global__ __launch_bounds__(256)
void attn_kernel(const float* __restrict__ qkv,
                 __nv_bfloat16* __restrict__ ohi,
                 __nv_bfloat16* __restrict__ olo)
{
    extern __shared__ float fsm[];
    float* Qs = fsm;
    float* Ks = fsm + 64 * ATT_STRIDE;
    float* Vs = fsm + 2 * 64 * ATT_STRIDE;
    #define QS(r, c) Qs[(r) * ATT_STRIDE + (c)]
    #define KS(r, c) Ks[(r) * ATT_STRIDE + (c)]
    #define VS(r, c) Vs[(r) * ATT_STRIDE + (c)]

    const int qb = blockIdx.x, h = blockIdx.y, b = blockIdx.z;
    const int tid = threadIdx.x;
    const int tx = tid & 15, ty = tid >> 4;

    const size_t base = (size_t)b * Ss * (3 * Dm);
    const int q0 = qb * 64;
    const float scale = 0.125f;

    #pragma unroll
    for (int r4 = 0; r4 < 4; r4++) {
        int idx = r4 * 256 + tid;
        int row = idx >> 4;
        int c4  = (idx & 15) * 4;
        float4 v = *(const float4*)(qkv + base + (size_t)(q0 + row) * (3 * Dm) + h * 64 + c4);
        QS(row, c4 + 0) = v.x * scale;
        QS(row, c4 + 1) = v.y * scale;
        QS(row, c4 + 2) = v.z * scale;
        QS(row, c4 + 3) = v.w * scale;
    }

    float m[4] = {-1e30f, -1e30f, -1e30f, -1e30f};
    float l[4] = {0.f, 0.f, 0.f, 0.f};
    float o[4][4] = {};

    for (int kt = 0; kt < Ss; kt += 64) {
        __syncthreads();
        #pragma unroll
        for (int r4 = 0; r4 < 4; r4++) {
            int idx = r4 * 256 + tid;
            int row = idx >> 4;
            int c4  = (idx & 15) * 4;
            size_t gg = base + (size_t)(kt + row) * (3 * Dm) + h * 64 + c4;
            float4 kv = *(const float4*)(qkv + gg + Dm);
            float4 vv = *(const float4*)(qkv + gg + 2 * Dm);
            KS(row, c4 + 0) = kv.x; KS(row, c4 + 1) = kv.y;
            KS(row, c4 + 2) = kv.z; KS(row, c4 + 3) = kv.w;
            VS(row, c4 + 0) = vv.x; VS(row, c4 + 1) = vv.y;
            VS(row, c4 + 2) = vv.z; VS(row, c4 + 3) = vv.w;
        }
        __syncthreads();

        float s[4][4] = {};
        #pragma unroll 8
        for (int d = 0; d < 64; d++) {
            float qv[4], kv[4];
            #pragma unroll
            for (int i = 0; i < 4; i++) qv[i] = QS(ty * 4 + i, d);
            #pragma unroll
            for (int j = 0; j < 4; j++) kv[j] = KS(tx * 4 + j, d);
            #pragma unroll
            for (int i = 0; i < 4; i++)
                #pragma unroll
                for (int j = 0; j < 4; j++)
                    s[i][j] = fmaf(qv[i], kv[j], s[i][j]);
        }

        float newm[4], psum[4];
        #pragma unroll
        for (int i = 0; i < 4; i++) {
            float tm = fmaxf(fmaxf(s[i][0], s[i][1]), fmaxf(s[i][2], s[i][3]));
            #pragma unroll
            for (int off = 1; off < 16; off <<= 1)
                tm = fmaxf(tm, __shfl_xor_sync(0xffffffffu, tm, off));
            newm[i] = fmaxf(m[i], tm);
            float ps = 0.f;
            #pragma unroll
            for (int j = 0; j < 4; j++) {
                s[i][j] = __expf(s[i][j] - newm[i]);
                ps += s[i][j];
            }
            #pragma unroll
            for (int off = 1; off < 16; off <<= 1)
                ps += __shfl_xor_sync(0xffffffffu, ps, off);
            psum[i] = ps;
        }

        __syncthreads();
        #pragma unroll
        for (int i = 0; i < 4; i++)
            #pragma unroll
            for (int j = 0; j < 4; j++)
                KS(ty * 4 + i, tx * 4 + j) = s[i][j];
        __syncthreads();

        #pragma unroll
        for (int i = 0; i < 4; i++) {
            float corr = __expf(m[i] - newm[i]);
            l[i] = l[i] * corr + psum[i];
            m[i] = newm[i];
            #pragma unroll
            for (int dd = 0; dd < 4; dd++) o[i][dd] *= corr;
        }

        #pragma unroll 8
        for (int j = 0; j < 64; j++) {
            float pv[4], vv[4];
            #pragma unroll
            for (int i = 0; i < 4; i++) pv[i] = KS(ty * 4 + i, j);
            #pragma unroll
            for (int dd = 0; dd < 4; dd++) vv[dd] = VS(j, tx * 4 + dd);
            #pragma unroll
            for (int i = 0; i < 4; i++)
                #pragma unroll
                for (int dd = 0; dd < 4; dd++)
                    o[i][dd] = fmaf(pv[i], vv[dd], o[i][dd]);
        }
    }

    #pragma unroll
    for (int i = 0; i < 4; i++) {
        float inv = 1.0f / l[i];
        int t = b * Ss + q0 + ty * 4 + i;
        size_t off = (size_t)t * Dm + h * 64 + tx * 4;
        uint32_t h01, l01, h23, l23;
        split2(o[i][0] * inv, o[i][1] * inv, h01, l01);
        split2(o[i][2] * inv, o[i][3] * inv, h23, l23);
        *(uint32_t*)&ohi[off]     = h01;
        *(uint32_t*)&ohi[off + 2] = h23;
        *(uint32_t*)&olo[off]     = l01;
        *(uint32_t*)&olo[off + 2] = l23;
    }
}

// ---------------------------------------------------------------------------
// Gating + routing
// ---------------------------------------------------------------------------
__global__ void gate_route_kernel(const float* __restrict__ h2,
                                  const float* __restrict__ gw,
                                  const float* __restrict__ gb,
                                  int* __restrict__ cnt,
                                  int* __restrict__ tok,
                                  int* __restrict__ dst,
                                  float* __restrict__ gw2)
{
    int t = blockIdx.x * 8 + (threadIdx.x >> 5);
    int lane = threadIdx.x & 31;
    const float* xr = h2 + (size_t)t * Dm;
    float acc[Ee] = {};
    for (int d = lane; d < Dm; d += 32) {
        float xv = xr[d];
        #pragma unroll
        for (int e = 0; e < Ee; e++)
            acc[e] = fmaf(xv, gw[d * Ee + e], acc[e]);
    }
    #pragma unroll
    for (int e = 0; e < Ee; e++)
        #pragma unroll
        for (int off = 16; off; off >>= 1)
            acc[e] += __shfl_xor_sync(0xffffffffu, acc[e], off);

    if (lane == 0) {
        float lg[Ee];
        #pragma unroll
        for (int e = 0; e < Ee; e++) lg[e] = acc[e] + gb[e];
        int i0 = 0;
        #pragma unroll
        for (int e = 1; e < Ee; e++) if (lg[e] > lg[i0]) i0 = e;
        int i1 = -1;
        #pragma unroll
        for (int e = 0; e < Ee; e++) {
            if (e == i0) continue;
            if (i1 < 0 || lg[e] > lg[i1]) i1 = e;
        }
        float e1 = expf(lg[i1] - lg[i0]);
        float denom = 1.0f / (1.0f + e1);
        float g0 = denom, g1 = e1 * denom;
        int p0 = atomicAdd(&cnt[i0], 1);
        tok[i0 * LISTCAP + p0] = t;
        dst[i0 * LISTCAP + p0] = t * 2;
        int p1 = atomicAdd(&cnt[i1], 1);
        tok[i1 * LISTCAP + p1] = t;
        dst[i1 * LISTCAP + p1] = t * 2 + 1;
        gw2[t * 2]     = g0;
        gw2[t * 2 + 1] = g1;
    }
}

// ---------------------------------------------------------------------------
// Final combine
// ---------------------------------------------------------------------------
__global__ void combine_kernel(float* __restrict__ out,
                               const float* __restrict__ moeo,
                               const float* __restrict__ gw2)
{
    int t = blockIdx.x;
    float g0 = gw2[t * 2], g1 = gw2[t * 2 + 1];
    const float* r0 = moeo + (size_t)(t * 2) * Dm;
    const float* r1 = r0 + Dm;
    float* orow = out + (size_t)t * Dm;
    for (int d = threadIdx.x; d < Dm; d += 256)
        orow[d] += g0 * r0[d] + g1 * r1[d];
}

// ---------------------------------------------------------------------------
// Launch
// ---------------------------------------------------------------------------
extern "C" void kernel_launch(void* const* d_in, const int* in_sizes, int n_in,
                              void* d_out, int out_size)
{
    const float* x      = (const float*)d_in[0];
    const float* ln1_g  = (const float*)d_in[1];
    const float* ln1_b  = (const float*)d_in[2];
    const float* w_qkv  = (const float*)d_in[3];
    const float* b_qkv  = (const float*)d_in[4];
    const float* w_o    = (const float*)d_in[5];
    const float* b_o    = (const float*)d_in[6];
    const float* ln2_g  = (const float*)d_in[7];
    const float* ln2_b  = (const float*)d_in[8];
    const float* gate_w = (const float*)d_in[9];
    const float* gate_b = (const float*)d_in[10];
    const float* W1     = (const float*)d_in[11];
    const float* b1     = (const float*)d_in[12];
    const float* W2     = (const float*)d_in[13];
    const float* b2     = (const float*)d_in[14];
    float* out = (float*)d_out;

    float *qkv, *h2, *moeo, *gwp;
    int *cnt, *tok, *dst;
    __nv_bfloat16 *h1hi, *h1lo, *atthi, *attlo, *h2hi, *h2lo, *hidhi, *hidlo;
    __nv_bfloat16 *wqkvThi, *wqkvTlo, *woThi, *woTlo, *W1Thi, *W1Tlo, *W2Thi, *W2Tlo;
    cudaGetSymbolAddress((void**)&qkv,   g_qkv);
    cudaGetSymbolAddress((void**)&h2,    g_h2);
    cudaGetSymbolAddress((void**)&moeo,  g_moeo);
    cudaGetSymbolAddress((void**)&cnt,   g_cnt);
    cudaGetSymbolAddress((void**)&tok,   g_tok);
    cudaGetSymbolAddress((void**)&dst,   g_dst);
    cudaGetSymbolAddress((void**)&gwp,   g_gw);
    cudaGetSymbolAddress((void**)&h1hi,  g_h1hi);
    cudaGetSymbolAddress((void**)&h1lo,  g_h1lo);
    cudaGetSymbolAddress((void**)&atthi, g_atthi);
    cudaGetSymbolAddress((void**)&attlo, g_attlo);
    cudaGetSymbolAddress((void**)&h2hi,  g_h2hi);
    cudaGetSymbolAddress((void**)&h2lo,  g_h2lo);
    cudaGetSymbolAddress((void**)&hidhi, g_hidhi);
    cudaGetSymbolAddress((void**)&hidlo, g_hidlo);
    cudaGetSymbolAddress((void**)&wqkvThi, g_wqkvThi);
    cudaGetSymbolAddress((void**)&wqkvTlo, g_wqkvTlo);
    cudaGetSymbolAddress((void**)&woThi, g_woThi);
    cudaGetSymbolAddress((void**)&woTlo, g_woTlo);
    cudaGetSymbolAddress((void**)&W1Thi, g_W1Thi);
    cudaGetSymbolAddress((void**)&W1Tlo, g_W1Tlo);
    cudaGetSymbolAddress((void**)&W2Thi, g_W2Thi);
    cudaGetSymbolAddress((void**)&W2Tlo, g_W2Tlo);

    static bool attr_done = false;
    if (!attr_done) {
        cudaFuncSetAttribute(attn_kernel,
                             cudaFuncAttributeMaxDynamicSharedMemorySize, ATT_SMEM_BYTES);
        cudaFuncSetAttribute(gemm_split<false, false, false, false>,
                             cudaFuncAttributeMaxDynamicSharedMemorySize, GEMM_SMEM);
        cudaFuncSetAttribute(gemm_split<false, false, true, false>,
                             cudaFuncAttributeMaxDynamicSharedMemorySize, GEMM_SMEM);
        cudaFuncSetAttribute(gemm_split<true, true, false, true>,
                             cudaFuncAttributeMaxDynamicSharedMemorySize, GEMM_SMEM);
        cudaFuncSetAttribute(gemm_split<true, false, false, false>,
                             cudaFuncAttributeMaxDynamicSharedMemorySize, GEMM_SMEM);
        attr_done = true;
    }

    cudaMemsetAsync(cnt, 0, Ee * sizeof(int));

    // 0) weight transpose + split
    dim3 cvtb(32, 8);
    convT_kernel<<<dim3(3 * Dm / 32, Dm / 32, 1), cvtb>>>(w_qkv, wqkvThi, wqkvTlo, Dm, 3 * Dm);
    convT_kernel<<<dim3(Dm / 32, Dm / 32, 1), cvtb>>>(w_o, woThi, woTlo, Dm, Dm);
    convT_kernel<<<dim3(DFFf / 32, Dm / 32, Ee), cvtb>>>(W1, W1Thi, W1Tlo, Dm, DFFf);
    convT_kernel<<<dim3(Dm / 32, DFFf / 32, Ee), cvtb>>>(W2, W2Thi, W2Tlo, DFFf, Dm);

    // 1) LN1 -> bf16 hi/lo
    ln_kernel<<<Tt, 256>>>(x, ln1_g, ln1_b, nullptr, h1hi, h1lo);

    // 2) QKV = h1 @ w_qkv + b_qkv (fp32 out for attention)
    gemm_split<false, false, false, false><<<dim3(3 * Dm / 128, Tt / 128), 256, GEMM_SMEM>>>(
        h1hi, h1lo, wqkvThi, wqkvTlo, qkv, nullptr, nullptr,
        b_qkv, nullptr, nullptr, nullptr, nullptr, Tt, Dm, 3 * Dm);

    // 3) attention -> bf16 hi/lo
    attn_kernel<<<dim3(Ss / 64, Hh, Bb), 256, ATT_SMEM_BYTES>>>(qkv, atthi, attlo);

    // 4) x1 = x + attno @ w_o + b_o  (fp32 -> d_out)
    gemm_split<false, false, true, false><<<dim3(Dm / 128, Tt / 128), 256, GEMM_SMEM>>>(
        atthi, attlo, woThi, woTlo, out, nullptr, nullptr,
        b_o, x, nullptr, nullptr, nullptr, Tt, Dm, Dm);

    // 5) LN2 -> fp32 (gate) + bf16 hi/lo (FFN1 A)
    ln_kernel<<<Tt, 256>>>(out, ln2_g, ln2_b, h2, h2hi, h2lo);

    // 6) gating + routing
    gate_route_kernel<<<Tt / 8, 256>>>(h2, gate_w, gate_b, cnt, tok, dst, gwp);

    // 7) MoE FFN1: hid = relu(h2[tok] @ W1[e] + b1[e]) -> bf16 hi/lo
    gemm_split<true, true, false, true><<<dim3(DFFf / 128, LISTCAP / 128, Ee), 256, GEMM_SMEM>>>(
        h2hi, h2lo, W1Thi, W1Tlo, nullptr, hidhi, hidlo,
        b1, nullptr, tok, dst, cnt, 0, Dm, DFFf);

    // 8) MoE FFN2: moeo = hid @ W2[e] + b2[e] (fp32)
    gemm_split<true, false, false, false><<<dim3(Dm / 128, LISTCAP / 128, Ee), 256, GEMM_SMEM>>>(
        hidhi, hidlo, W2Thi, W2Tlo, moeo, nullptr, nullptr,
        b2, nullptr, dst, dst, cnt, 0, DFFf, Dm);

    // 9) combine
    combine_kernel<<<Tt, 256>>>(out, moeo, gwp);
}

// round 9
// speedup vs baseline: 2.5504x; 1.3321x over previous
#include <cuda_runtime.h>
#include <cuda_bf16.h>
#include <math.h>
#include <stdint.h>

// Problem constants
#define Dm   1024
#define Hh   16
#define DKk  64
#define Ee   8
#define DFFf 4096
#define Ss   2048
#define Bb   2
#define Tt   (Bb * Ss)
#define NPAIR (Tt * 2)
#define LISTCAP 8192

// ---------------------------------------------------------------------------
// Static device scratch
// ---------------------------------------------------------------------------
__device__ float g_h2[(size_t)Tt * Dm];
__device__ float g_moeo[(size_t)NPAIR * Dm];
__device__ int   g_cnt[Ee];
__device__ int   g_tok[Ee * LISTCAP];
__device__ int   g_dst[Ee * LISTCAP];
__device__ float g_gw[NPAIR];

__device__ __nv_bfloat16 g_h1hi[(size_t)Tt * Dm],  g_h1lo[(size_t)Tt * Dm];
__device__ __nv_bfloat16 g_qkvhi[(size_t)Tt * 3 * Dm], g_qkvlo[(size_t)Tt * 3 * Dm];
__device__ __nv_bfloat16 g_atthi[(size_t)Tt * Dm], g_attlo[(size_t)Tt * Dm];
__device__ __nv_bfloat16 g_h2hi[(size_t)Tt * Dm],  g_h2lo[(size_t)Tt * Dm];
__device__ __nv_bfloat16 g_hidhi[(size_t)NPAIR * DFFf], g_hidlo[(size_t)NPAIR * DFFf];
__device__ __nv_bfloat16 g_wqkvThi[(size_t)3 * Dm * Dm], g_wqkvTlo[(size_t)3 * Dm * Dm];
__device__ __nv_bfloat16 g_woThi[(size_t)Dm * Dm],       g_woTlo[(size_t)Dm * Dm];
__device__ __nv_bfloat16 g_W1Thi[(size_t)Ee * DFFf * Dm], g_W1Tlo[(size_t)Ee * DFFf * Dm];
__device__ __nv_bfloat16 g_W2Thi[(size_t)Ee * Dm * DFFf], g_W2Tlo[(size_t)Ee * Dm * DFFf];

// ---------------------------------------------------------------------------
// helpers
// ---------------------------------------------------------------------------
__device__ __forceinline__ void split2(float f0, float f1,
                                       uint32_t& hi, uint32_t& lo) {
    uint32_t h;
    asm("cvt.rn.bf16x2.f32 %0, %1, %2;" : "=r"(h) : "f"(f1), "f"(f0));
    float h0 = __uint_as_float(h << 16);
    float h1 = __uint_as_float(h & 0xffff0000u);
    float r0 = f0 - h0;
    float r1 = f1 - h1;
    uint32_t l;
    asm("cvt.rn.bf16x2.f32 %0, %1, %2;" : "=r"(l) : "f"(r1), "f"(r0));
    hi = h; lo = l;
}
__device__ __forceinline__ void cp16(uint32_t dst, const void* src, int src_bytes) {
    asm volatile("cp.async.cg.shared.global [%0], [%1], 16, %2;"
                 :: "r"(dst), "l"(src), "r"(src_bytes));
}
__device__ __forceinline__ void cp_commit() {
    asm volatile("cp.async.commit_group;");
}
template<int N>
__device__ __forceinline__ void cp_wait() {
    asm volatile("cp.async.wait_group %0;" :: "n"(N));
}
__device__ __forceinline__ void mma_bf16(float* c, const uint32_t* a, const uint32_t* b) {
    asm volatile(
        "mma.sync.aligned.m16n8k16.row.col.f32.bf16.bf16.f32 "
        "{%0,%1,%2,%3}, {%4,%5,%6,%7}, {%8,%9}, {%0,%1,%2,%3};"
        : "+f"(c[0]), "+f"(c[1]), "+f"(c[2]), "+f"(c[3])
        : "r"(a[0]), "r"(a[1]), "r"(a[2]), "r"(a[3]), "r"(b[0]), "r"(b[1]));
}
__device__ __forceinline__ void ldmx4(uint32_t* r, uint32_t addr) {
    asm volatile("ldmatrix.sync.aligned.m8n8.x4.shared.b16 {%0,%1,%2,%3}, [%4];"
                 : "=r"(r[0]), "=r"(r[1]), "=r"(r[2]), "=r"(r[3]) : "r"(addr));
}
__device__ __forceinline__ void ldmx4t(uint32_t* r, uint32_t addr) {
    asm volatile("ldmatrix.sync.aligned.m8n8.x4.trans.shared.b16 {%0,%1,%2,%3}, [%4];"
                 : "=r"(r[0]), "=r"(r[1]), "=r"(r[2]), "=r"(r[3]) : "r"(addr));
}

// ---------------------------------------------------------------------------
// Weight transpose + split: fp32 [K,N] -> bf16 hi/lo [N,K]  (per expert z)
// ---------------------------------------------------------------------------
__global__ void convT_kernel(const float* __restrict__ src,
                             __nv_bfloat16* __restrict__ hi,
                             __nv_bfloat16* __restrict__ lo,
                             int K, int N)
{
    __shared__ float tile[32][33];
    int z = blockIdx.z;
    src += (size_t)z * K * N;
    hi  += (size_t)z * K * N;
    lo  += (size_t)z * K * N;
    int k0 = blockIdx.y * 32, n0 = blockIdx.x * 32;
    int tx = threadIdx.x, ty = threadIdx.y;   // 32 x 8
    #pragma unroll
    for (int i = 0; i < 4; i++)
        tile[ty + 8 * i][tx] = src[(size_t)(k0 + ty + 8 * i) * N + n0 + tx];
    __syncthreads();
    #pragma unroll
    for (int i = 0; i < 4; i++) {
        float v = tile[tx][ty + 8 * i];
        __nv_bfloat16 h = __float2bfloat16_rn(v);
        float r = v - __bfloat162float(h);
        size_t o = (size_t)(n0 + ty + 8 * i) * K + k0 + tx;
        hi[o] = h;
        lo[o] = __float2bfloat16_rn(r);
    }
}

// ---------------------------------------------------------------------------
// LayerNorm: writes bf16 hi/lo, optional fp32
// ---------------------------------------------------------------------------
__global__ void ln_kernel(const float* __restrict__ x,
                          const float* __restrict__ g,
                          const float* __restrict__ b,
                          float* __restrict__ outf,           // may be null
                          __nv_bfloat16* __restrict__ ohi,
                          __nv_bfloat16* __restrict__ olo)
{
    int t = blockIdx.x;
    const float* xr = x + (size_t)t * Dm;
    float s = 0.f, s2 = 0.f;
    for (int d = threadIdx.x; d < Dm; d += 256) {
        float v = xr[d];
        s += v; s2 += v * v;
    }
    #pragma unroll
    for (int off = 16; off; off >>= 1) {
        s  += __shfl_xor_sync(0xffffffffu, s, off);
        s2 += __shfl_xor_sync(0xffffffffu, s2, off);
    }
    __shared__ float sh[18];
    int w = threadIdx.x >> 5;
    if ((threadIdx.x & 31) == 0) { sh[w] = s; sh[w + 8] = s2; }
    __syncthreads();
    if (threadIdx.x == 0) {
        float ts = 0.f, ts2 = 0.f;
        #pragma unroll
        for (int i = 0; i < 8; i++) { ts += sh[i]; ts2 += sh[i + 8]; }
        sh[16] = ts; sh[17] = ts2;
    }
    __syncthreads();
    float mean = sh[16] * (1.0f / Dm);
    float var  = sh[17] * (1.0f / Dm) - mean * mean;
    float rstd = rsqrtf(var + 1e-5f);
    for (int d = threadIdx.x; d < Dm; d += 256) {
        float v = (xr[d] - mean) * rstd * g[d] + b[d];
        if (outf) outf[(size_t)t * Dm + d] = v;
        __nv_bfloat16 h = __float2bfloat16_rn(v);
        float r = v - __bfloat162float(h);
        ohi[(size_t)t * Dm + d] = h;
        olo[(size_t)t * Dm + d] = __float2bfloat16_rn(r);
    }
}

// ---------------------------------------------------------------------------
// bf16x3 GEMM, PRE-SPLIT operands + ldmatrix fragment loads. (R6, passing)
// ---------------------------------------------------------------------------
#define ASTR 40
#define TILE_BF (128 * ASTR)
#define BUF_UNITS (4 * TILE_BF)
#define GEMM_SMEM (2 * BUF_UNITS * 2)   // 81,920 bytes

template<bool MOE, bool RELU, bool RESID, bool WBF16>
__global__ __launch_bounds__(256, 2)
void gemm_split(const __nv_bfloat16* __restrict__ Ahi,
                const __nv_bfloat16* __restrict__ Alo,
                const __nv_bfloat16* __restrict__ BThi,   // [N,K]
                const __nv_bfloat16* __restrict__ BTlo,
                float* __restrict__ C,
                __nv_bfloat16* __restrict__ Chi,
                __nv_bfloat16* __restrict__ Clo,
                const float* __restrict__ bias,
                const float* __restrict__ resid,
                const int* __restrict__ a_idx,
                const int* __restrict__ c_idx,
                const int* __restrict__ cnt,
                int M, int K, int N)
{
    if (MOE) {
        int z = blockIdx.z;
        M = cnt[z];
        BThi += (size_t)z * K * N;
        BTlo += (size_t)z * K * N;
        bias += (size_t)z * N;
        a_idx += z * LISTCAP;
        c_idx += z * LISTCAP;
    }
    const int m0 = blockIdx.y * 128;
    if (m0 >= M) return;
    const int n0 = blockIdx.x * 128;

    extern __shared__ __nv_bfloat16 bsm[];

    const int tid = threadIdx.x;
    const int wid = tid >> 5;
    const int lane = tid & 31;
    const int g = lane >> 2;
    const int q = lane & 3;
    const int wm = wid & 1;
    const int wn = wid >> 1;

    const int kc = (tid & 3) * 8;
    int rl[2];
    rl[0] = tid >> 2;
    rl[1] = (tid >> 2) + 64;

    const __nv_bfloat16* a_srchi[2];
    const __nv_bfloat16* a_srclo[2];
    int a_bytes[2];
    #pragma unroll
    for (int i = 0; i < 2; i++) {
        int r = m0 + rl[i];
        bool valid = r < M;
        int gr = valid ? (MOE ? a_idx[r] : r) : 0;
        a_srchi[i] = Ahi + (size_t)gr * K + kc;
        a_srclo[i] = Alo + (size_t)gr * K + kc;
        a_bytes[i] = valid ? 16 : 0;
    }
    const __nv_bfloat16* b_srchi[2];
    const __nv_bfloat16* b_srclo[2];
    #pragma unroll
    for (int i = 0; i < 2; i++) {
        int n = n0 + rl[i];
        b_srchi[i] = BThi + (size_t)n * K + kc;
        b_srclo[i] = BTlo + (size_t)n * K + kc;
    }

    uint32_t dA[2], dB[2];
    #pragma unroll
    for (int i = 0; i < 2; i++) {
        dA[i] = (uint32_t)__cvta_generic_to_shared(&bsm[rl[i] * ASTR + kc]);
        dB[i] = dA[i] + 2 * TILE_BF * 2;
    }
    const uint32_t LO_OFF = TILE_BF * 2;
    const uint32_t BUFB   = BUF_UNITS * 2;

    const int nk = K / 32;

    #pragma unroll
    for (int i = 0; i < 2; i++) {
        cp16(dA[i],          a_srchi[i], a_bytes[i]);
        cp16(dA[i] + LO_OFF, a_srclo[i], a_bytes[i]);
        cp16(dB[i],          b_srchi[i], 16);
        cp16(dB[i] + LO_OFF, b_srclo[i], 16);
    }
    cp_commit();

    float acc[4][4][4] = {};

    const uint32_t la_off = (uint32_t)(((wm * 64 + (lane & 15)) * ASTR
                                        + ((lane >> 4) << 3)) * 2);
    const uint32_t lb_off = (uint32_t)(((wn * 32 + (lane & 7) + ((lane >> 4) << 3)) * ASTR
                                        + (((lane >> 3) & 1) << 3)) * 2);
    const uint32_t sm_base = (uint32_t)__cvta_generic_to_shared(bsm);

    int buf = 0;
    for (int kt = 0; kt < nk; kt++) {
        if (kt + 1 < nk) {
            int k0 = (kt + 1) * 32;
            uint32_t bo = (buf ^ 1) ? BUFB : 0;
            #pragma unroll
            for (int i = 0; i < 2; i++) {
                cp16(dA[i] + bo,          a_srchi[i] + k0, a_bytes[i]);
                cp16(dA[i] + bo + LO_OFF, a_srclo[i] + k0, a_bytes[i]);
                cp16(dB[i] + bo,          b_srchi[i] + k0, 16);
                cp16(dB[i] + bo + LO_OFF, b_srclo[i] + k0, 16);
            }
            cp_commit();
            cp_wait<1>();
        } else {
            cp_wait<0>();
        }
        __syncthreads();

        const uint32_t sA   = sm_base + buf * BUFB;
        const uint32_t sAlo = sA + LO_OFF;
        const uint32_t sB   = sA + 2 * LO_OFF;
        const uint32_t sBlo = sA + 3 * LO_OFF;

        #pragma unroll
        for (int ks = 0; ks < 2; ks++) {
            const uint32_t kbb = (uint32_t)(ks * 16 * 2);
            uint32_t bhi[2][4], blo[2][4];
            #pragma unroll
            for (int p = 0; p < 2; p++) {
                uint32_t po = (uint32_t)(p * 16 * ASTR * 2);
                ldmx4(bhi[p], sB   + lb_off + kbb + po);
                ldmx4(blo[p], sBlo + lb_off + kbb + po);
            }
            #pragma unroll
            for (int mt = 0; mt < 4; mt++) {
                uint32_t mo = (uint32_t)(mt * 16 * ASTR * 2);
                uint32_t ah[4], al[4];
                ldmx4(ah, sA   + la_off + kbb + mo);
                ldmx4(al, sAlo + la_off + kbb + mo);
                #pragma unroll
                for (int nt = 0; nt < 4; nt++) {
                    const uint32_t* bh = &bhi[nt >> 1][(nt & 1) * 2];
                    const uint32_t* bl = &blo[nt >> 1][(nt & 1) * 2];
                    mma_bf16(acc[mt][nt], ah, bh);
                    mma_bf16(acc[mt][nt], ah, bl);
                    mma_bf16(acc[mt][nt], al, bh);
                }
            }
        }
        __syncthreads();
        buf ^= 1;
    }

    #pragma unroll
    for (int mt = 0; mt < 4; mt++) {
        #pragma unroll
        for (int half = 0; half < 2; half++) {
            int r = m0 + wm * 64 + mt * 16 + g + half * 8;
            if (MOE && r >= M) continue;
            int cr = MOE ? c_idx[r] : r;
            #pragma unroll
            for (int nt = 0; nt < 4; nt++) {
                int c = n0 + wn * 32 + nt * 8 + 2 * q;
                float v0 = acc[mt][nt][half * 2 + 0] + bias[c];
                float v1 = acc[mt][nt][half * 2 + 1] + bias[c + 1];
                if (RELU) { v0 = fmaxf(v0, 0.f); v1 = fmaxf(v1, 0.f); }
                if (RESID) {
                    float2 rr = *(const float2*)(resid + (size_t)r * N + c);
                    v0 += rr.x; v1 += rr.y;
                }
                if (WBF16) {
                    uint32_t h, l;
                    split2(v0, v1, h, l);
                    *(uint32_t*)&Chi[(size_t)cr * N + c] = h;
                    *(uint32_t*)&Clo[(size_t)cr * N + c] = l;
                } else {
                    *(float2*)(C + (size_t)cr * N + c) = make_float2(v0, v1);
                }
            }
        }
    }
}

// ---------------------------------------------------------------------------
// Tensor-core flash attention (bf16 hi/lo 3-term, fp32 softmax).
// CTA: 64 q-rows x (head, batch). 8 warps: wm=wid&3 (m16 strip),
// wn=wid>>2 (kv 32-half of the 64-wide kv tile).
// ---------------------------------------------------------------------------
#define AQS 72
#define AQ_ARR (64 * AQS * 2)                 // 9216 B per bf16 array
#define OFF_QHI 0
#define OFF_QLO AQ_ARR
#define OFF_KV  (2 * AQ_ARR)                  // per buf: Khi,Klo,Vhi,Vlo
#define KVBUF   (4 * AQ_ARR)                  // 36864
#define OFF_RED (OFF_KV + 2 * KVBUF)          // 92160
#define ATT_SMEM (OFF_RED + 1024)             // 93184

__global__ __launch_bounds__(256, 2)
void attn_tc(const __nv_bfloat16* __restrict__ qkvhi,
             const __nv_bfloat16* __restrict__ qkvlo,
             __nv_bfloat16* __restrict__ ohi,
             __nv_bfloat16* __restrict__ olo)
{
    extern __shared__ char asm_[];
    const uint32_t sb = (uint32_t)__cvta_generic_to_shared(asm_);
    const int qb = blockIdx.x, h = blockIdx.y, b = blockIdx.z;
    const int tid = threadIdx.x;
    const int wid = tid >> 5;
    const int lane = tid & 31;
    const int g = lane >> 2;
    const int q = lane & 3;
    const int wm = wid & 3;
    const int wn = wid >> 2;

    float* redmax = (float*)(asm_ + OFF_RED);          // [2][64]
    float* redsum = (float*)(asm_ + OFF_RED + 512);    // [2][64]

    // ---- load Q (hi/lo) into smem ------------------------------------
    {
        int row = tid >> 2;
        const __nv_bfloat16* qh = qkvhi + (size_t)(b * Ss + qb * 64 + row) * (3 * Dm) + h * 64;
        const __nv_bfloat16* ql = qkvlo + (size_t)(b * Ss + qb * 64 + row) * (3 * Dm) + h * 64;
        #pragma unroll
        for (int i = 0; i < 2; i++) {
            int c = (tid & 3) + 4 * i;      // 16B chunk id (0..7)
            cp16(sb + OFF_QHI + (row * AQS + c * 8) * 2, qh + c * 8, 16);
            cp16(sb + OFF_QLO + (row * AQS + c * 8) * 2, ql + c * 8, 16);
        }
    }
    // ---- KV loader lambda --------------------------------------------
    const int kvrow = tid >> 2;
    const __nv_bfloat16* kbase_hi = qkvhi + (size_t)(b * Ss) * (3 * Dm) + Dm + h * 64;
    const __nv_bfloat16* kbase_lo = qkvlo + (size_t)(b * Ss) * (3 * Dm) + Dm + h * 64;
    auto load_kv = [&](int bufi, int kt) {
        uint32_t so = sb + OFF_KV + bufi * KVBUF;
        const __nv_bfloat16* srch = kbase_hi + (size_t)(kt * 64 + kvrow) * (3 * Dm);
        const __nv_bfloat16* srcl = kbase_lo + (size_t)(kt * 64 + kvrow) * (3 * Dm);
        #pragma unroll
        for (int i = 0; i < 2; i++) {
            int c = (tid & 3) + 4 * i;
            uint32_t sm = (uint32_t)((kvrow * AQS + c * 8) * 2);
            cp16(so + sm,              srch + c * 8, 16);           // K hi
            cp16(so + AQ_ARR + sm,     srcl + c * 8, 16);           // K lo
            cp16(so + 2 * AQ_ARR + sm, srch + Dm + c * 8, 16);      // V hi
            cp16(so + 3 * AQ_ARR + sm, srcl + Dm + c * 8, 16);      // V lo
        }
    };
    load_kv(0, 0);
    cp_commit();
    // FIX (R7 NaN): drain the Q + KV(0) cp.async group BEFORE reading Q
    cp_wait<0>();
    __syncthreads();

    // ---- Q fragments into registers ----------------------------------
    const uint32_t qa_off = (uint32_t)(((wm * 16 + (lane & 15)) * AQS
                                        + ((lane >> 4) << 3)) * 2);
    uint32_t qh[4][4], ql[4][4];
    #pragma unroll
    for (int ks = 0; ks < 4; ks++) {
        ldmx4(qh[ks], sb + OFF_QHI + qa_off + ks * 32);
        ldmx4(ql[ks], sb + OFF_QLO + qa_off + ks * 32);
    }

    const uint32_t kb_off = (uint32_t)(((wn * 32 + (lane & 7) + ((lane >> 4) << 3)) * AQS
                                        + (((lane >> 3) & 1) << 3)) * 2);
    const uint32_t vb_row = (uint32_t)(wn * 32 + ((lane >> 3) & 1) * 8 + (lane & 7));
    const uint32_t vb_col = (uint32_t)((lane >> 4) << 3);

    float m0 = -1e30f, m1 = -1e30f, l0 = 0.f, l1 = 0.f;
    float oacc[8][4] = {};

    const int NKV = Ss / 64;   // 32
    for (int kt = 0; kt < NKV; kt++) {
        const int bufi = kt & 1;
        // KV(kt) is already arrived + synced at this point.
        if (kt + 1 < NKV) {
            load_kv(bufi ^ 1, kt + 1);   // prefetch overlaps compute
            cp_commit();
        }
        const uint32_t sK   = sb + OFF_KV + bufi * KVBUF;
        const uint32_t sKlo = sK + AQ_ARR;
        const uint32_t sV   = sK + 2 * AQ_ARR;
        const uint32_t sVlo = sK + 3 * AQ_ARR;

        // ---- S = Q K^T (m16 x n32 per warp) --------------------------
        float s[4][4] = {};
        #pragma unroll
        for (int ks = 0; ks < 4; ks++) {
            uint32_t bh[2][4], bl[2][4];
            #pragma unroll
            for (int p = 0; p < 2; p++) {
                uint32_t po = (uint32_t)(p * 16 * AQS * 2) + (uint32_t)(ks * 32);
                ldmx4(bh[p], sK   + kb_off + po);
                ldmx4(bl[p], sKlo + kb_off + po);
            }
            #pragma unroll
            for (int nt = 0; nt < 4; nt++) {
                const uint32_t* bhp = &bh[nt >> 1][(nt & 1) * 2];
                const uint32_t* blp = &bl[nt >> 1][(nt & 1) * 2];
                mma_bf16(s[nt], qh[ks], bhp);
                mma_bf16(s[nt], qh[ks], blp);
                mma_bf16(s[nt], ql[ks], bhp);
            }
        }
        // scale
        #pragma unroll
        for (int nt = 0; nt < 4; nt++)
            #pragma unroll
            for (int j = 0; j < 4; j++)
                s[nt][j] *= 0.125f;

        // ---- online softmax ------------------------------------------
        float mx0 = -1e30f, mx1 = -1e30f;
        #pragma unroll
        for (int nt = 0; nt < 4; nt++) {
            mx0 = fmaxf(mx0, fmaxf(s[nt][0], s[nt][1]));
            mx1 = fmaxf(mx1, fmaxf(s[nt][2], s[nt][3]));
        }
        #pragma unroll
        for (int off = 1; off < 4; off <<= 1) {
            mx0 = fmaxf(mx0, __shfl_xor_sync(0xffffffffu, mx0, off));
            mx1 = fmaxf(mx1, __shfl_xor_sync(0xffffffffu, mx1, off));
        }
        if (q == 0) {
            redmax[wn * 64 + wm * 16 + g]     = mx0;
            redmax[wn * 64 + wm * 16 + 8 + g] = mx1;
        }
        __syncthreads();
        float om0 = redmax[(wn ^ 1) * 64 + wm * 16 + g];
        float om1 = redmax[(wn ^ 1) * 64 + wm * 16 + 8 + g];
        float nm0 = fmaxf(m0, fmaxf(mx0, om0));
        float nm1 = fmaxf(m1, fmaxf(mx1, om1));

        float ps0 = 0.f, ps1 = 0.f;
        #pragma unroll
        for (int nt = 0; nt < 4; nt++) {
            s[nt][0] = __expf(s[nt][0] - nm0); ps0 += s[nt][0];
            s[nt][1] = __expf(s[nt][1] - nm0); ps0 += s[nt][1];
            s[nt][2] = __expf(s[nt][2] - nm1); ps1 += s[nt][2];
            s[nt][3] = __expf(s[nt][3] - nm1); ps1 += s[nt][3];
        }
        #pragma unroll
        for (int off = 1; off < 4; off <<= 1) {
            ps0 += __shfl_xor_sync(0xffffffffu, ps0, off);
            ps1 += __shfl_xor_sync(0xffffffffu, ps1, off);
        }
        if (q == 0) {
            redsum[wn * 64 + wm * 16 + g]     = ps0;
            redsum[wn * 64 + wm * 16 + 8 + g] = ps1;
        }
        __syncthreads();
        float os0 = redsum[(wn ^ 1) * 64 + wm * 16 + g];
        float os1 = redsum[(wn ^ 1) * 64 + wm * 16 + 8 + g];
        float corr0 = __expf(m0 - nm0);
        float corr1 = __expf(m1 - nm1);
        m0 = nm0; m1 = nm1;
        l0 = l0 * corr0 + ps0 + os0;
        l1 = l1 * corr1 + ps1 + os1;
        #pragma unroll
        for (int nt = 0; nt < 8; nt++) {
            oacc[nt][0] *= corr0; oacc[nt][1] *= corr0;
            oacc[nt][2] *= corr1; oacc[nt][3] *= corr1;
        }

        // ---- O += P V (warp k-range = its n32 of S) ------------------
        #pragma unroll
        for (int sstep = 0; sstep < 2; sstep++) {
            uint32_t ph[4], pl[4];
            split2(s[2 * sstep][0],     s[2 * sstep][1],     ph[0], pl[0]);
            split2(s[2 * sstep][2],     s[2 * sstep][3],     ph[1], pl[1]);
            split2(s[2 * sstep + 1][0], s[2 * sstep + 1][1], ph[2], pl[2]);
            split2(s[2 * sstep + 1][2], s[2 * sstep + 1][3], ph[3], pl[3]);
            #pragma unroll
            for (int dp = 0; dp < 4; dp++) {
                uint32_t vh[4], vl[4];
                uint32_t va = (uint32_t)(((vb_row + sstep * 16) * AQS
                                          + dp * 16 + vb_col) * 2);
                ldmx4t(vh, sV   + va);
                ldmx4t(vl, sVlo + va);
                #pragma unroll
                for (int half = 0; half < 2; half++) {
                    int nt = dp * 2 + half;
                    const uint32_t* bhp = &vh[half * 2];
                    const uint32_t* blp = &vl[half * 2];
                    mma_bf16(oacc[nt], ph, bhp);
                    mma_bf16(oacc[nt], ph, blp);
                    mma_bf16(oacc[nt], pl, bhp);
                }
            }
        }

        // ---- wait for next KV buffer; barrier also fences buffer reuse
        if (kt + 1 < NKV) {
            cp_wait<0>();
            __syncthreads();
        }
    }

    // ---- partner (wn) reduction + epilogue ----------------------------
    float* ob = (float*)asm_;      // reuse Q smem: [64][64] floats = 16KB
    __syncthreads();
    if (wn == 1) {
        #pragma unroll
        for (int nt = 0; nt < 8; nt++)
            #pragma unroll
            for (int j = 0; j < 4; j++) {
                int row = wm * 16 + g + ((j >> 1) << 3);
                int col = nt * 8 + 2 * q + (j & 1);
                ob[row * 64 + col] = oacc[nt][j];
            }
    }
    __syncthreads();
    if (wn == 0) {
        float inv0 = 1.0f / l0, inv1 = 1.0f / l1;
        #pragma unroll
        for (int nt = 0; nt < 8; nt++) {
            int col = nt * 8 + 2 * q;
            #pragma unroll
            for (int hrow = 0; hrow < 2; hrow++) {
                int row = wm * 16 + g + hrow * 8;
                float inv = hrow ? inv1 : inv0;
                float v0 = (oacc[nt][hrow * 2 + 0] + ob[row * 64 + col])     * inv;
                float v1 = (oacc[nt][hrow * 2 + 1] + ob[row * 64 + col + 1]) * inv;
                uint32_t hh, ll;
                split2(v0, v1, hh, ll);
                size_t t = (size_t)(b * Ss + qb * 64 + row);
                size_t o = t * Dm + h * 64 + col;
                *(uint32_t*)&ohi[o] = hh;
                *(uint32_t*)&olo[o] = ll;
            }
        }
    }
}

// ---------------------------------------------------------------------------
// Gating + routing
// ---------------------------------------------------------------------------
__global__ void gate_route_kernel(const float* __restrict__ h2,
                                  const float* __restrict__ gw,
                                  const float* __restrict__ gb,
                                  int* __restrict__ cnt,
                                  int* __restrict__ tok,
                                  int* __restrict__ dst,
                                  float* __restrict__ gw2)
{
    int t = blockIdx.x * 8 + (threadIdx.x >> 5);
    int lane = threadIdx.x & 31;
    const float* xr = h2 + (size_t)t * Dm;
    float acc[Ee] = {};
    for (int d = lane; d < Dm; d += 32) {
        float xv = xr[d];
        #pragma unroll
        for (int e = 0; e < Ee; e++)
            acc[e] = fmaf(xv, gw[d * Ee + e], acc[e]);
    }
    #pragma unroll
    for (int e = 0; e < Ee; e++)
        #pragma unroll
        for (int off = 16; off; off >>= 1)
            acc[e] += __shfl_xor_sync(0xffffffffu, acc[e], off);

    if (lane == 0) {
        float lg[Ee];
        #pragma unroll
        for (int e = 0; e < Ee; e++) lg[e] = acc[e] + gb[e];
        int i0 = 0;
        #pragma unroll
        for (int e = 1; e < Ee; e++) if (lg[e] > lg[i0]) i0 = e;
        int i1 = -1;
        #pragma unroll
        for (int e = 0; e < Ee; e++) {
            if (e == i0) continue;
            if (i1 < 0 || lg[e] > lg[i1]) i1 = e;
        }
        float e1 = expf(lg[i1] - lg[i0]);
        float denom = 1.0f / (1.0f + e1);
        float g0 = denom, g1 = e1 * denom;
        int p0 = atomicAdd(&cnt[i0], 1);
        tok[i0 * LISTCAP + p0] = t;
        dst[i0 * LISTCAP + p0] = t * 2;
        int p1 = atomicAdd(&cnt[i1], 1);
        tok[i1 * LISTCAP + p1] = t;
        dst[i1 * LISTCAP + p1] = t * 2 + 1;
        gw2[t * 2]     = g0;
        gw2[t * 2 + 1] = g1;
    }
}

// ---------------------------------------------------------------------------
// Final combine
// ---------------------------------------------------------------------------
__global__ void combine_kernel(float* __restrict__ out,
                               const float* __restrict__ moeo,
                               const float* __restrict__ gw2)
{
    int t = blockIdx.x;
    float g0 = gw2[t * 2], g1 = gw2[t * 2 + 1];
    const float* r0 = moeo + (size_t)(t * 2) * Dm;
    const float* r1 = r0 + Dm;
    float* orow = out + (size_t)t * Dm;
    for (int d = threadIdx.x; d < Dm; d += 256)
        orow[d] += g0 * r0[d] + g1 * r1[d];
}

// ---------------------------------------------------------------------------
// Launch
// ---------------------------------------------------------------------------
extern "C" void kernel_launch(void* const* d_in, const int* in_sizes, int n_in,
                              void* d_out, int out_size)
{
    const float* x      = (const float*)d_in[0];
    const float* ln1_g  = (const float*)d_in[1];
    const float* ln1_b  = (const float*)d_in[2];
    const float* w_qkv  = (const float*)d_in[3];
    const float* b_qkv  = (const float*)d_in[4];
    const float* w_o    = (const float*)d_in[5];
    const float* b_o    = (const float*)d_in[6];
    const float* ln2_g  = (const float*)d_in[7];
    const float* ln2_b  = (const float*)d_in[8];
    const float* gate_w = (const float*)d_in[9];
    const float* gate_b = (const float*)d_in[10];
    const float* W1     = (const float*)d_in[11];
    const float* b1     = (const float*)d_in[12];
    const float* W2     = (const float*)d_in[13];
    const float* b2     = (const float*)d_in[14];
    float* out = (float*)d_out;

    float *h2, *moeo, *gwp;
    int *cnt, *tok, *dst;
    __nv_bfloat16 *h1hi, *h1lo, *qkvhi, *qkvlo, *atthi, *attlo, *h2hi, *h2lo, *hidhi, *hidlo;
    __nv_bfloat16 *wqkvThi, *wqkvTlo, *woThi, *woTlo, *W1Thi, *W1Tlo, *W2Thi, *W2Tlo;
    cudaGetSymbolAddress((void**)&h2,    g_h2);
    cudaGetSymbolAddress((void**)&moeo,  g_moeo);
    cudaGetSymbolAddress((void**)&cnt,   g_cnt);
    cudaGetSymbolAddress((void**)&tok,   g_tok);
    cudaGetSymbolAddress((void**)&dst,   g_dst);
    cudaGetSymbolAddress((void**)&gwp,   g_gw);
    cudaGetSymbolAddress((void**)&h1hi,  g_h1hi);
    cudaGetSymbolAddress((void**)&h1lo,  g_h1lo);
    cudaGetSymbolAddress((void**)&qkvhi, g_qkvhi);
    cudaGetSymbolAddress((void**)&qkvlo, g_qkvlo);
    cudaGetSymbolAddress((void**)&atthi, g_atthi);
    cudaGetSymbolAddress((void**)&attlo, g_attlo);
    cudaGetSymbolAddress((void**)&h2hi,  g_h2hi);
    cudaGetSymbolAddress((void**)&h2lo,  g_h2lo);
    cudaGetSymbolAddress((void**)&hidhi, g_hidhi);
    cudaGetSymbolAddress((void**)&hidlo, g_hidlo);
    cudaGetSymbolAddress((void**)&wqkvThi, g_wqkvThi);
    cudaGetSymbolAddress((void**)&wqkvTlo, g_wqkvTlo);
    cudaGetSymbolAddress((void**)&woThi, g_woThi);
    cudaGetSymbolAddress((void**)&woTlo, g_woTlo);
    cudaGetSymbolAddress((void**)&W1Thi, g_W1Thi);
    cudaGetSymbolAddress((void**)&W1Tlo, g_W1Tlo);
    cudaGetSymbolAddress((void**)&W2Thi, g_W2Thi);
    cudaGetSymbolAddress((void**)&W2Tlo, g_W2Tlo);

    static bool attr_done = false;
    if (!attr_done) {
        cudaFuncSetAttribute(attn_tc,
                             cudaFuncAttributeMaxDynamicSharedMemorySize, ATT_SMEM);
        cudaFuncSetAttribute(gemm_split<false, false, false, true>,
                             cudaFuncAttributeMaxDynamicSharedMemorySize, GEMM_SMEM);
        cudaFuncSetAttribute(gemm_split<false, false, true, false>,
                             cudaFuncAttributeMaxDynamicSharedMemorySize, GEMM_SMEM);
        cudaFuncSetAttribute(gemm_split<true, true, false, true>,
                             cudaFuncAttributeMaxDynamicSharedMemorySize, GEMM_SMEM);
        cudaFuncSetAttribute(gemm_split<true, false, false, false>,
                             cudaFuncAttributeMaxDynamicSharedMemorySize, GEMM_SMEM);
        attr_done = true;
    }

    cudaMemsetAsync(cnt, 0, Ee * sizeof(int));

    // 0) weight transpose + split
    dim3 cvtb(32, 8);
    convT_kernel<<<dim3(3 * Dm / 32, Dm / 32, 1), cvtb>>>(w_qkv, wqkvThi, wqkvTlo, Dm, 3 * Dm);
    convT_kernel<<<dim3(Dm / 32, Dm / 32, 1), cvtb>>>(w_o, woThi, woTlo, Dm, Dm);
    convT_kernel<<<dim3(DFFf / 32, Dm / 32, Ee), cvtb>>>(W1, W1Thi, W1Tlo, Dm, DFFf);
    convT_kernel<<<dim3(Dm / 32, DFFf / 32, Ee), cvtb>>>(W2, W2Thi, W2Tlo, DFFf, Dm);

    // 1) LN1 -> bf16 hi/lo
    ln_kernel<<<Tt, 256>>>(x, ln1_g, ln1_b, nullptr, h1hi, h1lo);

    // 2) QKV = h1 @ w_qkv + b_qkv  -> bf16 hi/lo
    gemm_split<false, false, false, true><<<dim3(3 * Dm / 128, Tt / 128), 256, GEMM_SMEM>>>(
        h1hi, h1lo, wqkvThi, wqkvTlo, nullptr, qkvhi, qkvlo,
        b_qkv, nullptr, nullptr, nullptr, nullptr, Tt, Dm, 3 * Dm);

    // 3) tensor-core attention -> bf16 hi/lo
    attn_tc<<<dim3(Ss / 64, Hh, Bb), 256, ATT_SMEM>>>(qkvhi, qkvlo, atthi, attlo);

    // 4) x1 = x + attno @ w_o + b_o  (fp32 -> d_out)
    gemm_split<false, false, true, false><<<dim3(Dm / 128, Tt / 128), 256, GEMM_SMEM>>>(
        atthi, attlo, woThi, woTlo, out, nullptr, nullptr,
        b_o, x, nullptr, nullptr, nullptr, Tt, Dm, Dm);

    // 5) LN2 -> fp32 (gate) + bf16 hi/lo (FFN1 A)
    ln_kernel<<<Tt, 256>>>(out, ln2_g, ln2_b, h2, h2hi, h2lo);

    // 6) gating + routing
    gate_route_kernel<<<Tt / 8, 256>>>(h2, gate_w, gate_b, cnt, tok, dst, gwp);

    // 7) MoE FFN1: hid = relu(h2[tok] @ W1[e] + b1[e]) -> bf16 hi/lo
    gemm_split<true, true, false, true><<<dim3(DFFf / 128, LISTCAP / 128, Ee), 256, GEMM_SMEM>>>(
        h2hi, h2lo, W1Thi, W1Tlo, nullptr, hidhi, hidlo,
        b1, nullptr, tok, dst, cnt, 0, Dm, DFFf);

    // 8) MoE FFN2: moeo = hid @ W2[e] + b2[e] (fp32)
    gemm_split<true, false, false, false><<<dim3(Dm / 128, LISTCAP / 128, Ee), 256, GEMM_SMEM>>>(
        hidhi, hidlo, W2Thi, W2Tlo, moeo, nullptr, nullptr,
        b2, nullptr, dst, dst, cnt, 0, DFFf, Dm);

    // 9) combine
    combine_kernel<<<Tt, 256>>>(out, moeo, gwp);
}

// round 10
// speedup vs baseline: 2.5773x; 1.0106x over previous
#include <cuda_runtime.h>
#include <cuda_bf16.h>
#include <math.h>
#include <stdint.h>

// Problem constants
#define Dm   1024
#define Hh   16
#define DKk  64
#define Ee   8
#define DFFf 4096
#define Ss   2048
#define Bb   2
#define Tt   (Bb * Ss)
#define NPAIR (Tt * 2)
#define LISTCAP 8192

// ---------------------------------------------------------------------------
// Static device scratch
// ---------------------------------------------------------------------------
__device__ float g_h2[(size_t)Tt * Dm];
__device__ float g_moeo[(size_t)NPAIR * Dm];
__device__ int   g_cnt[Ee];
__device__ int   g_tok[Ee * LISTCAP];
__device__ int   g_dst[Ee * LISTCAP];
__device__ float g_gw[NPAIR];

__device__ __nv_bfloat16 g_h1hi[(size_t)Tt * Dm],  g_h1lo[(size_t)Tt * Dm];
__device__ __nv_bfloat16 g_qkvhi[(size_t)Tt * 3 * Dm], g_qkvlo[(size_t)Tt * 3 * Dm];
__device__ __nv_bfloat16 g_atthi[(size_t)Tt * Dm], g_attlo[(size_t)Tt * Dm];
__device__ __nv_bfloat16 g_h2hi[(size_t)Tt * Dm],  g_h2lo[(size_t)Tt * Dm];
__device__ __nv_bfloat16 g_hidhi[(size_t)NPAIR * DFFf], g_hidlo[(size_t)NPAIR * DFFf];
__device__ __nv_bfloat16 g_wqkvThi[(size_t)3 * Dm * Dm], g_wqkvTlo[(size_t)3 * Dm * Dm];
__device__ __nv_bfloat16 g_woThi[(size_t)Dm * Dm],       g_woTlo[(size_t)Dm * Dm];
__device__ __nv_bfloat16 g_W1Thi[(size_t)Ee * DFFf * Dm], g_W1Tlo[(size_t)Ee * DFFf * Dm];
__device__ __nv_bfloat16 g_W2Thi[(size_t)Ee * Dm * DFFf], g_W2Tlo[(size_t)Ee * Dm * DFFf];

// ---------------------------------------------------------------------------
// helpers
// ---------------------------------------------------------------------------
__device__ __forceinline__ void split2(float f0, float f1,
                                       uint32_t& hi, uint32_t& lo) {
    uint32_t h;
    asm("cvt.rn.bf16x2.f32 %0, %1, %2;" : "=r"(h) : "f"(f1), "f"(f0));
    float h0 = __uint_as_float(h << 16);
    float h1 = __uint_as_float(h & 0xffff0000u);
    float r0 = f0 - h0;
    float r1 = f1 - h1;
    uint32_t l;
    asm("cvt.rn.bf16x2.f32 %0, %1, %2;" : "=r"(l) : "f"(r1), "f"(r0));
    hi = h; lo = l;
}
__device__ __forceinline__ void cp16(uint32_t dst, const void* src, int src_bytes) {
    asm volatile("cp.async.cg.shared.global [%0], [%1], 16, %2;"
                 :: "r"(dst), "l"(src), "r"(src_bytes));
}
__device__ __forceinline__ void cp_commit() {
    asm volatile("cp.async.commit_group;");
}
template<int N>
__device__ __forceinline__ void cp_wait() {
    asm volatile("cp.async.wait_group %0;" :: "n"(N));
}
__device__ __forceinline__ void mma_bf16(float* c, const uint32_t* a, const uint32_t* b) {
    asm volatile(
        "mma.sync.aligned.m16n8k16.row.col.f32.bf16.bf16.f32 "
        "{%0,%1,%2,%3}, {%4,%5,%6,%7}, {%8,%9}, {%0,%1,%2,%3};"
        : "+f"(c[0]), "+f"(c[1]), "+f"(c[2]), "+f"(c[3])
        : "r"(a[0]), "r"(a[1]), "r"(a[2]), "r"(a[3]), "r"(b[0]), "r"(b[1]));
}
__device__ __forceinline__ void ldmx4(uint32_t* r, uint32_t addr) {
    asm volatile("ldmatrix.sync.aligned.m8n8.x4.shared.b16 {%0,%1,%2,%3}, [%4];"
                 : "=r"(r[0]), "=r"(r[1]), "=r"(r[2]), "=r"(r[3]) : "r"(addr));
}
__device__ __forceinline__ void ldmx4t(uint32_t* r, uint32_t addr) {
    asm volatile("ldmatrix.sync.aligned.m8n8.x4.trans.shared.b16 {%0,%1,%2,%3}, [%4];"
                 : "=r"(r[0]), "=r"(r[1]), "=r"(r[2]), "=r"(r[3]) : "r"(addr));
}

// ---------------------------------------------------------------------------
// Weight transpose + split v2: fp32 [K,N] -> bf16 hi/lo [N,K], vectorized
// 16B stores. Tile: 64 (k) x 32 (n). Grid: (N/32, K/64, E).
// ---------------------------------------------------------------------------
__global__ void convT_kernel(const float* __restrict__ src,
                             __nv_bfloat16* __restrict__ hi,
                             __nv_bfloat16* __restrict__ lo,
                             int K, int N)
{
    __shared__ float tile[64][33];
    int z = blockIdx.z;
    src += (size_t)z * K * N;
    hi  += (size_t)z * K * N;
    lo  += (size_t)z * K * N;
    int k0 = blockIdx.y * 64, n0 = blockIdx.x * 32;
    int t = threadIdx.x;                       // 256 threads
    #pragma unroll
    for (int i = 0; i < 8; i++) {
        int idx = t + i * 256;
        int r = idx >> 5, c = idx & 31;
        tile[r][c] = src[(size_t)(k0 + r) * N + n0 + c];
    }
    __syncthreads();
    int n  = t >> 3;
    int kc = (t & 7) * 8;
    uint32_t hp[4], lp[4];
    #pragma unroll
    for (int j = 0; j < 4; j++) {
        float f0 = tile[kc + 2 * j][n];
        float f1 = tile[kc + 2 * j + 1][n];
        split2(f0, f1, hp[j], lp[j]);
    }
    size_t o = (size_t)(n0 + n) * K + k0 + kc;
    *(uint4*)&hi[o] = *(uint4*)hp;
    *(uint4*)&lo[o] = *(uint4*)lp;
}

// ---------------------------------------------------------------------------
// LayerNorm: writes bf16 hi/lo, optional fp32
// ---------------------------------------------------------------------------
__global__ void ln_kernel(const float* __restrict__ x,
                          const float* __restrict__ g,
                          const float* __restrict__ b,
                          float* __restrict__ outf,           // may be null
                          __nv_bfloat16* __restrict__ ohi,
                          __nv_bfloat16* __restrict__ olo)
{
    int t = blockIdx.x;
    const float* xr = x + (size_t)t * Dm;
    float s = 0.f, s2 = 0.f;
    for (int d = threadIdx.x; d < Dm; d += 256) {
        float v = xr[d];
        s += v; s2 += v * v;
    }
    #pragma unroll
    for (int off = 16; off; off >>= 1) {
        s  += __shfl_xor_sync(0xffffffffu, s, off);
        s2 += __shfl_xor_sync(0xffffffffu, s2, off);
    }
    __shared__ float sh[18];
    int w = threadIdx.x >> 5;
    if ((threadIdx.x & 31) == 0) { sh[w] = s; sh[w + 8] = s2; }
    __syncthreads();
    if (threadIdx.x == 0) {
        float ts = 0.f, ts2 = 0.f;
        #pragma unroll
        for (int i = 0; i < 8; i++) { ts += sh[i]; ts2 += sh[i + 8]; }
        sh[16] = ts; sh[17] = ts2;
    }
    __syncthreads();
    float mean = sh[16] * (1.0f / Dm);
    float var  = sh[17] * (1.0f / Dm) - mean * mean;
    float rstd = rsqrtf(var + 1e-5f);
    for (int d = threadIdx.x; d < Dm; d += 256) {
        float v = (xr[d] - mean) * rstd * g[d] + b[d];
        if (outf) outf[(size_t)t * Dm + d] = v;
        __nv_bfloat16 h = __float2bfloat16_rn(v);
        float r = v - __bfloat162float(h);
        ohi[(size_t)t * Dm + d] = h;
        olo[(size_t)t * Dm + d] = __float2bfloat16_rn(r);
    }
}

// ---------------------------------------------------------------------------
// bf16x3 GEMM, PRE-SPLIT operands + ldmatrix fragment loads.
// R9: single barrier per k-iteration (prefetch -> compute -> wait+sync).
// ---------------------------------------------------------------------------
#define ASTR 40
#define TILE_BF (128 * ASTR)
#define BUF_UNITS (4 * TILE_BF)
#define GEMM_SMEM (2 * BUF_UNITS * 2)   // 81,920 bytes

template<bool MOE, bool RELU, bool RESID, bool WBF16>
__global__ __launch_bounds__(256, 2)
void gemm_split(const __nv_bfloat16* __restrict__ Ahi,
                const __nv_bfloat16* __restrict__ Alo,
                const __nv_bfloat16* __restrict__ BThi,   // [N,K]
                const __nv_bfloat16* __restrict__ BTlo,
                float* __restrict__ C,
                __nv_bfloat16* __restrict__ Chi,
                __nv_bfloat16* __restrict__ Clo,
                const float* __restrict__ bias,
                const float* __restrict__ resid,
                const int* __restrict__ a_idx,
                const int* __restrict__ c_idx,
                const int* __restrict__ cnt,
                int M, int K, int N)
{
    if (MOE) {
        int z = blockIdx.z;
        M = cnt[z];
        BThi += (size_t)z * K * N;
        BTlo += (size_t)z * K * N;
        bias += (size_t)z * N;
        a_idx += z * LISTCAP;
        c_idx += z * LISTCAP;
    }
    const int m0 = blockIdx.y * 128;
    if (m0 >= M) return;
    const int n0 = blockIdx.x * 128;

    extern __shared__ __nv_bfloat16 bsm[];

    const int tid = threadIdx.x;
    const int wid = tid >> 5;
    const int lane = tid & 31;
    const int g = lane >> 2;
    const int q = lane & 3;
    const int wm = wid & 1;
    const int wn = wid >> 1;

    const int kc = (tid & 3) * 8;
    int rl[2];
    rl[0] = tid >> 2;
    rl[1] = (tid >> 2) + 64;

    const __nv_bfloat16* a_srchi[2];
    const __nv_bfloat16* a_srclo[2];
    int a_bytes[2];
    #pragma unroll
    for (int i = 0; i < 2; i++) {
        int r = m0 + rl[i];
        bool valid = r < M;
        int gr = valid ? (MOE ? a_idx[r] : r) : 0;
        a_srchi[i] = Ahi + (size_t)gr * K + kc;
        a_srclo[i] = Alo + (size_t)gr * K + kc;
        a_bytes[i] = valid ? 16 : 0;
    }
    const __nv_bfloat16* b_srchi[2];
    const __nv_bfloat16* b_srclo[2];
    #pragma unroll
    for (int i = 0; i < 2; i++) {
        int n = n0 + rl[i];
        b_srchi[i] = BThi + (size_t)n * K + kc;
        b_srclo[i] = BTlo + (size_t)n * K + kc;
    }

    uint32_t dA[2], dB[2];
    #pragma unroll
    for (int i = 0; i < 2; i++) {
        dA[i] = (uint32_t)__cvta_generic_to_shared(&bsm[rl[i] * ASTR + kc]);
        dB[i] = dA[i] + 2 * TILE_BF * 2;
    }
    const uint32_t LO_OFF = TILE_BF * 2;
    const uint32_t BUFB   = BUF_UNITS * 2;

    const int nk = K / 32;

    // prefetch tile 0 into buffer 0, drain, sync
    #pragma unroll
    for (int i = 0; i < 2; i++) {
        cp16(dA[i],          a_srchi[i], a_bytes[i]);
        cp16(dA[i] + LO_OFF, a_srclo[i], a_bytes[i]);
        cp16(dB[i],          b_srchi[i], 16);
        cp16(dB[i] + LO_OFF, b_srclo[i], 16);
    }
    cp_commit();
    cp_wait<0>();
    __syncthreads();

    float acc[4][4][4] = {};

    const uint32_t la_off = (uint32_t)(((wm * 64 + (lane & 15)) * ASTR
                                        + ((lane >> 4) << 3)) * 2);
    const uint32_t lb_off = (uint32_t)(((wn * 32 + (lane & 7) + ((lane >> 4) << 3)) * ASTR
                                        + (((lane >> 3) & 1) << 3)) * 2);
    const uint32_t sm_base = (uint32_t)__cvta_generic_to_shared(bsm);

    for (int kt = 0; kt < nk; kt++) {
        const int buf = kt & 1;
        // prefetch next tile into the other buffer (its last readers finished
        // before the tail barrier of iteration kt-1)
        if (kt + 1 < nk) {
            int k0 = (kt + 1) * 32;
            uint32_t bo = (buf ^ 1) ? BUFB : 0;
            #pragma unroll
            for (int i = 0; i < 2; i++) {
                cp16(dA[i] + bo,          a_srchi[i] + k0, a_bytes[i]);
                cp16(dA[i] + bo + LO_OFF, a_srclo[i] + k0, a_bytes[i]);
                cp16(dB[i] + bo,          b_srchi[i] + k0, 16);
                cp16(dB[i] + bo + LO_OFF, b_srclo[i] + k0, 16);
            }
            cp_commit();
        }

        const uint32_t sA   = sm_base + buf * BUFB;
        const uint32_t sAlo = sA + LO_OFF;
        const uint32_t sB   = sA + 2 * LO_OFF;
        const uint32_t sBlo = sA + 3 * LO_OFF;

        #pragma unroll
        for (int ks = 0; ks < 2; ks++) {
            const uint32_t kbb = (uint32_t)(ks * 16 * 2);
            uint32_t bhi[2][4], blo[2][4];
            #pragma unroll
            for (int p = 0; p < 2; p++) {
                uint32_t po = (uint32_t)(p * 16 * ASTR * 2);
                ldmx4(bhi[p], sB   + lb_off + kbb + po);
                ldmx4(blo[p], sBlo + lb_off + kbb + po);
            }
            #pragma unroll
            for (int mt = 0; mt < 4; mt++) {
                uint32_t mo = (uint32_t)(mt * 16 * ASTR * 2);
                uint32_t ah[4], al[4];
                ldmx4(ah, sA   + la_off + kbb + mo);
                ldmx4(al, sAlo + la_off + kbb + mo);
                #pragma unroll
                for (int nt = 0; nt < 4; nt++) {
                    const uint32_t* bh = &bhi[nt >> 1][(nt & 1) * 2];
                    const uint32_t* bl = &blo[nt >> 1][(nt & 1) * 2];
                    mma_bf16(acc[mt][nt], ah, bh);
                    mma_bf16(acc[mt][nt], ah, bl);
                    mma_bf16(acc[mt][nt], al, bh);
                }
            }
        }

        // single tail barrier: next tile arrived AND all warps done with buf
        if (kt + 1 < nk) {
            cp_wait<0>();
            __syncthreads();
        }
    }

    #pragma unroll
    for (int mt = 0; mt < 4; mt++) {
        #pragma unroll
        for (int half = 0; half < 2; half++) {
            int r = m0 + wm * 64 + mt * 16 + g + half * 8;
            if (MOE && r >= M) continue;
            int cr = MOE ? c_idx[r] : r;
            #pragma unroll
            for (int nt = 0; nt < 4; nt++) {
                int c = n0 + wn * 32 + nt * 8 + 2 * q;
                float v0 = acc[mt][nt][half * 2 + 0] + bias[c];
                float v1 = acc[mt][nt][half * 2 + 1] + bias[c + 1];
                if (RELU) { v0 = fmaxf(v0, 0.f); v1 = fmaxf(v1, 0.f); }
                if (RESID) {
                    float2 rr = *(const float2*)(resid + (size_t)r * N + c);
                    v0 += rr.x; v1 += rr.y;
                }
                if (WBF16) {
                    uint32_t h, l;
                    split2(v0, v1, h, l);
                    *(uint32_t*)&Chi[(size_t)cr * N + c] = h;
                    *(uint32_t*)&Clo[(size_t)cr * N + c] = l;
                } else {
                    *(float2*)(C + (size_t)cr * N + c) = make_float2(v0, v1);
                }
            }
        }
    }
}

// ---------------------------------------------------------------------------
// Tensor-core flash attention (bf16 hi/lo 3-term, fp32 softmax). (R8, passing)
// ---------------------------------------------------------------------------
#define AQS 72
#define AQ_ARR (64 * AQS * 2)                 // 9216 B per bf16 array
#define OFF_QHI 0
#define OFF_QLO AQ_ARR
#define OFF_KV  (2 * AQ_ARR)                  // per buf: Khi,Klo,Vhi,Vlo
#define KVBUF   (4 * AQ_ARR)                  // 36864
#define OFF_RED (OFF_KV + 2 * KVBUF)          // 92160
#define ATT_SMEM (OFF_RED + 1024)             // 93184

__global__ __launch_bounds__(256, 2)
void attn_tc(const __nv_bfloat16* __restrict__ qkvhi,
             const __nv_bfloat16* __restrict__ qkvlo,
             __nv_bfloat16* __restrict__ ohi,
             __nv_bfloat16* __restrict__ olo)
{
    extern __shared__ char asm_[];
    const uint32_t sb = (uint32_t)__cvta_generic_to_shared(asm_);
    const int qb = blockIdx.x, h = blockIdx.y, b = blockIdx.z;
    const int tid = threadIdx.x;
    const int wid = tid >> 5;
    const int lane = tid & 31;
    const int g = lane >> 2;
    const int q = lane & 3;
    const int wm = wid & 3;
    const int wn = wid >> 2;

    float* redmax = (float*)(asm_ + OFF_RED);          // [2][64]
    float* redsum = (float*)(asm_ + OFF_RED + 512);    // [2][64]

    // ---- load Q (hi/lo) into smem ------------------------------------
    {
        int row = tid >> 2;
        const __nv_bfloat16* qh = qkvhi + (size_t)(b * Ss + qb * 64 + row) * (3 * Dm) + h * 64;
        const __nv_bfloat16* ql = qkvlo + (size_t)(b * Ss + qb * 64 + row) * (3 * Dm) + h * 64;
        #pragma unroll
        for (int i = 0; i < 2; i++) {
            int c = (tid & 3) + 4 * i;      // 16B chunk id (0..7)
            cp16(sb + OFF_QHI + (row * AQS + c * 8) * 2, qh + c * 8, 16);
            cp16(sb + OFF_QLO + (row * AQS + c * 8) * 2, ql + c * 8, 16);
        }
    }
    // ---- KV loader lambda --------------------------------------------
    const int kvrow = tid >> 2;
    const __nv_bfloat16* kbase_hi = qkvhi + (size_t)(b * Ss) * (3 * Dm) + Dm + h * 64;
    const __nv_bfloat16* kbase_lo = qkvlo + (size_t)(b * Ss) * (3 * Dm) + Dm + h * 64;
    auto load_kv = [&](int bufi, int kt) {
        uint32_t so = sb + OFF_KV + bufi * KVBUF;
        const __nv_bfloat16* srch = kbase_hi + (size_t)(kt * 64 + kvrow) * (3 * Dm);
        const __nv_bfloat16* srcl = kbase_lo + (size_t)(kt * 64 + kvrow) * (3 * Dm);
        #pragma unroll
        for (int i = 0; i < 2; i++) {
            int c = (tid & 3) + 4 * i;
            uint32_t sm = (uint32_t)((kvrow * AQS + c * 8) * 2);
            cp16(so + sm,              srch + c * 8, 16);           // K hi
            cp16(so + AQ_ARR + sm,     srcl + c * 8, 16);           // K lo
            cp16(so + 2 * AQ_ARR + sm, srch + Dm + c * 8, 16);      // V hi
            cp16(so + 3 * AQ_ARR + sm, srcl + Dm + c * 8, 16);      // V lo
        }
    };
    load_kv(0, 0);
    cp_commit();
    cp_wait<0>();
    __syncthreads();

    // ---- Q fragments into registers ----------------------------------
    const uint32_t qa_off = (uint32_t)(((wm * 16 + (lane & 15)) * AQS
                                        + ((lane >> 4) << 3)) * 2);
    uint32_t qh[4][4], ql[4][4];
    #pragma unroll
    for (int ks = 0; ks < 4; ks++) {
        ldmx4(qh[ks], sb + OFF_QHI + qa_off + ks * 32);
        ldmx4(ql[ks], sb + OFF_QLO + qa_off + ks * 32);
    }

    const uint32_t kb_off = (uint32_t)(((wn * 32 + (lane & 7) + ((lane >> 4) << 3)) * AQS
                                        + (((lane >> 3) & 1) << 3)) * 2);
    const uint32_t vb_row = (uint32_t)(wn * 32 + ((lane >> 3) & 1) * 8 + (lane & 7));
    const uint32_t vb_col = (uint32_t)((lane >> 4) << 3);

    float m0 = -1e30f, m1 = -1e30f, l0 = 0.f, l1 = 0.f;
    float oacc[8][4] = {};

    const int NKV = Ss / 64;   // 32
    for (int kt = 0; kt < NKV; kt++) {
        const int bufi = kt & 1;
        if (kt + 1 < NKV) {
            load_kv(bufi ^ 1, kt + 1);   // prefetch overlaps compute
            cp_commit();
        }
        const uint32_t sK   = sb + OFF_KV + bufi * KVBUF;
        const uint32_t sKlo = sK + AQ_ARR;
        const uint32_t sV   = sK + 2 * AQ_ARR;
        const uint32_t sVlo = sK + 3 * AQ_ARR;

        // ---- S = Q K^T (m16 x n32 per warp) --------------------------
        float s[4][4] = {};
        #pragma unroll
        for (int ks = 0; ks < 4; ks++) {
            uint32_t bh[2][4], bl[2][4];
            #pragma unroll
            for (int p = 0; p < 2; p++) {
                uint32_t po = (uint32_t)(p * 16 * AQS * 2) + (uint32_t)(ks * 32);
                ldmx4(bh[p], sK   + kb_off + po);
                ldmx4(bl[p], sKlo + kb_off + po);
            }
            #pragma unroll
            for (int nt = 0; nt < 4; nt++) {
                const uint32_t* bhp = &bh[nt >> 1][(nt & 1) * 2];
                const uint32_t* blp = &bl[nt >> 1][(nt & 1) * 2];
                mma_bf16(s[nt], qh[ks], bhp);
                mma_bf16(s[nt], qh[ks], blp);
                mma_bf16(s[nt], ql[ks], bhp);
            }
        }
        // scale
        #pragma unroll
        for (int nt = 0; nt < 4; nt++)
            #pragma unroll
            for (int j = 0; j < 4; j++)
                s[nt][j] *= 0.125f;

        // ---- online softmax ------------------------------------------
        float mx0 = -1e30f, mx1 = -1e30f;
        #pragma unroll
        for (int nt = 0; nt < 4; nt++) {
            mx0 = fmaxf(mx0, fmaxf(s[nt][0], s[nt][1]));
            mx1 = fmaxf(mx1, fmaxf(s[nt][2], s[nt][3]));
        }
        #pragma unroll
        for (int off = 1; off < 4; off <<= 1) {
            mx0 = fmaxf(mx0, __shfl_xor_sync(0xffffffffu, mx0, off));
            mx1 = fmaxf(mx1, __shfl_xor_sync(0xffffffffu, mx1, off));
        }
        if (q == 0) {
            redmax[wn * 64 + wm * 16 + g]     = mx0;
            redmax[wn * 64 + wm * 16 + 8 + g] = mx1;
        }
        __syncthreads();
        float om0 = redmax[(wn ^ 1) * 64 + wm * 16 + g];
        float om1 = redmax[(wn ^ 1) * 64 + wm * 16 + 8 + g];
        float nm0 = fmaxf(m0, fmaxf(mx0, om0));
        float nm1 = fmaxf(m1, fmaxf(mx1, om1));

        float ps0 = 0.f, ps1 = 0.f;
        #pragma unroll
        for (int nt = 0; nt < 4; nt++) {
            s[nt][0] = __expf(s[nt][0] - nm0); ps0 += s[nt][0];
            s[nt][1] = __expf(s[nt][1] - nm0); ps0 += s[nt][1];
            s[nt][2] = __expf(s[nt][2] - nm1); ps1 += s[nt][2];
            s[nt][3] = __expf(s[nt][3] - nm1); ps1 += s[nt][3];
        }
        #pragma unroll
        for (int off = 1; off < 4; off <<= 1) {
            ps0 += __shfl_xor_sync(0xffffffffu, ps0, off);
            ps1 += __shfl_xor_sync(0xffffffffu, ps1, off);
        }
        if (q == 0) {
            redsum[wn * 64 + wm * 16 + g]     = ps0;
            redsum[wn * 64 + wm * 16 + 8 + g] = ps1;
        }
        __syncthreads();
        float os0 = redsum[(wn ^ 1) * 64 + wm * 16 + g];
        float os1 = redsum[(wn ^ 1) * 64 + wm * 16 + 8 + g];
        float corr0 = __expf(m0 - nm0);
        float corr1 = __expf(m1 - nm1);
        m0 = nm0; m1 = nm1;
        l0 = l0 * corr0 + ps0 + os0;
        l1 = l1 * corr1 + ps1 + os1;
        #pragma unroll
        for (int nt = 0; nt < 8; nt++) {
            oacc[nt][0] *= corr0; oacc[nt][1] *= corr0;
            oacc[nt][2] *= corr1; oacc[nt][3] *= corr1;
        }

        // ---- O += P V (warp k-range = its n32 of S) ------------------
        #pragma unroll
        for (int sstep = 0; sstep < 2; sstep++) {
            uint32_t ph[4], pl[4];
            split2(s[2 * sstep][0],     s[2 * sstep][1],     ph[0], pl[0]);
            split2(s[2 * sstep][2],     s[2 * sstep][3],     ph[1], pl[1]);
            split2(s[2 * sstep + 1][0], s[2 * sstep + 1][1], ph[2], pl[2]);
            split2(s[2 * sstep + 1][2], s[2 * sstep + 1][3], ph[3], pl[3]);
            #pragma unroll
            for (int dp = 0; dp < 4; dp++) {
                uint32_t vh[4], vl[4];
                uint32_t va = (uint32_t)(((vb_row + sstep * 16) * AQS
                                          + dp * 16 + vb_col) * 2);
                ldmx4t(vh, sV   + va);
                ldmx4t(vl, sVlo + va);
                #pragma unroll
                for (int half = 0; half < 2; half++) {
                    int nt = dp * 2 + half;
                    const uint32_t* bhp = &vh[half * 2];
                    const uint32_t* blp = &vl[half * 2];
                    mma_bf16(oacc[nt], ph, bhp);
                    mma_bf16(oacc[nt], ph, blp);
                    mma_bf16(oacc[nt], pl, bhp);
                }
            }
        }

        if (kt + 1 < NKV) {
            cp_wait<0>();
            __syncthreads();
        }
    }

    // ---- partner (wn) reduction + epilogue ----------------------------
    float* ob = (float*)asm_;      // reuse Q smem: [64][64] floats = 16KB
    __syncthreads();
    if (wn == 1) {
        #pragma unroll
        for (int nt = 0; nt < 8; nt++)
            #pragma unroll
            for (int j = 0; j < 4; j++) {
                int row = wm * 16 + g + ((j >> 1) << 3);
                int col = nt * 8 + 2 * q + (j & 1);
                ob[row * 64 + col] = oacc[nt][j];
            }
    }
    __syncthreads();
    if (wn == 0) {
        float inv0 = 1.0f / l0, inv1 = 1.0f / l1;
        #pragma unroll
        for (int nt = 0; nt < 8; nt++) {
            int col = nt * 8 + 2 * q;
            #pragma unroll
            for (int hrow = 0; hrow < 2; hrow++) {
                int row = wm * 16 + g + hrow * 8;
                float inv = hrow ? inv1 : inv0;
                float v0 = (oacc[nt][hrow * 2 + 0] + ob[row * 64 + col])     * inv;
                float v1 = (oacc[nt][hrow * 2 + 1] + ob[row * 64 + col + 1]) * inv;
                uint32_t hh, ll;
                split2(v0, v1, hh, ll);
                size_t t = (size_t)(b * Ss + qb * 64 + row);
                size_t o = t * Dm + h * 64 + col;
                *(uint32_t*)&ohi[o] = hh;
                *(uint32_t*)&olo[o] = ll;
            }
        }
    }
}

// ---------------------------------------------------------------------------
// Gating + routing
// ---------------------------------------------------------------------------
__global__ void gate_route_kernel(const float* __restrict__ h2,
                                  const float* __restrict__ gw,
                                  const float* __restrict__ gb,
                                  int* __restrict__ cnt,
                                  int* __restrict__ tok,
                                  int* __restrict__ dst,
                                  float* __restrict__ gw2)
{
    int t = blockIdx.x * 8 + (threadIdx.x >> 5);
    int lane = threadIdx.x & 31;
    const float* xr = h2 + (size_t)t * Dm;
    float acc[Ee] = {};
    for (int d = lane; d < Dm; d += 32) {
        float xv = xr[d];
        #pragma unroll
        for (int e = 0; e < Ee; e++)
            acc[e] = fmaf(xv, gw[d * Ee + e], acc[e]);
    }
    #pragma unroll
    for (int e = 0; e < Ee; e++)
        #pragma unroll
        for (int off = 16; off; off >>= 1)
            acc[e] += __shfl_xor_sync(0xffffffffu, acc[e], off);

    if (lane == 0) {
        float lg[Ee];
        #pragma unroll
        for (int e = 0; e < Ee; e++) lg[e] = acc[e] + gb[e];
        int i0 = 0;
        #pragma unroll
        for (int e = 1; e < Ee; e++) if (lg[e] > lg[i0]) i0 = e;
        int i1 = -1;
        #pragma unroll
        for (int e = 0; e < Ee; e++) {
            if (e == i0) continue;
            if (i1 < 0 || lg[e] > lg[i1]) i1 = e;
        }
        float e1 = expf(lg[i1] - lg[i0]);
        float denom = 1.0f / (1.0f + e1);
        float g0 = denom, g1 = e1 * denom;
        int p0 = atomicAdd(&cnt[i0], 1);
        tok[i0 * LISTCAP + p0] = t;
        dst[i0 * LISTCAP + p0] = t * 2;
        int p1 = atomicAdd(&cnt[i1], 1);
        tok[i1 * LISTCAP + p1] = t;
        dst[i1 * LISTCAP + p1] = t * 2 + 1;
        gw2[t * 2]     = g0;
        gw2[t * 2 + 1] = g1;
    }
}

// ---------------------------------------------------------------------------
// Final combine
// ---------------------------------------------------------------------------
__global__ void combine_kernel(float* __restrict__ out,
                               const float* __restrict__ moeo,
                               const float* __restrict__ gw2)
{
    int t = blockIdx.x;
    float g0 = gw2[t * 2], g1 = gw2[t * 2 + 1];
    const float* r0 = moeo + (size_t)(t * 2) * Dm;
    const float* r1 = r0 + Dm;
    float* orow = out + (size_t)t * Dm;
    for (int d = threadIdx.x; d < Dm; d += 256)
        orow[d] += g0 * r0[d] + g1 * r1[d];
}

// ---------------------------------------------------------------------------
// Launch
// ---------------------------------------------------------------------------
extern "C" void kernel_launch(void* const* d_in, const int* in_sizes, int n_in,
                              void* d_out, int out_size)
{
    const float* x      = (const float*)d_in[0];
    const float* ln1_g  = (const float*)d_in[1];
    const float* ln1_b  = (const float*)d_in[2];
    const float* w_qkv  = (const float*)d_in[3];
    const float* b_qkv  = (const float*)d_in[4];
    const float* w_o    = (const float*)d_in[5];
    const float* b_o    = (const float*)d_in[6];
    const float* ln2_g  = (const float*)d_in[7];
    const float* ln2_b  = (const float*)d_in[8];
    const float* gate_w = (const float*)d_in[9];
    const float* gate_b = (const float*)d_in[10];
    const float* W1     = (const float*)d_in[11];
    const float* b1     = (const float*)d_in[12];
    const float* W2     = (const float*)d_in[13];
    const float* b2     = (const float*)d_in[14];
    float* out = (float*)d_out;

    float *h2, *moeo, *gwp;
    int *cnt, *tok, *dst;
    __nv_bfloat16 *h1hi, *h1lo, *qkvhi, *qkvlo, *atthi, *attlo, *h2hi, *h2lo, *hidhi, *hidlo;
    __nv_bfloat16 *wqkvThi, *wqkvTlo, *woThi, *woTlo, *W1Thi, *W1Tlo, *W2Thi, *W2Tlo;
    cudaGetSymbolAddress((void**)&h2,    g_h2);
    cudaGetSymbolAddress((void**)&moeo,  g_moeo);
    cudaGetSymbolAddress((void**)&cnt,   g_cnt);
    cudaGetSymbolAddress((void**)&tok,   g_tok);
    cudaGetSymbolAddress((void**)&dst,   g_dst);
    cudaGetSymbolAddress((void**)&gwp,   g_gw);
    cudaGetSymbolAddress((void**)&h1hi,  g_h1hi);
    cudaGetSymbolAddress((void**)&h1lo,  g_h1lo);
    cudaGetSymbolAddress((void**)&qkvhi, g_qkvhi);
    cudaGetSymbolAddress((void**)&qkvlo, g_qkvlo);
    cudaGetSymbolAddress((void**)&atthi, g_atthi);
    cudaGetSymbolAddress((void**)&attlo, g_attlo);
    cudaGetSymbolAddress((void**)&h2hi,  g_h2hi);
    cudaGetSymbolAddress((void**)&h2lo,  g_h2lo);
    cudaGetSymbolAddress((void**)&hidhi, g_hidhi);
    cudaGetSymbolAddress((void**)&hidlo, g_hidlo);
    cudaGetSymbolAddress((void**)&wqkvThi, g_wqkvThi);
    cudaGetSymbolAddress((void**)&wqkvTlo, g_wqkvTlo);
    cudaGetSymbolAddress((void**)&woThi, g_woThi);
    cudaGetSymbolAddress((void**)&woTlo, g_woTlo);
    cudaGetSymbolAddress((void**)&W1Thi, g_W1Thi);
    cudaGetSymbolAddress((void**)&W1Tlo, g_W1Tlo);
    cudaGetSymbolAddress((void**)&W2Thi, g_W2Thi);
    cudaGetSymbolAddress((void**)&W2Tlo, g_W2Tlo);

    static bool attr_done = false;
    if (!attr_done) {
        cudaFuncSetAttribute(attn_tc,
                             cudaFuncAttributeMaxDynamicSharedMemorySize, ATT_SMEM);
        cudaFuncSetAttribute(gemm_split<false, false, false, true>,
                             cudaFuncAttributeMaxDynamicSharedMemorySize, GEMM_SMEM);
        cudaFuncSetAttribute(gemm_split<false, false, true, false>,
                             cudaFuncAttributeMaxDynamicSharedMemorySize, GEMM_SMEM);
        cudaFuncSetAttribute(gemm_split<true, true, false, true>,
                             cudaFuncAttributeMaxDynamicSharedMemorySize, GEMM_SMEM);
        cudaFuncSetAttribute(gemm_split<true, false, false, false>,
                             cudaFuncAttributeMaxDynamicSharedMemorySize, GEMM_SMEM);
        attr_done = true;
    }

    cudaMemsetAsync(cnt, 0, Ee * sizeof(int));

    // 0) weight transpose + split (v2: 64x32 tiles, 16B stores)
    convT_kernel<<<dim3(3 * Dm / 32, Dm / 64, 1), 256>>>(w_qkv, wqkvThi, wqkvTlo, Dm, 3 * Dm);
    convT_kernel<<<dim3(Dm / 32, Dm / 64, 1), 256>>>(w_o, woThi, woTlo, Dm, Dm);
    convT_kernel<<<dim3(DFFf / 32, Dm / 64, Ee), 256>>>(W1, W1Thi, W1Tlo, Dm, DFFf);
    convT_kernel<<<dim3(Dm / 32, DFFf / 64, Ee), 256>>>(W2, W2Thi, W2Tlo, DFFf, Dm);

    // 1) LN1 -> bf16 hi/lo
    ln_kernel<<<Tt, 256>>>(x, ln1_g, ln1_b, nullptr, h1hi, h1lo);

    // 2) QKV = h1 @ w_qkv + b_qkv  -> bf16 hi/lo
    gemm_split<false, false, false, true><<<dim3(3 * Dm / 128, Tt / 128), 256, GEMM_SMEM>>>(
        h1hi, h1lo, wqkvThi, wqkvTlo, nullptr, qkvhi, qkvlo,
        b_qkv, nullptr, nullptr, nullptr, nullptr, Tt, Dm, 3 * Dm);

    // 3) tensor-core attention -> bf16 hi/lo
    attn_tc<<<dim3(Ss / 64, Hh, Bb), 256, ATT_SMEM>>>(qkvhi, qkvlo, atthi, attlo);

    // 4) x1 = x + attno @ w_o + b_o  (fp32 -> d_out)
    gemm_split<false, false, true, false><<<dim3(Dm / 128, Tt / 128), 256, GEMM_SMEM>>>(
        atthi, attlo, woThi, woTlo, out, nullptr, nullptr,
        b_o, x, nullptr, nullptr, nullptr, Tt, Dm, Dm);

    // 5) LN2 -> fp32 (gate) + bf16 hi/lo (FFN1 A)
    ln_kernel<<<Tt, 256>>>(out, ln2_g, ln2_b, h2, h2hi, h2lo);

    // 6) gating + routing
    gate_route_kernel<<<Tt / 8, 256>>>(h2, gate_w, gate_b, cnt, tok, dst, gwp);

    // 7) MoE FFN1: hid = relu(h2[tok] @ W1[e] + b1[e]) -> bf16 hi/lo
    gemm_split<true, true, false, true><<<dim3(DFFf / 128, LISTCAP / 128, Ee), 256, GEMM_SMEM>>>(
        h2hi, h2lo, W1Thi, W1Tlo, nullptr, hidhi, hidlo,
        b1, nullptr, tok, dst, cnt, 0, Dm, DFFf);

    // 8) MoE FFN2: moeo = hid @ W2[e] + b2[e] (fp32)
    gemm_split<true, false, false, false><<<dim3(Dm / 128, LISTCAP / 128, Ee), 256, GEMM_SMEM>>>(
        hidhi, hidlo, W2Thi, W2Tlo, moeo, nullptr, nullptr,
        b2, nullptr, dst, dst, cnt, 0, DFFf, Dm);

    // 9) combine
    combine_kernel<<<Tt, 256>>>(out, moeo, gwp);
}

// round 11
// speedup vs baseline: 3.1586x; 1.2255x over previous
#include <cuda_runtime.h>
#include <cuda_fp16.h>
#include <math.h>
#include <stdint.h>

// Problem constants
#define Dm   1024
#define Hh   16
#define DKk  64
#define Ee   8
#define DFFf 4096
#define Ss   2048
#define Bb   2
#define Tt   (Bb * Ss)
#define NPAIR (Tt * 2)
#define LISTCAP 8192

// ---------------------------------------------------------------------------
// Static device scratch
// ---------------------------------------------------------------------------
__device__ float g_h2[(size_t)Tt * Dm];
__device__ float g_moeo[(size_t)NPAIR * Dm];
__device__ int   g_cnt[Ee];
__device__ int   g_tok[Ee * LISTCAP];
__device__ int   g_dst[Ee * LISTCAP];
__device__ float g_gw[NPAIR];

__device__ __half g_h1hi[(size_t)Tt * Dm],  g_h1lo[(size_t)Tt * Dm];
__device__ __half g_qkvhi[(size_t)Tt * 3 * Dm], g_qkvlo[(size_t)Tt * 3 * Dm];
__device__ __half g_atthi[(size_t)Tt * Dm], g_attlo[(size_t)Tt * Dm];
__device__ __half g_h2hi[(size_t)Tt * Dm],  g_h2lo[(size_t)Tt * Dm];
__device__ __half g_hidhi[(size_t)NPAIR * DFFf], g_hidlo[(size_t)NPAIR * DFFf];
__device__ __half g_wqkvThi[(size_t)3 * Dm * Dm], g_wqkvTlo[(size_t)3 * Dm * Dm];
__device__ __half g_woThi[(size_t)Dm * Dm],       g_woTlo[(size_t)Dm * Dm];
__device__ __half g_W1Thi[(size_t)Ee * DFFf * Dm];   // lo not needed (2-term MoE)
__device__ __half g_W2Thi[(size_t)Ee * Dm * DFFf];

// ---------------------------------------------------------------------------
// helpers
// ---------------------------------------------------------------------------
__device__ __forceinline__ void split2(float f0, float f1,
                                       uint32_t& hi, uint32_t& lo) {
    __half2 h2v = __floats2half2_rn(f0, f1);
    float2 hf = __half22float2(h2v);
    __half2 l2v = __floats2half2_rn(f0 - hf.x, f1 - hf.y);
    hi = *(uint32_t*)&h2v;
    lo = *(uint32_t*)&l2v;
}
__device__ __forceinline__ void cp16(uint32_t dst, const void* src, int src_bytes) {
    asm volatile("cp.async.cg.shared.global [%0], [%1], 16, %2;"
                 :: "r"(dst), "l"(src), "r"(src_bytes));
}
__device__ __forceinline__ void cp_commit() {
    asm volatile("cp.async.commit_group;");
}
template<int N>
__device__ __forceinline__ void cp_wait() {
    asm volatile("cp.async.wait_group %0;" :: "n"(N));
}
__device__ __forceinline__ void mma_f16(float* c, const uint32_t* a, const uint32_t* b) {
    asm volatile(
        "mma.sync.aligned.m16n8k16.row.col.f32.f16.f16.f32 "
        "{%0,%1,%2,%3}, {%4,%5,%6,%7}, {%8,%9}, {%0,%1,%2,%3};"
        : "+f"(c[0]), "+f"(c[1]), "+f"(c[2]), "+f"(c[3])
        : "r"(a[0]), "r"(a[1]), "r"(a[2]), "r"(a[3]), "r"(b[0]), "r"(b[1]));
}
__device__ __forceinline__ void ldmx4(uint32_t* r, uint32_t addr) {
    asm volatile("ldmatrix.sync.aligned.m8n8.x4.shared.b16 {%0,%1,%2,%3}, [%4];"
                 : "=r"(r[0]), "=r"(r[1]), "=r"(r[2]), "=r"(r[3]) : "r"(addr));
}
__device__ __forceinline__ void ldmx4t(uint32_t* r, uint32_t addr) {
    asm volatile("ldmatrix.sync.aligned.m8n8.x4.trans.shared.b16 {%0,%1,%2,%3}, [%4];"
                 : "=r"(r[0]), "=r"(r[1]), "=r"(r[2]), "=r"(r[3]) : "r"(addr));
}

// ---------------------------------------------------------------------------
// Weight transpose + split: fp32 [K,N] -> fp16 hi (+optional lo) [N,K].
// Tile 64(k) x 32(n), 16B stores.
// ---------------------------------------------------------------------------
__global__ void convT_kernel(const float* __restrict__ src,
                             __half* __restrict__ hi,
                             __half* __restrict__ lo,   // may be null
                             int K, int N)
{
    __shared__ float tile[64][33];
    int z = blockIdx.z;
    src += (size_t)z * K * N;
    hi  += (size_t)z * K * N;
    if (lo) lo += (size_t)z * K * N;
    int k0 = blockIdx.y * 64, n0 = blockIdx.x * 32;
    int t = threadIdx.x;
    #pragma unroll
    for (int i = 0; i < 8; i++) {
        int idx = t + i * 256;
        int r = idx >> 5, c = idx & 31;
        tile[r][c] = src[(size_t)(k0 + r) * N + n0 + c];
    }
    __syncthreads();
    int n  = t >> 3;
    int kc = (t & 7) * 8;
    uint32_t hp[4], lp[4];
    #pragma unroll
    for (int j = 0; j < 4; j++) {
        float f0 = tile[kc + 2 * j][n];
        float f1 = tile[kc + 2 * j + 1][n];
        split2(f0, f1, hp[j], lp[j]);
    }
    size_t o = (size_t)(n0 + n) * K + k0 + kc;
    *(uint4*)&hi[o] = *(uint4*)hp;
    if (lo) *(uint4*)&lo[o] = *(uint4*)lp;
}

// ---------------------------------------------------------------------------
// LayerNorm: writes fp16 hi/lo, optional fp32
// ---------------------------------------------------------------------------
__global__ void ln_kernel(const float* __restrict__ x,
                          const float* __restrict__ g,
                          const float* __restrict__ b,
                          float* __restrict__ outf,           // may be null
                          __half* __restrict__ ohi,
                          __half* __restrict__ olo)
{
    int t = blockIdx.x;
    const float* xr = x + (size_t)t * Dm;
    float s = 0.f, s2 = 0.f;
    for (int d = threadIdx.x; d < Dm; d += 256) {
        float v = xr[d];
        s += v; s2 += v * v;
    }
    #pragma unroll
    for (int off = 16; off; off >>= 1) {
        s  += __shfl_xor_sync(0xffffffffu, s, off);
        s2 += __shfl_xor_sync(0xffffffffu, s2, off);
    }
    __shared__ float sh[18];
    int w = threadIdx.x >> 5;
    if ((threadIdx.x & 31) == 0) { sh[w] = s; sh[w + 8] = s2; }
    __syncthreads();
    if (threadIdx.x == 0) {
        float ts = 0.f, ts2 = 0.f;
        #pragma unroll
        for (int i = 0; i < 8; i++) { ts += sh[i]; ts2 += sh[i + 8]; }
        sh[16] = ts; sh[17] = ts2;
    }
    __syncthreads();
    float mean = sh[16] * (1.0f / Dm);
    float var  = sh[17] * (1.0f / Dm) - mean * mean;
    float rstd = rsqrtf(var + 1e-5f);
    for (int d = threadIdx.x; d < Dm; d += 256) {
        float v = (xr[d] - mean) * rstd * g[d] + b[d];
        if (outf) outf[(size_t)t * Dm + d] = v;
        __half h = __float2half_rn(v);
        float r = v - __half2float(h);
        ohi[(size_t)t * Dm + d] = h;
        olo[(size_t)t * Dm + d] = __float2half_rn(r);
    }
}

// ---------------------------------------------------------------------------
// fp16 split GEMM. NT=3: Ahi*Bhi + Ahi*Blo + Alo*Bhi (fp32-accurate).
// NT=2: Ahi*Bhi + Alo*Bhi (drops weight-lo term; err ~2^-12).
// 128x128x32 tile, 256 threads, double-buffered cp.async, ldmatrix frags.
// ---------------------------------------------------------------------------
#define ASTR 40
#define TILE_BF (128 * ASTR)
#define BUF_UNITS (4 * TILE_BF)
#define GEMM_SMEM (2 * BUF_UNITS * 2)   // 81,920 bytes

template<bool MOE, bool RELU, bool RESID, bool WHL, int NT>
__global__ __launch_bounds__(256, 2)
void gemm_split(const __half* __restrict__ Ahi,
                const __half* __restrict__ Alo,
                const __half* __restrict__ BThi,   // [N,K]
                const __half* __restrict__ BTlo,   // unused if NT==2
                float* __restrict__ C,
                __half* __restrict__ Chi,
                __half* __restrict__ Clo,
                const float* __restrict__ bias,
                const float* __restrict__ resid,
                const int* __restrict__ a_idx,
                const int* __restrict__ c_idx,
                const int* __restrict__ cnt,
                int M, int K, int N)
{
    if (MOE) {
        int z = blockIdx.z;
        M = cnt[z];
        BThi += (size_t)z * K * N;
        if (NT == 3) BTlo += (size_t)z * K * N;
        bias += (size_t)z * N;
        a_idx += z * LISTCAP;
        c_idx += z * LISTCAP;
    }
    const int m0 = blockIdx.y * 128;
    if (m0 >= M) return;
    const int n0 = blockIdx.x * 128;

    extern __shared__ __half bsm[];

    const int tid = threadIdx.x;
    const int wid = tid >> 5;
    const int lane = tid & 31;
    const int g = lane >> 2;
    const int q = lane & 3;
    const int wm = wid & 1;
    const int wn = wid >> 1;

    const int kc = (tid & 3) * 8;
    int rl[2];
    rl[0] = tid >> 2;
    rl[1] = (tid >> 2) + 64;

    const __half* a_srchi[2];
    const __half* a_srclo[2];
    int a_bytes[2];
    #pragma unroll
    for (int i = 0; i < 2; i++) {
        int r = m0 + rl[i];
        bool valid = r < M;
        int gr = valid ? (MOE ? a_idx[r] : r) : 0;
        a_srchi[i] = Ahi + (size_t)gr * K + kc;
        a_srclo[i] = Alo + (size_t)gr * K + kc;
        a_bytes[i] = valid ? 16 : 0;
    }
    const __half* b_srchi[2];
    const __half* b_srclo[2];
    #pragma unroll
    for (int i = 0; i < 2; i++) {
        int n = n0 + rl[i];
        b_srchi[i] = BThi + (size_t)n * K + kc;
        b_srclo[i] = (NT == 3) ? (BTlo + (size_t)n * K + kc) : b_srchi[i];
    }

    uint32_t dA[2], dB[2];
    #pragma unroll
    for (int i = 0; i < 2; i++) {
        dA[i] = (uint32_t)__cvta_generic_to_shared(&bsm[rl[i] * ASTR + kc]);
        dB[i] = dA[i] + 2 * TILE_BF * 2;
    }
    const uint32_t LO_OFF = TILE_BF * 2;
    const uint32_t BUFB   = BUF_UNITS * 2;

    const int nk = K / 32;

    // prefetch tile 0 into buffer 0, drain, sync
    #pragma unroll
    for (int i = 0; i < 2; i++) {
        cp16(dA[i],          a_srchi[i], a_bytes[i]);
        cp16(dA[i] + LO_OFF, a_srclo[i], a_bytes[i]);
        cp16(dB[i],          b_srchi[i], 16);
        if (NT == 3) cp16(dB[i] + LO_OFF, b_srclo[i], 16);
    }
    cp_commit();
    cp_wait<0>();
    __syncthreads();

    float acc[4][4][4] = {};

    const uint32_t la_off = (uint32_t)(((wm * 64 + (lane & 15)) * ASTR
                                        + ((lane >> 4) << 3)) * 2);
    const uint32_t lb_off = (uint32_t)(((wn * 32 + (lane & 7) + ((lane >> 4) << 3)) * ASTR
                                        + (((lane >> 3) & 1) << 3)) * 2);
    const uint32_t sm_base = (uint32_t)__cvta_generic_to_shared(bsm);

    for (int kt = 0; kt < nk; kt++) {
        const int buf = kt & 1;
        if (kt + 1 < nk) {
            int k0 = (kt + 1) * 32;
            uint32_t bo = (buf ^ 1) ? BUFB : 0;
            #pragma unroll
            for (int i = 0; i < 2; i++) {
                cp16(dA[i] + bo,          a_srchi[i] + k0, a_bytes[i]);
                cp16(dA[i] + bo + LO_OFF, a_srclo[i] + k0, a_bytes[i]);
                cp16(dB[i] + bo,          b_srchi[i] + k0, 16);
                if (NT == 3) cp16(dB[i] + bo + LO_OFF, b_srclo[i] + k0, 16);
            }
            cp_commit();
        }

        const uint32_t sA   = sm_base + buf * BUFB;
        const uint32_t sAlo = sA + LO_OFF;
        const uint32_t sB   = sA + 2 * LO_OFF;
        const uint32_t sBlo = sA + 3 * LO_OFF;

        #pragma unroll
        for (int ks = 0; ks < 2; ks++) {
            const uint32_t kbb = (uint32_t)(ks * 16 * 2);
            uint32_t bhi[2][4], blo[2][4];
            #pragma unroll
            for (int p = 0; p < 2; p++) {
                uint32_t po = (uint32_t)(p * 16 * ASTR * 2);
                ldmx4(bhi[p], sB + lb_off + kbb + po);
                if (NT == 3) ldmx4(blo[p], sBlo + lb_off + kbb + po);
            }
            #pragma unroll
            for (int mt = 0; mt < 4; mt++) {
                uint32_t mo = (uint32_t)(mt * 16 * ASTR * 2);
                uint32_t ah[4], al[4];
                ldmx4(ah, sA   + la_off + kbb + mo);
                ldmx4(al, sAlo + la_off + kbb + mo);
                #pragma unroll
                for (int nt = 0; nt < 4; nt++) {
                    const uint32_t* bh = &bhi[nt >> 1][(nt & 1) * 2];
                    mma_f16(acc[mt][nt], ah, bh);
                    mma_f16(acc[mt][nt], al, bh);
                    if (NT == 3) {
                        const uint32_t* bl = &blo[nt >> 1][(nt & 1) * 2];
                        mma_f16(acc[mt][nt], ah, bl);
                    }
                }
            }
        }

        if (kt + 1 < nk) {
            cp_wait<0>();
            __syncthreads();
        }
    }

    #pragma unroll
    for (int mt = 0; mt < 4; mt++) {
        #pragma unroll
        for (int half = 0; half < 2; half++) {
            int r = m0 + wm * 64 + mt * 16 + g + half * 8;
            if (MOE && r >= M) continue;
            int cr = MOE ? c_idx[r] : r;
            #pragma unroll
            for (int nt = 0; nt < 4; nt++) {
                int c = n0 + wn * 32 + nt * 8 + 2 * q;
                float v0 = acc[mt][nt][half * 2 + 0] + bias[c];
                float v1 = acc[mt][nt][half * 2 + 1] + bias[c + 1];
                if (RELU) { v0 = fmaxf(v0, 0.f); v1 = fmaxf(v1, 0.f); }
                if (RESID) {
                    float2 rr = *(const float2*)(resid + (size_t)r * N + c);
                    v0 += rr.x; v1 += rr.y;
                }
                if (WHL) {
                    uint32_t h, l;
                    split2(v0, v1, h, l);
                    *(uint32_t*)&Chi[(size_t)cr * N + c] = h;
                    *(uint32_t*)&Clo[(size_t)cr * N + c] = l;
                } else {
                    *(float2*)(C + (size_t)cr * N + c) = make_float2(v0, v1);
                }
            }
        }
    }
}

// ---------------------------------------------------------------------------
// Tensor-core flash attention (fp16 hi/lo 3-term, fp32 softmax).
// ---------------------------------------------------------------------------
#define AQS 72
#define AQ_ARR (64 * AQS * 2)
#define OFF_QHI 0
#define OFF_QLO AQ_ARR
#define OFF_KV  (2 * AQ_ARR)
#define KVBUF   (4 * AQ_ARR)
#define OFF_RED (OFF_KV + 2 * KVBUF)
#define ATT_SMEM (OFF_RED + 1024)

__global__ __launch_bounds__(256, 2)
void attn_tc(const __half* __restrict__ qkvhi,
             const __half* __restrict__ qkvlo,
             __half* __restrict__ ohi,
             __half* __restrict__ olo)
{
    extern __shared__ char asm_[];
    const uint32_t sb = (uint32_t)__cvta_generic_to_shared(asm_);
    const int qb = blockIdx.x, h = blockIdx.y, b = blockIdx.z;
    const int tid = threadIdx.x;
    const int wid = tid >> 5;
    const int lane = tid & 31;
    const int g = lane >> 2;
    const int q = lane & 3;
    const int wm = wid & 3;
    const int wn = wid >> 2;

    float* redmax = (float*)(asm_ + OFF_RED);
    float* redsum = (float*)(asm_ + OFF_RED + 512);

    {
        int row = tid >> 2;
        const __half* qh = qkvhi + (size_t)(b * Ss + qb * 64 + row) * (3 * Dm) + h * 64;
        const __half* ql = qkvlo + (size_t)(b * Ss + qb * 64 + row) * (3 * Dm) + h * 64;
        #pragma unroll
        for (int i = 0; i < 2; i++) {
            int c = (tid & 3) + 4 * i;
            cp16(sb + OFF_QHI + (row * AQS + c * 8) * 2, qh + c * 8, 16);
            cp16(sb + OFF_QLO + (row * AQS + c * 8) * 2, ql + c * 8, 16);
        }
    }
    const int kvrow = tid >> 2;
    const __half* kbase_hi = qkvhi + (size_t)(b * Ss) * (3 * Dm) + Dm + h * 64;
    const __half* kbase_lo = qkvlo + (size_t)(b * Ss) * (3 * Dm) + Dm + h * 64;
    auto load_kv = [&](int bufi, int kt) {
        uint32_t so = sb + OFF_KV + bufi * KVBUF;
        const __half* srch = kbase_hi + (size_t)(kt * 64 + kvrow) * (3 * Dm);
        const __half* srcl = kbase_lo + (size_t)(kt * 64 + kvrow) * (3 * Dm);
        #pragma unroll
        for (int i = 0; i < 2; i++) {
            int c = (tid & 3) + 4 * i;
            uint32_t sm = (uint32_t)((kvrow * AQS + c * 8) * 2);
            cp16(so + sm,              srch + c * 8, 16);
            cp16(so + AQ_ARR + sm,     srcl + c * 8, 16);
            cp16(so + 2 * AQ_ARR + sm, srch + Dm + c * 8, 16);
            cp16(so + 3 * AQ_ARR + sm, srcl + Dm + c * 8, 16);
        }
    };
    load_kv(0, 0);
    cp_commit();
    cp_wait<0>();
    __syncthreads();

    const uint32_t qa_off = (uint32_t)(((wm * 16 + (lane & 15)) * AQS
                                        + ((lane >> 4) << 3)) * 2);
    uint32_t qh[4][4], ql[4][4];
    #pragma unroll
    for (int ks = 0; ks < 4; ks++) {
        ldmx4(qh[ks], sb + OFF_QHI + qa_off + ks * 32);
        ldmx4(ql[ks], sb + OFF_QLO + qa_off + ks * 32);
    }

    const uint32_t kb_off = (uint32_t)(((wn * 32 + (lane & 7) + ((lane >> 4) << 3)) * AQS
                                        + (((lane >> 3) & 1) << 3)) * 2);
    const uint32_t vb_row = (uint32_t)(wn * 32 + ((lane >> 3) & 1) * 8 + (lane & 7));
    const uint32_t vb_col = (uint32_t)((lane >> 4) << 3);

    float m0 = -1e30f, m1 = -1e30f, l0 = 0.f, l1 = 0.f;
    float oacc[8][4] = {};

    const int NKV = Ss / 64;
    for (int kt = 0; kt < NKV; kt++) {
        const int bufi = kt & 1;
        if (kt + 1 < NKV) {
            load_kv(bufi ^ 1, kt + 1);
            cp_commit();
        }
        const uint32_t sK   = sb + OFF_KV + bufi * KVBUF;
        const uint32_t sKlo = sK + AQ_ARR;
        const uint32_t sV   = sK + 2 * AQ_ARR;
        const uint32_t sVlo = sK + 3 * AQ_ARR;

        float s[4][4] = {};
        #pragma unroll
        for (int ks = 0; ks < 4; ks++) {
            uint32_t bh[2][4], bl[2][4];
            #pragma unroll
            for (int p = 0; p < 2; p++) {
                uint32_t po = (uint32_t)(p * 16 * AQS * 2) + (uint32_t)(ks * 32);
                ldmx4(bh[p], sK   + kb_off + po);
                ldmx4(bl[p], sKlo + kb_off + po);
            }
            #pragma unroll
            for (int nt = 0; nt < 4; nt++) {
                const uint32_t* bhp = &bh[nt >> 1][(nt & 1) * 2];
                const uint32_t* blp = &bl[nt >> 1][(nt & 1) * 2];
                mma_f16(s[nt], qh[ks], bhp);
                mma_f16(s[nt], qh[ks], blp);
                mma_f16(s[nt], ql[ks], bhp);
            }
        }
        #pragma unroll
        for (int nt = 0; nt < 4; nt++)
            #pragma unroll
            for (int j = 0; j < 4; j++)
                s[nt][j] *= 0.125f;

        float mx0 = -1e30f, mx1 = -1e30f;
        #pragma unroll
        for (int nt = 0; nt < 4; nt++) {
            mx0 = fmaxf(mx0, fmaxf(s[nt][0], s[nt][1]));
            mx1 = fmaxf(mx1, fmaxf(s[nt][2], s[nt][3]));
        }
        #pragma unroll
        for (int off = 1; off < 4; off <<= 1) {
            mx0 = fmaxf(mx0, __shfl_xor_sync(0xffffffffu, mx0, off));
            mx1 = fmaxf(mx1, __shfl_xor_sync(0xffffffffu, mx1, off));
        }
        if (q == 0) {
            redmax[wn * 64 + wm * 16 + g]     = mx0;
            redmax[wn * 64 + wm * 16 + 8 + g] = mx1;
        }
        __syncthreads();
        float om0 = redmax[(wn ^ 1) * 64 + wm * 16 + g];
        float om1 = redmax[(wn ^ 1) * 64 + wm * 16 + 8 + g];
        float nm0 = fmaxf(m0, fmaxf(mx0, om0));
        float nm1 = fmaxf(m1, fmaxf(mx1, om1));

        float ps0 = 0.f, ps1 = 0.f;
        #pragma unroll
        for (int nt = 0; nt < 4; nt++) {
            s[nt][0] = __expf(s[nt][0] - nm0); ps0 += s[nt][0];
            s[nt][1] = __expf(s[nt][1] - nm0); ps0 += s[nt][1];
            s[nt][2] = __expf(s[nt][2] - nm1); ps1 += s[nt][2];
            s[nt][3] = __expf(s[nt][3] - nm1); ps1 += s[nt][3];
        }
        #pragma unroll
        for (int off = 1; off < 4; off <<= 1) {
            ps0 += __shfl_xor_sync(0xffffffffu, ps0, off);
            ps1 += __shfl_xor_sync(0xffffffffu, ps1, off);
        }
        if (q == 0) {
            redsum[wn * 64 + wm * 16 + g]     = ps0;
            redsum[wn * 64 + wm * 16 + 8 + g] = ps1;
        }
        __syncthreads();
        float os0 = redsum[(wn ^ 1) * 64 + wm * 16 + g];
        float os1 = redsum[(wn ^ 1) * 64 + wm * 16 + 8 + g];
        float corr0 = __expf(m0 - nm0);
        float corr1 = __expf(m1 - nm1);
        m0 = nm0; m1 = nm1;
        l0 = l0 * corr0 + ps0 + os0;
        l1 = l1 * corr1 + ps1 + os1;
        #pragma unroll
        for (int nt = 0; nt < 8; nt++) {
            oacc[nt][0] *= corr0; oacc[nt][1] *= corr0;
            oacc[nt][2] *= corr1; oacc[nt][3] *= corr1;
        }

        #pragma unroll
        for (int sstep = 0; sstep < 2; sstep++) {
            uint32_t ph[4], pl[4];
            split2(s[2 * sstep][0],     s[2 * sstep][1],     ph[0], pl[0]);
            split2(s[2 * sstep][2],     s[2 * sstep][3],     ph[1], pl[1]);
            split2(s[2 * sstep + 1][0], s[2 * sstep + 1][1], ph[2], pl[2]);
            split2(s[2 * sstep + 1][2], s[2 * sstep + 1][3], ph[3], pl[3]);
            #pragma unroll
            for (int dp = 0; dp < 4; dp++) {
                uint32_t vh[4], vl[4];
                uint32_t va = (uint32_t)(((vb_row + sstep * 16) * AQS
                                          + dp * 16 + vb_col) * 2);
                ldmx4t(vh, sV   + va);
                ldmx4t(vl, sVlo + va);
                #pragma unroll
                for (int half = 0; half < 2; half++) {
                    int nt = dp * 2 + half;
                    const uint32_t* bhp = &vh[half * 2];
                    const uint32_t* blp = &vl[half * 2];
                    mma_f16(oacc[nt], ph, bhp);
                    mma_f16(oacc[nt], ph, blp);
                    mma_f16(oacc[nt], pl, bhp);
                }
            }
        }

        if (kt + 1 < NKV) {
            cp_wait<0>();
            __syncthreads();
        }
    }

    float* ob = (float*)asm_;
    __syncthreads();
    if (wn == 1) {
        #pragma unroll
        for (int nt = 0; nt < 8; nt++)
            #pragma unroll
            for (int j = 0; j < 4; j++) {
                int row = wm * 16 + g + ((j >> 1) << 3);
                int col = nt * 8 + 2 * q + (j & 1);
                ob[row * 64 + col] = oacc[nt][j];
            }
    }
    __syncthreads();
    if (wn == 0) {
        float inv0 = 1.0f / l0, inv1 = 1.0f / l1;
        #pragma unroll
        for (int nt = 0; nt < 8; nt++) {
            int col = nt * 8 + 2 * q;
            #pragma unroll
            for (int hrow = 0; hrow < 2; hrow++) {
                int row = wm * 16 + g + hrow * 8;
                float inv = hrow ? inv1 : inv0;
                float v0 = (oacc[nt][hrow * 2 + 0] + ob[row * 64 + col])     * inv;
                float v1 = (oacc[nt][hrow * 2 + 1] + ob[row * 64 + col + 1]) * inv;
                uint32_t hh, ll;
                split2(v0, v1, hh, ll);
                size_t t = (size_t)(b * Ss + qb * 64 + row);
                size_t o = t * Dm + h * 64 + col;
                *(uint32_t*)&ohi[o] = hh;
                *(uint32_t*)&olo[o] = ll;
            }
        }
    }
}

// ---------------------------------------------------------------------------
// Gating + routing
// ---------------------------------------------------------------------------
__global__ void gate_route_kernel(const float* __restrict__ h2,
                                  const float* __restrict__ gw,
                                  const float* __restrict__ gb,
                                  int* __restrict__ cnt,
                                  int* __restrict__ tok,
                                  int* __restrict__ dst,
                                  float* __restrict__ gw2)
{
    int t = blockIdx.x * 8 + (threadIdx.x >> 5);
    int lane = threadIdx.x & 31;
    const float* xr = h2 + (size_t)t * Dm;
    float acc[Ee] = {};
    for (int d = lane; d < Dm; d += 32) {
        float xv = xr[d];
        #pragma unroll
        for (int e = 0; e < Ee; e++)
            acc[e] = fmaf(xv, gw[d * Ee + e], acc[e]);
    }
    #pragma unroll
    for (int e = 0; e < Ee; e++)
        #pragma unroll
        for (int off = 16; off; off >>= 1)
            acc[e] += __shfl_xor_sync(0xffffffffu, acc[e], off);

    if (lane == 0) {
        float lg[Ee];
        #pragma unroll
        for (int e = 0; e < Ee; e++) lg[e] = acc[e] + gb[e];
        int i0 = 0;
        #pragma unroll
        for (int e = 1; e < Ee; e++) if (lg[e] > lg[i0]) i0 = e;
        int i1 = -1;
        #pragma unroll
        for (int e = 0; e < Ee; e++) {
            if (e == i0) continue;
            if (i1 < 0 || lg[e] > lg[i1]) i1 = e;
        }
        float e1 = expf(lg[i1] - lg[i0]);
        float denom = 1.0f / (1.0f + e1);
        float g0 = denom, g1 = e1 * denom;
        int p0 = atomicAdd(&cnt[i0], 1);
        tok[i0 * LISTCAP + p0] = t;
        dst[i0 * LISTCAP + p0] = t * 2;
        int p1 = atomicAdd(&cnt[i1], 1);
        tok[i1 * LISTCAP + p1] = t;
        dst[i1 * LISTCAP + p1] = t * 2 + 1;
        gw2[t * 2]     = g0;
        gw2[t * 2 + 1] = g1;
    }
}

// ---------------------------------------------------------------------------
// Final combine
// ---------------------------------------------------------------------------
__global__ void combine_kernel(float* __restrict__ out,
                               const float* __restrict__ moeo,
                               const float* __restrict__ gw2)
{
    int t = blockIdx.x;
    float g0 = gw2[t * 2], g1 = gw2[t * 2 + 1];
    const float* r0 = moeo + (size_t)(t * 2) * Dm;
    const float* r1 = r0 + Dm;
    float* orow = out + (size_t)t * Dm;
    for (int d = threadIdx.x; d < Dm; d += 256)
        orow[d] += g0 * r0[d] + g1 * r1[d];
}

// ---------------------------------------------------------------------------
// Launch
// ---------------------------------------------------------------------------
extern "C" void kernel_launch(void* const* d_in, const int* in_sizes, int n_in,
                              void* d_out, int out_size)
{
    const float* x      = (const float*)d_in[0];
    const float* ln1_g  = (const float*)d_in[1];
    const float* ln1_b  = (const float*)d_in[2];
    const float* w_qkv  = (const float*)d_in[3];
    const float* b_qkv  = (const float*)d_in[4];
    const float* w_o    = (const float*)d_in[5];
    const float* b_o    = (const float*)d_in[6];
    const float* ln2_g  = (const float*)d_in[7];
    const float* ln2_b  = (const float*)d_in[8];
    const float* gate_w = (const float*)d_in[9];
    const float* gate_b = (const float*)d_in[10];
    const float* W1     = (const float*)d_in[11];
    const float* b1     = (const float*)d_in[12];
    const float* W2     = (const float*)d_in[13];
    const float* b2     = (const float*)d_in[14];
    float* out = (float*)d_out;

    float *h2, *moeo, *gwp;
    int *cnt, *tok, *dst;
    __half *h1hi, *h1lo, *qkvhi, *qkvlo, *atthi, *attlo, *h2hi, *h2lo, *hidhi, *hidlo;
    __half *wqkvThi, *wqkvTlo, *woThi, *woTlo, *W1Thi, *W2Thi;
    cudaGetSymbolAddress((void**)&h2,    g_h2);
    cudaGetSymbolAddress((void**)&moeo,  g_moeo);
    cudaGetSymbolAddress((void**)&cnt,   g_cnt);
    cudaGetSymbolAddress((void**)&tok,   g_tok);
    cudaGetSymbolAddress((void**)&dst,   g_dst);
    cudaGetSymbolAddress((void**)&gwp,   g_gw);
    cudaGetSymbolAddress((void**)&h1hi,  g_h1hi);
    cudaGetSymbolAddress((void**)&h1lo,  g_h1lo);
    cudaGetSymbolAddress((void**)&qkvhi, g_qkvhi);
    cudaGetSymbolAddress((void**)&qkvlo, g_qkvlo);
    cudaGetSymbolAddress((void**)&atthi, g_atthi);
    cudaGetSymbolAddress((void**)&attlo, g_attlo);
    cudaGetSymbolAddress((void**)&h2hi,  g_h2hi);
    cudaGetSymbolAddress((void**)&h2lo,  g_h2lo);
    cudaGetSymbolAddress((void**)&hidhi, g_hidhi);
    cudaGetSymbolAddress((void**)&hidlo, g_hidlo);
    cudaGetSymbolAddress((void**)&wqkvThi, g_wqkvThi);
    cudaGetSymbolAddress((void**)&wqkvTlo, g_wqkvTlo);
    cudaGetSymbolAddress((void**)&woThi, g_woThi);
    cudaGetSymbolAddress((void**)&woTlo, g_woTlo);
    cudaGetSymbolAddress((void**)&W1Thi, g_W1Thi);
    cudaGetSymbolAddress((void**)&W2Thi, g_W2Thi);

    static bool attr_done = false;
    if (!attr_done) {
        cudaFuncSetAttribute(attn_tc,
                             cudaFuncAttributeMaxDynamicSharedMemorySize, ATT_SMEM);
        cudaFuncSetAttribute(gemm_split<false, false, false, true, 3>,
                             cudaFuncAttributeMaxDynamicSharedMemorySize, GEMM_SMEM);
        cudaFuncSetAttribute(gemm_split<false, false, true, false, 3>,
                             cudaFuncAttributeMaxDynamicSharedMemorySize, GEMM_SMEM);
        cudaFuncSetAttribute(gemm_split<true, true, false, true, 2>,
                             cudaFuncAttributeMaxDynamicSharedMemorySize, GEMM_SMEM);
        cudaFuncSetAttribute(gemm_split<true, false, false, false, 2>,
                             cudaFuncAttributeMaxDynamicSharedMemorySize, GEMM_SMEM);
        attr_done = true;
    }

    cudaMemsetAsync(cnt, 0, Ee * sizeof(int));

    // 0) weight transpose + split (W1/W2: hi only — 2-term MoE)
    convT_kernel<<<dim3(3 * Dm / 32, Dm / 64, 1), 256>>>(w_qkv, wqkvThi, wqkvTlo, Dm, 3 * Dm);
    convT_kernel<<<dim3(Dm / 32, Dm / 64, 1), 256>>>(w_o, woThi, woTlo, Dm, Dm);
    convT_kernel<<<dim3(DFFf / 32, Dm / 64, Ee), 256>>>(W1, W1Thi, nullptr, Dm, DFFf);
    convT_kernel<<<dim3(Dm / 32, DFFf / 64, Ee), 256>>>(W2, W2Thi, nullptr, DFFf, Dm);

    // 1) LN1 -> fp16 hi/lo
    ln_kernel<<<Tt, 256>>>(x, ln1_g, ln1_b, nullptr, h1hi, h1lo);

    // 2) QKV (3-term) -> fp16 hi/lo
    gemm_split<false, false, false, true, 3><<<dim3(3 * Dm / 128, Tt / 128), 256, GEMM_SMEM>>>(
        h1hi, h1lo, wqkvThi, wqkvTlo, nullptr, qkvhi, qkvlo,
        b_qkv, nullptr, nullptr, nullptr, nullptr, Tt, Dm, 3 * Dm);

    // 3) tensor-core attention (3-term) -> fp16 hi/lo
    attn_tc<<<dim3(Ss / 64, Hh, Bb), 256, ATT_SMEM>>>(qkvhi, qkvlo, atthi, attlo);

    // 4) x1 = x + attno @ w_o + b_o (3-term, fp32 -> d_out)
    gemm_split<false, false, true, false, 3><<<dim3(Dm / 128, Tt / 128), 256, GEMM_SMEM>>>(
        atthi, attlo, woThi, woTlo, out, nullptr, nullptr,
        b_o, x, nullptr, nullptr, nullptr, Tt, Dm, Dm);

    // 5) LN2 -> fp32 (gate) + fp16 hi/lo
    ln_kernel<<<Tt, 256>>>(out, ln2_g, ln2_b, h2, h2hi, h2lo);

    // 6) gating + routing
    gate_route_kernel<<<Tt / 8, 256>>>(h2, gate_w, gate_b, cnt, tok, dst, gwp);

    // 7) MoE FFN1 (2-term) -> fp16 hi/lo hidden
    gemm_split<true, true, false, true, 2><<<dim3(DFFf / 128, LISTCAP / 128, Ee), 256, GEMM_SMEM>>>(
        h2hi, h2lo, W1Thi, nullptr, nullptr, hidhi, hidlo,
        b1, nullptr, tok, dst, cnt, 0, Dm, DFFf);

    // 8) MoE FFN2 (2-term, fp32)
    gemm_split<true, false, false, false, 2><<<dim3(Dm / 128, LISTCAP / 128, Ee), 256, GEMM_SMEM>>>(
        hidhi, hidlo, W2Thi, nullptr, moeo, nullptr, nullptr,
        b2, nullptr, dst, dst, cnt, 0, DFFf, Dm);

    // 9) combine
    combine_kernel<<<Tt, 256>>>(out, moeo, gwp);
}

// round 15
// speedup vs baseline: 4.0413x; 1.2795x over previous
#include <cuda_runtime.h>
#include <cuda_fp16.h>
#include <math.h>
#include <stdint.h>

// Problem constants
#define Dm   1024
#define Hh   16
#define DKk  64
#define Ee   8
#define DFFf 4096
#define Ss   2048
#define Bb   2
#define Tt   (Bb * Ss)
#define NPAIR (Tt * 2)
#define LISTCAP 8192

// ---------------------------------------------------------------------------
// Static device scratch
// ---------------------------------------------------------------------------
__device__ float g_h2[(size_t)Tt * Dm];
__device__ float g_moeo[(size_t)NPAIR * Dm];
__device__ int   g_cnt[Ee];
__device__ int   g_tok[Ee * LISTCAP];
__device__ int   g_dst[Ee * LISTCAP];
__device__ float g_gw[NPAIR];

__device__ __half g_h1hi[(size_t)Tt * Dm],  g_h1lo[(size_t)Tt * Dm];
__device__ __half g_qkvhi[(size_t)Tt * 3 * Dm], g_qkvlo[(size_t)Tt * 3 * Dm];
__device__ __half g_atthi[(size_t)Tt * Dm], g_attlo[(size_t)Tt * Dm];
__device__ __half g_h2hi[(size_t)Tt * Dm];
__device__ __half g_hidhi[(size_t)NPAIR * DFFf];
__device__ __half g_wqkvThi[(size_t)3 * Dm * Dm], g_wqkvTlo[(size_t)3 * Dm * Dm];
__device__ __half g_woThi[(size_t)Dm * Dm],       g_woTlo[(size_t)Dm * Dm];
__device__ __half g_W1Thi[(size_t)Ee * DFFf * Dm];
__device__ __half g_W2Thi[(size_t)Ee * Dm * DFFf];

// ---------------------------------------------------------------------------
// helpers
// ---------------------------------------------------------------------------
__device__ __forceinline__ void split2(float f0, float f1,
                                       uint32_t& hi, uint32_t& lo) {
    __half2 h2v = __floats2half2_rn(f0, f1);
    float2 hf = __half22float2(h2v);
    __half2 l2v = __floats2half2_rn(f0 - hf.x, f1 - hf.y);
    hi = *(uint32_t*)&h2v;
    lo = *(uint32_t*)&l2v;
}
__device__ __forceinline__ void cp16(uint32_t dst, const void* src, int src_bytes) {
    asm volatile("cp.async.cg.shared.global [%0], [%1], 16, %2;"
                 :: "r"(dst), "l"(src), "r"(src_bytes));
}
__device__ __forceinline__ void cp_commit() {
    asm volatile("cp.async.commit_group;");
}
template<int N>
__device__ __forceinline__ void cp_wait() {
    asm volatile("cp.async.wait_group %0;" :: "n"(N));
}
__device__ __forceinline__ void mma_f16(float* c, const uint32_t* a, const uint32_t* b) {
    asm volatile(
        "mma.sync.aligned.m16n8k16.row.col.f32.f16.f16.f32 "
        "{%0,%1,%2,%3}, {%4,%5,%6,%7}, {%8,%9}, {%0,%1,%2,%3};"
        : "+f"(c[0]), "+f"(c[1]), "+f"(c[2]), "+f"(c[3])
        : "r"(a[0]), "r"(a[1]), "r"(a[2]), "r"(a[3]), "r"(b[0]), "r"(b[1]));
}
__device__ __forceinline__ void ldmx4(uint32_t* r, uint32_t addr) {
    asm volatile("ldmatrix.sync.aligned.m8n8.x4.shared.b16 {%0,%1,%2,%3}, [%4];"
                 : "=r"(r[0]), "=r"(r[1]), "=r"(r[2]), "=r"(r[3]) : "r"(addr));
}
__device__ __forceinline__ void ldmx4t(uint32_t* r, uint32_t addr) {
    asm volatile("ldmatrix.sync.aligned.m8n8.x4.trans.shared.b16 {%0,%1,%2,%3}, [%4];"
                 : "=r"(r[0]), "=r"(r[1]), "=r"(r[2]), "=r"(r[3]) : "r"(addr));
}

// ---------------------------------------------------------------------------
// Weight transpose + split: fp32 [K,N] -> fp16 hi (+optional lo) [N,K].
// ---------------------------------------------------------------------------
__global__ void convT_kernel(const float* __restrict__ src,
                             __half* __restrict__ hi,
                             __half* __restrict__ lo,   // may be null
                             int K, int N)
{
    __shared__ float tile[64][33];
    int z = blockIdx.z;
    src += (size_t)z * K * N;
    hi  += (size_t)z * K * N;
    if (lo) lo += (size_t)z * K * N;
    int k0 = blockIdx.y * 64, n0 = blockIdx.x * 32;
    int t = threadIdx.x;
    #pragma unroll
    for (int i = 0; i < 8; i++) {
        int idx = t + i * 256;
        int r = idx >> 5, c = idx & 31;
        tile[r][c] = src[(size_t)(k0 + r) * N + n0 + c];
    }
    __syncthreads();
    int n  = t >> 3;
    int kc = (t & 7) * 8;
    uint32_t hp[4], lp[4];
    #pragma unroll
    for (int j = 0; j < 4; j++) {
        float f0 = tile[kc + 2 * j][n];
        float f1 = tile[kc + 2 * j + 1][n];
        split2(f0, f1, hp[j], lp[j]);
    }
    size_t o = (size_t)(n0 + n) * K + k0 + kc;
    *(uint4*)&hi[o] = *(uint4*)hp;
    if (lo) *(uint4*)&lo[o] = *(uint4*)lp;
}

// ---------------------------------------------------------------------------
// LayerNorm: writes fp16 hi (+optional lo), optional fp32
// ---------------------------------------------------------------------------
__global__ void ln_kernel(const float* __restrict__ x,
                          const float* __restrict__ g,
                          const float* __restrict__ b,
                          float* __restrict__ outf,
                          __half* __restrict__ ohi,
                          __half* __restrict__ olo)   // may be null
{
    int t = blockIdx.x;
    const float* xr = x + (size_t)t * Dm;
    float s = 0.f, s2 = 0.f;
    for (int d = threadIdx.x; d < Dm; d += 256) {
        float v = xr[d];
        s += v; s2 += v * v;
    }
    #pragma unroll
    for (int off = 16; off; off >>= 1) {
        s  += __shfl_xor_sync(0xffffffffu, s, off);
        s2 += __shfl_xor_sync(0xffffffffu, s2, off);
    }
    __shared__ float sh[18];
    int w = threadIdx.x >> 5;
    if ((threadIdx.x & 31) == 0) { sh[w] = s; sh[w + 8] = s2; }
    __syncthreads();
    if (threadIdx.x == 0) {
        float ts = 0.f, ts2 = 0.f;
        #pragma unroll
        for (int i = 0; i < 8; i++) { ts += sh[i]; ts2 += sh[i + 8]; }
        sh[16] = ts; sh[17] = ts2;
    }
    __syncthreads();
    float mean = sh[16] * (1.0f / Dm);
    float var  = sh[17] * (1.0f / Dm) - mean * mean;
    float rstd = rsqrtf(var + 1e-5f);
    for (int d = threadIdx.x; d < Dm; d += 256) {
        float v = (xr[d] - mean) * rstd * g[d] + b[d];
        if (outf) outf[(size_t)t * Dm + d] = v;
        __half h = __float2half_rn(v);
        ohi[(size_t)t * Dm + d] = h;
        if (olo) {
            float r = v - __half2float(h);
            olo[(size_t)t * Dm + d] = __float2half_rn(r);
        }
    }
}

// ---------------------------------------------------------------------------
// fp16 split GEMM.
// NT=3: Ahi*Bhi + Ahi*Blo + Alo*Bhi (fp32-accurate).
// NT=2: Ahi*Bhi + Alo*Bhi.
// NT=1: Ahi*Bhi (plain fp16).
// WMODE: 0 = fp32 out, 1 = fp16 hi+lo out, 2 = fp16 hi-only out.
// ---------------------------------------------------------------------------
#define ASTR 40
#define TILE_BF (128 * ASTR)
#define BUF_UNITS (4 * TILE_BF)
#define GEMM_SMEM (2 * BUF_UNITS * 2)   // 81,920 bytes (NT=3 worst case)

template<bool MOE, bool RELU, bool RESID, int WMODE, int NT>
__global__ __launch_bounds__(256, 2)
void gemm_split(const __half* __restrict__ Ahi,
                const __half* __restrict__ Alo,    // unused if NT==1
                const __half* __restrict__ BThi,   // [N,K]
                const __half* __restrict__ BTlo,   // unused if NT<3
                float* __restrict__ C,
                __half* __restrict__ Chi,
                __half* __restrict__ Clo,
                const float* __restrict__ bias,
                const float* __restrict__ resid,
                const int* __restrict__ a_idx,
                const int* __restrict__ c_idx,
                const int* __restrict__ cnt,
                int M, int K, int N)
{
    if (MOE) {
        int z = blockIdx.z;
        M = cnt[z];
        BThi += (size_t)z * K * N;
        if (NT == 3) BTlo += (size_t)z * K * N;
        bias += (size_t)z * N;
        a_idx += z * LISTCAP;
        c_idx += z * LISTCAP;
    }
    const int m0 = blockIdx.y * 128;
    if (m0 >= M) return;
    const int n0 = blockIdx.x * 128;

    extern __shared__ __half bsm[];

    const int tid = threadIdx.x;
    const int wid = tid >> 5;
    const int lane = tid & 31;
    const int g = lane >> 2;
    const int q = lane & 3;
    const int wm = wid & 1;
    const int wn = wid >> 1;

    const int kc = (tid & 3) * 8;
    int rl[2];
    rl[0] = tid >> 2;
    rl[1] = (tid >> 2) + 64;

    const __half* a_srchi[2];
    const __half* a_srclo[2];
    int a_bytes[2];
    #pragma unroll
    for (int i = 0; i < 2; i++) {
        int r = m0 + rl[i];
        bool valid = r < M;
        int gr = valid ? (MOE ? a_idx[r] : r) : 0;
        a_srchi[i] = Ahi + (size_t)gr * K + kc;
        a_srclo[i] = (NT >= 2) ? (Alo + (size_t)gr * K + kc) : a_srchi[i];
        a_bytes[i] = valid ? 16 : 0;
    }
    const __half* b_srchi[2];
    const __half* b_srclo[2];
    #pragma unroll
    for (int i = 0; i < 2; i++) {
        int n = n0 + rl[i];
        b_srchi[i] = BThi + (size_t)n * K + kc;
        b_srclo[i] = (NT == 3) ? (BTlo + (size_t)n * K + kc) : b_srchi[i];
    }

    uint32_t dA[2], dB[2];
    #pragma unroll
    for (int i = 0; i < 2; i++) {
        dA[i] = (uint32_t)__cvta_generic_to_shared(&bsm[rl[i] * ASTR + kc]);
        dB[i] = dA[i] + 2 * TILE_BF * 2;
    }
    const uint32_t LO_OFF = TILE_BF * 2;
    const uint32_t BUFB   = BUF_UNITS * 2;

    const int nk = K / 32;

    #pragma unroll
    for (int i = 0; i < 2; i++) {
        cp16(dA[i],          a_srchi[i], a_bytes[i]);
        if (NT >= 2) cp16(dA[i] + LO_OFF, a_srclo[i], a_bytes[i]);
        cp16(dB[i],          b_srchi[i], 16);
        if (NT == 3) cp16(dB[i] + LO_OFF, b_srclo[i], 16);
    }
    cp_commit();
    cp_wait<0>();
    __syncthreads();

    float acc[4][4][4] = {};

    const uint32_t la_off = (uint32_t)(((wm * 64 + (lane & 15)) * ASTR
                                        + ((lane >> 4) << 3)) * 2);
    const uint32_t lb_off = (uint32_t)(((wn * 32 + (lane & 7) + ((lane >> 4) << 3)) * ASTR
                                        + (((lane >> 3) & 1) << 3)) * 2);
    const uint32_t sm_base = (uint32_t)__cvta_generic_to_shared(bsm);

    for (int kt = 0; kt < nk; kt++) {
        const int buf = kt & 1;
        if (kt + 1 < nk) {
            int k0 = (kt + 1) * 32;
            uint32_t bo = (buf ^ 1) ? BUFB : 0;
            #pragma unroll
            for (int i = 0; i < 2; i++) {
                cp16(dA[i] + bo,          a_srchi[i] + k0, a_bytes[i]);
                if (NT >= 2) cp16(dA[i] + bo + LO_OFF, a_srclo[i] + k0, a_bytes[i]);
                cp16(dB[i] + bo,          b_srchi[i] + k0, 16);
                if (NT == 3) cp16(dB[i] + bo + LO_OFF, b_srclo[i] + k0, 16);
            }
            cp_commit();
        }

        const uint32_t sA   = sm_base + buf * BUFB;
        const uint32_t sAlo = sA + LO_OFF;
        const uint32_t sB   = sA + 2 * LO_OFF;
        const uint32_t sBlo = sA + 3 * LO_OFF;

        #pragma unroll
        for (int ks = 0; ks < 2; ks++) {
            const uint32_t kbb = (uint32_t)(ks * 16 * 2);
            uint32_t bhi[2][4], blo[2][4];
            #pragma unroll
            for (int p = 0; p < 2; p++) {
                uint32_t po = (uint32_t)(p * 16 * ASTR * 2);
                ldmx4(bhi[p], sB + lb_off + kbb + po);
                if (NT == 3) ldmx4(blo[p], sBlo + lb_off + kbb + po);
            }
            #pragma unroll
            for (int mt = 0; mt < 4; mt++) {
                uint32_t mo = (uint32_t)(mt * 16 * ASTR * 2);
                uint32_t ah[4], al[4];
                ldmx4(ah, sA + la_off + kbb + mo);
                if (NT >= 2) ldmx4(al, sAlo + la_off + kbb + mo);
                #pragma unroll
                for (int nt = 0; nt < 4; nt++) {
                    const uint32_t* bh = &bhi[nt >> 1][(nt & 1) * 2];
                    mma_f16(acc[mt][nt], ah, bh);
                    if (NT >= 2) mma_f16(acc[mt][nt], al, bh);
                    if (NT == 3) {
                        const uint32_t* bl = &blo[nt >> 1][(nt & 1) * 2];
                        mma_f16(acc[mt][nt], ah, bl);
                    }
                }
            }
        }

        if (kt + 1 < nk) {
            cp_wait<0>();
            __syncthreads();
        }
    }

    #pragma unroll
    for (int mt = 0; mt < 4; mt++) {
        #pragma unroll
        for (int half = 0; half < 2; half++) {
            int r = m0 + wm * 64 + mt * 16 + g + half * 8;
            if (MOE && r >= M) continue;
            int cr = MOE ? c_idx[r] : r;
            #pragma unroll
            for (int nt = 0; nt < 4; nt++) {
                int c = n0 + wn * 32 + nt * 8 + 2 * q;
                float v0 = acc[mt][nt][half * 2 + 0] + bias[c];
                float v1 = acc[mt][nt][half * 2 + 1] + bias[c + 1];
                if (RELU) { v0 = fmaxf(v0, 0.f); v1 = fmaxf(v1, 0.f); }
                if (RESID) {
                    float2 rr = *(const float2*)(resid + (size_t)r * N + c);
                    v0 += rr.x; v1 += rr.y;
                }
                if (WMODE == 1) {
                    uint32_t h, l;
                    split2(v0, v1, h, l);
                    *(uint32_t*)&Chi[(size_t)cr * N + c] = h;
                    *(uint32_t*)&Clo[(size_t)cr * N + c] = l;
                } else if (WMODE == 2) {
                    __half2 h2v = __floats2half2_rn(v0, v1);
                    *(uint32_t*)&Chi[(size_t)cr * N + c] = *(uint32_t*)&h2v;
                } else {
                    *(float2*)(C + (size_t)cr * N + c) = make_float2(v0, v1);
                }
            }
        }
    }
}

// ---------------------------------------------------------------------------
// Tensor-core flash attention, fp16 3-term BOTH stages (R10 config):
//   S = Qhi*Khi + Qhi*Klo + Qlo*Khi
//   O = Phi*Vhi + Phi*Vlo + Plo*Vhi
// fp32 softmax. KV buffer: Khi, Klo, Vhi, Vlo.
// ---------------------------------------------------------------------------
#define AQS 72
#define AQ_ARR (64 * AQS * 2)
#define OFF_QHI 0
#define OFF_QLO AQ_ARR
#define OFF_KV  (2 * AQ_ARR)
#define KVBUF   (4 * AQ_ARR)
#define OFF_RED (OFF_KV + 2 * KVBUF)
#define ATT_SMEM (OFF_RED + 1024)

__global__ __launch_bounds__(256, 2)
void attn_tc(const __half* __restrict__ qkvhi,
             const __half* __restrict__ qkvlo,
             __half* __restrict__ ohi,
             __half* __restrict__ olo)
{
    extern __shared__ char asm_[];
    const uint32_t sb = (uint32_t)__cvta_generic_to_shared(asm_);
    const int qb = blockIdx.x, h = blockIdx.y, b = blockIdx.z;
    const int tid = threadIdx.x;
    const int wid = tid >> 5;
    const int lane = tid & 31;
    const int g = lane >> 2;
    const int q = lane & 3;
    const int wm = wid & 3;
    const int wn = wid >> 2;

    float* redmax = (float*)(asm_ + OFF_RED);
    float* redsum = (float*)(asm_ + OFF_RED + 512);

    {
        int row = tid >> 2;
        const __half* qh = qkvhi + (size_t)(b * Ss + qb * 64 + row) * (3 * Dm) + h * 64;
        const __half* ql = qkvlo + (size_t)(b * Ss + qb * 64 + row) * (3 * Dm) + h * 64;
        #pragma unroll
        for (int i = 0; i < 2; i++) {
            int c = (tid & 3) + 4 * i;
            cp16(sb + OFF_QHI + (row * AQS + c * 8) * 2, qh + c * 8, 16);
            cp16(sb + OFF_QLO + (row * AQS + c * 8) * 2, ql + c * 8, 16);
        }
    }
    const int kvrow = tid >> 2;
    const __half* kbase_hi = qkvhi + (size_t)(b * Ss) * (3 * Dm) + Dm + h * 64;
    const __half* kbase_lo = qkvlo + (size_t)(b * Ss) * (3 * Dm) + Dm + h * 64;
    auto load_kv = [&](int bufi, int kt) {
        uint32_t so = sb + OFF_KV + bufi * KVBUF;
        const __half* srch = kbase_hi + (size_t)(kt * 64 + kvrow) * (3 * Dm);
        const __half* srcl = kbase_lo + (size_t)(kt * 64 + kvrow) * (3 * Dm);
        #pragma unroll
        for (int i = 0; i < 2; i++) {
            int c = (tid & 3) + 4 * i;
            uint32_t sm = (uint32_t)((kvrow * AQS + c * 8) * 2);
            cp16(so + sm,              srch + c * 8, 16);           // K hi
            cp16(so + AQ_ARR + sm,     srcl + c * 8, 16);           // K lo
            cp16(so + 2 * AQ_ARR + sm, srch + Dm + c * 8, 16);      // V hi
            cp16(so + 3 * AQ_ARR + sm, srcl + Dm + c * 8, 16);      // V lo
        }
    };
    load_kv(0, 0);
    cp_commit();
    cp_wait<0>();
    __syncthreads();

    const uint32_t qa_off = (uint32_t)(((wm * 16 + (lane & 15)) * AQS
                                        + ((lane >> 4) << 3)) * 2);
    uint32_t qh[4][4], ql[4][4];
    #pragma unroll
    for (int ks = 0; ks < 4; ks++) {
        ldmx4(qh[ks], sb + OFF_QHI + qa_off + ks * 32);
        ldmx4(ql[ks], sb + OFF_QLO + qa_off + ks * 32);
    }

    const uint32_t kb_off = (uint32_t)(((wn * 32 + (lane & 7) + ((lane >> 4) << 3)) * AQS
                                        + (((lane >> 3) & 1) << 3)) * 2);
    const uint32_t vb_row = (uint32_t)(wn * 32 + ((lane >> 3) & 1) * 8 + (lane & 7));
    const uint32_t vb_col = (uint32_t)((lane >> 4) << 3);

    float m0 = -1e30f, m1 = -1e30f, l0 = 0.f, l1 = 0.f;
    float oacc[8][4] = {};

    const int NKV = Ss / 64;
    for (int kt = 0; kt < NKV; kt++) {
        const int bufi = kt & 1;
        if (kt + 1 < NKV) {
            load_kv(bufi ^ 1, kt + 1);
            cp_commit();
        }
        const uint32_t sK   = sb + OFF_KV + bufi * KVBUF;
        const uint32_t sKlo = sK + AQ_ARR;
        const uint32_t sV   = sK + 2 * AQ_ARR;
        const uint32_t sVlo = sK + 3 * AQ_ARR;

        float s[4][4] = {};
        #pragma unroll
        for (int ks = 0; ks < 4; ks++) {
            uint32_t bh[2][4], bl[2][4];
            #pragma unroll
            for (int p = 0; p < 2; p++) {
                uint32_t po = (uint32_t)(p * 16 * AQS * 2) + (uint32_t)(ks * 32);
                ldmx4(bh[p], sK   + kb_off + po);
                ldmx4(bl[p], sKlo + kb_off + po);
            }
            #pragma unroll
            for (int nt = 0; nt < 4; nt++) {
                const uint32_t* bhp = &bh[nt >> 1][(nt & 1) * 2];
                const uint32_t* blp = &bl[nt >> 1][(nt & 1) * 2];
                mma_f16(s[nt], qh[ks], bhp);
                mma_f16(s[nt], qh[ks], blp);
                mma_f16(s[nt], ql[ks], bhp);
            }
        }
        #pragma unroll
        for (int nt = 0; nt < 4; nt++)
            #pragma unroll
            for (int j = 0; j < 4; j++)
                s[nt][j] *= 0.125f;

        float mx0 = -1e30f, mx1 = -1e30f;
        #pragma unroll
        for (int nt = 0; nt < 4; nt++) {
            mx0 = fmaxf(mx0, fmaxf(s[nt][0], s[nt][1]));
            mx1 = fmaxf(mx1, fmaxf(s[nt][2], s[nt][3]));
        }
        #pragma unroll
        for (int off = 1; off < 4; off <<= 1) {
            mx0 = fmaxf(mx0, __shfl_xor_sync(0xffffffffu, mx0, off));
            mx1 = fmaxf(mx1, __shfl_xor_sync(0xffffffffu, mx1, off));
        }
        if (q == 0) {
            redmax[wn * 64 + wm * 16 + g]     = mx0;
            redmax[wn * 64 + wm * 16 + 8 + g] = mx1;
        }
        __syncthreads();
        float om0 = redmax[(wn ^ 1) * 64 + wm * 16 + g];
        float om1 = redmax[(wn ^ 1) * 64 + wm * 16 + 8 + g];
        float nm0 = fmaxf(m0, fmaxf(mx0, om0));
        float nm1 = fmaxf(m1, fmaxf(mx1, om1));

        float ps0 = 0.f, ps1 = 0.f;
        #pragma unroll
        for (int nt = 0; nt < 4; nt++) {
            s[nt][0] = __expf(s[nt][0] - nm0); ps0 += s[nt][0];
            s[nt][1] = __expf(s[nt][1] - nm0); ps0 += s[nt][1];
            s[nt][2] = __expf(s[nt][2] - nm1); ps1 += s[nt][2];
            s[nt][3] = __expf(s[nt][3] - nm1); ps1 += s[nt][3];
        }
        #pragma unroll
        for (int off = 1; off < 4; off <<= 1) {
            ps0 += __shfl_xor_sync(0xffffffffu, ps0, off);
            ps1 += __shfl_xor_sync(0xffffffffu, ps1, off);
        }
        if (q == 0) {
            redsum[wn * 64 + wm * 16 + g]     = ps0;
            redsum[wn * 64 + wm * 16 + 8 + g] = ps1;
        }
        __syncthreads();
        float os0 = redsum[(wn ^ 1) * 64 + wm * 16 + g];
        float os1 = redsum[(wn ^ 1) * 64 + wm * 16 + 8 + g];
        float corr0 = __expf(m0 - nm0);
        float corr1 = __expf(m1 - nm1);
        m0 = nm0; m1 = nm1;
        l0 = l0 * corr0 + ps0 + os0;
        l1 = l1 * corr1 + ps1 + os1;
        #pragma unroll
        for (int nt = 0; nt < 8; nt++) {
            oacc[nt][0] *= corr0; oacc[nt][1] *= corr0;
            oacc[nt][2] *= corr1; oacc[nt][3] *= corr1;
        }

        #pragma unroll
        for (int sstep = 0; sstep < 2; sstep++) {
            uint32_t ph[4], pl[4];
            split2(s[2 * sstep][0],     s[2 * sstep][1],     ph[0], pl[0]);
            split2(s[2 * sstep][2],     s[2 * sstep][3],     ph[1], pl[1]);
            split2(s[2 * sstep + 1][0], s[2 * sstep + 1][1], ph[2], pl[2]);
            split2(s[2 * sstep + 1][2], s[2 * sstep + 1][3], ph[3], pl[3]);
            #pragma unroll
            for (int dp = 0; dp < 4; dp++) {
                uint32_t vh[4], vl[4];
                uint32_t va = (uint32_t)(((vb_row + sstep * 16) * AQS
                                          + dp * 16 + vb_col) * 2);
                ldmx4t(vh, sV   + va);
                ldmx4t(vl, sVlo + va);
                #pragma unroll
                for (int half = 0; half < 2; half++) {
                    int nt = dp * 2 + half;
                    const uint32_t* vhp = &vh[half * 2];
                    const uint32_t* vlp = &vl[half * 2];
                    mma_f16(oacc[nt], ph, vhp);
                    mma_f16(oacc[nt], ph, vlp);
                    mma_f16(oacc[nt], pl, vhp);
                }
            }
        }

        if (kt + 1 < NKV) {
            cp_wait<0>();
            __syncthreads();
        }
    }

    float* ob = (float*)asm_;
    __syncthreads();
    if (wn == 1) {
        #pragma unroll
        for (int nt = 0; nt < 8; nt++)
            #pragma unroll
            for (int j = 0; j < 4; j++) {
                int row = wm * 16 + g + ((j >> 1) << 3);
                int col = nt * 8 + 2 * q + (j & 1);
                ob[row * 64 + col] = oacc[nt][j];
            }
    }
    __syncthreads();
    if (wn == 0) {
        float inv0 = 1.0f / l0, inv1 = 1.0f / l1;
        #pragma unroll
        for (int nt = 0; nt < 8; nt++) {
            int col = nt * 8 + 2 * q;
            #pragma unroll
            for (int hrow = 0; hrow < 2; hrow++) {
                int row = wm * 16 + g + hrow * 8;
                float inv = hrow ? inv1 : inv0;
                float v0 = (oacc[nt][hrow * 2 + 0] + ob[row * 64 + col])     * inv;
                float v1 = (oacc[nt][hrow * 2 + 1] + ob[row * 64 + col + 1]) * inv;
                uint32_t hh, ll;
                split2(v0, v1, hh, ll);
                size_t t = (size_t)(b * Ss + qb * 64 + row);
                size_t o = t * Dm + h * 64 + col;
                *(uint32_t*)&ohi[o] = hh;
                *(uint32_t*)&olo[o] = ll;
            }
        }
    }
}

// ---------------------------------------------------------------------------
// Gating + routing
// ---------------------------------------------------------------------------
__global__ void gate_route_kernel(const float* __restrict__ h2,
                                  const float* __restrict__ gw,
                                  const float* __restrict__ gb,
                                  int* __restrict__ cnt,
                                  int* __restrict__ tok,
                                  int* __restrict__ dst,
                                  float* __restrict__ gw2)
{
    int t = blockIdx.x * 8 + (threadIdx.x >> 5);
    int lane = threadIdx.x & 31;
    const float* xr = h2 + (size_t)t * Dm;
    float acc[Ee] = {};
    for (int d = lane; d < Dm; d += 32) {
        float xv = xr[d];
        #pragma unroll
        for (int e = 0; e < Ee; e++)
            acc[e] = fmaf(xv, gw[d * Ee + e], acc[e]);
    }
    #pragma unroll
    for (int e = 0; e < Ee; e++)
        #pragma unroll
        for (int off = 16; off; off >>= 1)
            acc[e] += __shfl_xor_sync(0xffffffffu, acc[e], off);

    if (lane == 0) {
        float lg[Ee];
        #pragma unroll
        for (int e = 0; e < Ee; e++) lg[e] = acc[e] + gb[e];
        int i0 = 0;
        #pragma unroll
        for (int e = 1; e < Ee; e++) if (lg[e] > lg[i0]) i0 = e;
        int i1 = -1;
        #pragma unroll
        for (int e = 0; e < Ee; e++) {
            if (e == i0) continue;
            if (i1 < 0 || lg[e] > lg[i1]) i1 = e;
        }
        float e1 = expf(lg[i1] - lg[i0]);
        float denom = 1.0f / (1.0f + e1);
        float g0 = denom, g1 = e1 * denom;
        int p0 = atomicAdd(&cnt[i0], 1);
        tok[i0 * LISTCAP + p0] = t;
        dst[i0 * LISTCAP + p0] = t * 2;
        int p1 = atomicAdd(&cnt[i1], 1);
        tok[i1 * LISTCAP + p1] = t;
        dst[i1 * LISTCAP + p1] = t * 2 + 1;
        gw2[t * 2]     = g0;
        gw2[t * 2 + 1] = g1;
    }
}

// ---------------------------------------------------------------------------
// Final combine
// ---------------------------------------------------------------------------
__global__ void combine_kernel(float* __restrict__ out,
                               const float* __restrict__ moeo,
                               const float* __restrict__ gw2)
{
    int t = blockIdx.x;
    float g0 = gw2[t * 2], g1 = gw2[t * 2 + 1];
    const float* r0 = moeo + (size_t)(t * 2) * Dm;
    const float* r1 = r0 + Dm;
    float* orow = out + (size_t)t * Dm;
    for (int d = threadIdx.x; d < Dm; d += 256)
        orow[d] += g0 * r0[d] + g1 * r1[d];
}

// ---------------------------------------------------------------------------
// Launch
// ---------------------------------------------------------------------------
extern "C" void kernel_launch(void* const* d_in, const int* in_sizes, int n_in,
                              void* d_out, int out_size)
{
    const float* x      = (const float*)d_in[0];
    const float* ln1_g  = (const float*)d_in[1];
    const float* ln1_b  = (const float*)d_in[2];
    const float* w_qkv  = (const float*)d_in[3];
    const float* b_qkv  = (const float*)d_in[4];
    const float* w_o    = (const float*)d_in[5];
    const float* b_o    = (const float*)d_in[6];
    const float* ln2_g  = (const float*)d_in[7];
    const float* ln2_b  = (const float*)d_in[8];
    const float* gate_w = (const float*)d_in[9];
    const float* gate_b = (const float*)d_in[10];
    const float* W1     = (const float*)d_in[11];
    const float* b1     = (const float*)d_in[12];
    const float* W2     = (const float*)d_in[13];
    const float* b2     = (const float*)d_in[14];
    float* out = (float*)d_out;

    float *h2, *moeo, *gwp;
    int *cnt, *tok, *dst;
    __half *h1hi, *h1lo, *qkvhi, *qkvlo, *atthi, *attlo, *h2hi, *hidhi;
    __half *wqkvThi, *wqkvTlo, *woThi, *woTlo, *W1Thi, *W2Thi;
    cudaGetSymbolAddress((void**)&h2,    g_h2);
    cudaGetSymbolAddress((void**)&moeo,  g_moeo);
    cudaGetSymbolAddress((void**)&cnt,   g_cnt);
    cudaGetSymbolAddress((void**)&tok,   g_tok);
    cudaGetSymbolAddress((void**)&dst,   g_dst);
    cudaGetSymbolAddress((void**)&gwp,   g_gw);
    cudaGetSymbolAddress((void**)&h1hi,  g_h1hi);
    cudaGetSymbolAddress((void**)&h1lo,  g_h1lo);
    cudaGetSymbolAddress((void**)&qkvhi, g_qkvhi);
    cudaGetSymbolAddress((void**)&qkvlo, g_qkvlo);
    cudaGetSymbolAddress((void**)&atthi, g_atthi);
    cudaGetSymbolAddress((void**)&attlo, g_attlo);
    cudaGetSymbolAddress((void**)&h2hi,  g_h2hi);
    cudaGetSymbolAddress((void**)&hidhi, g_hidhi);
    cudaGetSymbolAddress((void**)&wqkvThi, g_wqkvThi);
    cudaGetSymbolAddress((void**)&wqkvTlo, g_wqkvTlo);
    cudaGetSymbolAddress((void**)&woThi, g_woThi);
    cudaGetSymbolAddress((void**)&woTlo, g_woTlo);
    cudaGetSymbolAddress((void**)&W1Thi, g_W1Thi);
    cudaGetSymbolAddress((void**)&W2Thi, g_W2Thi);

    static bool attr_done = false;
    if (!attr_done) {
        cudaFuncSetAttribute(attn_tc,
                             cudaFuncAttributeMaxDynamicSharedMemorySize, ATT_SMEM);
        cudaFuncSetAttribute(gemm_split<false, false, false, 1, 3>,
                             cudaFuncAttributeMaxDynamicSharedMemorySize, GEMM_SMEM);
        cudaFuncSetAttribute(gemm_split<false, false, true, 0, 3>,
                             cudaFuncAttributeMaxDynamicSharedMemorySize, GEMM_SMEM);
        cudaFuncSetAttribute(gemm_split<true, true, false, 2, 1>,
                             cudaFuncAttributeMaxDynamicSharedMemorySize, GEMM_SMEM);
        cudaFuncSetAttribute(gemm_split<true, false, false, 0, 1>,
                             cudaFuncAttributeMaxDynamicSharedMemorySize, GEMM_SMEM);
        attr_done = true;
    }

    cudaMemsetAsync(cnt, 0, Ee * sizeof(int));

    // 0) weight transpose + split (wqkv & wo: hi+lo for 3-term; W1/W2 hi only)
    convT_kernel<<<dim3(3 * Dm / 32, Dm / 64, 1), 256>>>(w_qkv, wqkvThi, wqkvTlo, Dm, 3 * Dm);
    convT_kernel<<<dim3(Dm / 32, Dm / 64, 1), 256>>>(w_o, woThi, woTlo, Dm, Dm);
    convT_kernel<<<dim3(DFFf / 32, Dm / 64, Ee), 256>>>(W1, W1Thi, nullptr, Dm, DFFf);
    convT_kernel<<<dim3(Dm / 32, DFFf / 64, Ee), 256>>>(W2, W2Thi, nullptr, DFFf, Dm);

    // 1) LN1 -> fp16 hi/lo
    ln_kernel<<<Tt, 256>>>(x, ln1_g, ln1_b, nullptr, h1hi, h1lo);

    // 2) QKV (3-term, gate-upstream) -> fp16 hi/lo
    gemm_split<false, false, false, 1, 3><<<dim3(3 * Dm / 128, Tt / 128), 256, GEMM_SMEM>>>(
        h1hi, h1lo, wqkvThi, wqkvTlo, nullptr, qkvhi, qkvlo,
        b_qkv, nullptr, nullptr, nullptr, nullptr, Tt, Dm, 3 * Dm);

    // 3) attention (3-term both stages, gate-upstream) -> fp16 hi/lo
    attn_tc<<<dim3(Ss / 64, Hh, Bb), 256, ATT_SMEM>>>(qkvhi, qkvlo, atthi, attlo);

    // 4) x1 = x + attno @ w_o + b_o (3-term, gate-upstream, fp32 -> d_out)
    gemm_split<false, false, true, 0, 3><<<dim3(Dm / 128, Tt / 128), 256, GEMM_SMEM>>>(
        atthi, attlo, woThi, woTlo, out, nullptr, nullptr,
        b_o, x, nullptr, nullptr, nullptr, Tt, Dm, Dm);

    // 5) LN2 -> fp32 (gate) + fp16 hi (MoE A, 1-term)
    ln_kernel<<<Tt, 256>>>(out, ln2_g, ln2_b, h2, h2hi, nullptr);

    // 6) gating + routing (fp32 h2 — routing exact)
    gate_route_kernel<<<Tt / 8, 256>>>(h2, gate_w, gate_b, cnt, tok, dst, gwp);

    // 7) MoE FFN1 (1-term plain fp16, gate-downstream) -> fp16 hi
    gemm_split<true, true, false, 2, 1><<<dim3(DFFf / 128, LISTCAP / 128, Ee), 256, GEMM_SMEM>>>(
        h2hi, nullptr, W1Thi, nullptr, nullptr, hidhi, nullptr,
        b1, nullptr, tok, dst, cnt, 0, Dm, DFFf);

    // 8) MoE FFN2 (1-term plain fp16, fp32 out)
    gemm_split<true, false, false, 0, 1><<<dim3(Dm / 128, LISTCAP / 128, Ee), 256, GEMM_SMEM>>>(
        hidhi, nullptr, W2Thi, nullptr, moeo, nullptr, nullptr,
        b2, nullptr, dst, dst, cnt, 0, DFFf, Dm);

    // 9) combine
    combine_kernel<<<Tt, 256>>>(out, moeo, gwp);
}

// round 17
// speedup vs baseline: 4.0947x; 1.0132x over previous
#include <cuda_runtime.h>
#include <cuda_fp16.h>
#include <math.h>
#include <stdint.h>

// Problem constants
#define Dm   1024
#define Hh   16
#define DKk  64
#define Ee   8
#define DFFf 4096
#define Ss   2048
#define Bb   2
#define Tt   (Bb * Ss)
#define NPAIR (Tt * 2)
#define LISTCAP 8192

// ---------------------------------------------------------------------------
// Static device scratch
// ---------------------------------------------------------------------------
__device__ float g_moeo[(size_t)NPAIR * Dm];
__device__ int   g_cnt[Ee];
__device__ int   g_tok[Ee * LISTCAP];
__device__ int   g_dst[Ee * LISTCAP];
__device__ float g_gw[NPAIR];

__device__ __half g_h1hi[(size_t)Tt * Dm],  g_h1lo[(size_t)Tt * Dm];
__device__ __half g_qkvhi[(size_t)Tt * 3 * Dm], g_qkvlo[(size_t)Tt * 3 * Dm];
__device__ __half g_atthi[(size_t)Tt * Dm], g_attlo[(size_t)Tt * Dm];
__device__ __half g_h2hi[(size_t)Tt * Dm];
__device__ __half g_hidhi[(size_t)NPAIR * DFFf];
__device__ __half g_wqkvThi[(size_t)3 * Dm * Dm], g_wqkvTlo[(size_t)3 * Dm * Dm];
__device__ __half g_woThi[(size_t)Dm * Dm],       g_woTlo[(size_t)Dm * Dm];
__device__ __half g_W1Thi[(size_t)Ee * DFFf * Dm];
__device__ __half g_W2Thi[(size_t)Ee * Dm * DFFf];

// ---------------------------------------------------------------------------
// helpers
// ---------------------------------------------------------------------------
__device__ __forceinline__ void split2(float f0, float f1,
                                       uint32_t& hi, uint32_t& lo) {
    __half2 h2v = __floats2half2_rn(f0, f1);
    float2 hf = __half22float2(h2v);
    __half2 l2v = __floats2half2_rn(f0 - hf.x, f1 - hf.y);
    hi = *(uint32_t*)&h2v;
    lo = *(uint32_t*)&l2v;
}
__device__ __forceinline__ void cp16(uint32_t dst, const void* src, int src_bytes) {
    asm volatile("cp.async.cg.shared.global [%0], [%1], 16, %2;"
                 :: "r"(dst), "l"(src), "r"(src_bytes));
}
__device__ __forceinline__ void cp_commit() {
    asm volatile("cp.async.commit_group;");
}
template<int N>
__device__ __forceinline__ void cp_wait() {
    asm volatile("cp.async.wait_group %0;" :: "n"(N));
}
__device__ __forceinline__ void mma_f16(float* c, const uint32_t* a, const uint32_t* b) {
    asm volatile(
        "mma.sync.aligned.m16n8k16.row.col.f32.f16.f16.f32 "
        "{%0,%1,%2,%3}, {%4,%5,%6,%7}, {%8,%9}, {%0,%1,%2,%3};"
        : "+f"(c[0]), "+f"(c[1]), "+f"(c[2]), "+f"(c[3])
        : "r"(a[0]), "r"(a[1]), "r"(a[2]), "r"(a[3]), "r"(b[0]), "r"(b[1]));
}
__device__ __forceinline__ void ldmx4(uint32_t* r, uint32_t addr) {
    asm volatile("ldmatrix.sync.aligned.m8n8.x4.shared.b16 {%0,%1,%2,%3}, [%4];"
                 : "=r"(r[0]), "=r"(r[1]), "=r"(r[2]), "=r"(r[3]) : "r"(addr));
}
__device__ __forceinline__ void ldmx4t(uint32_t* r, uint32_t addr) {
    asm volatile("ldmatrix.sync.aligned.m8n8.x4.trans.shared.b16 {%0,%1,%2,%3}, [%4];"
                 : "=r"(r[0]), "=r"(r[1]), "=r"(r[2]), "=r"(r[3]) : "r"(addr));
}

// ---------------------------------------------------------------------------
// Weight transpose + split: fp32 [K,N] -> fp16 hi (+optional lo) [N,K].
// ---------------------------------------------------------------------------
__global__ void convT_kernel(const float* __restrict__ src,
                             __half* __restrict__ hi,
                             __half* __restrict__ lo,   // may be null
                             int K, int N)
{
    __shared__ float tile[64][33];
    int z = blockIdx.z;
    src += (size_t)z * K * N;
    hi  += (size_t)z * K * N;
    if (lo) lo += (size_t)z * K * N;
    int k0 = blockIdx.y * 64, n0 = blockIdx.x * 32;
    int t = threadIdx.x;
    #pragma unroll
    for (int i = 0; i < 8; i++) {
        int idx = t + i * 256;
        int r = idx >> 5, c = idx & 31;
        tile[r][c] = src[(size_t)(k0 + r) * N + n0 + c];
    }
    __syncthreads();
    int n  = t >> 3;
    int kc = (t & 7) * 8;
    uint32_t hp[4], lp[4];
    #pragma unroll
    for (int j = 0; j < 4; j++) {
        float f0 = tile[kc + 2 * j][n];
        float f1 = tile[kc + 2 * j + 1][n];
        split2(f0, f1, hp[j], lp[j]);
    }
    size_t o = (size_t)(n0 + n) * K + k0 + kc;
    *(uint4*)&hi[o] = *(uint4*)hp;
    if (lo) *(uint4*)&lo[o] = *(uint4*)lp;
}

// ---------------------------------------------------------------------------
// LayerNorm (LN1): writes fp16 hi/lo
// ---------------------------------------------------------------------------
__global__ void ln_kernel(const float* __restrict__ x,
                          const float* __restrict__ g,
                          const float* __restrict__ b,
                          __half* __restrict__ ohi,
                          __half* __restrict__ olo)
{
    int t = blockIdx.x;
    const float* xr = x + (size_t)t * Dm;
    float s = 0.f, s2 = 0.f;
    for (int d = threadIdx.x; d < Dm; d += 256) {
        float v = xr[d];
        s += v; s2 += v * v;
    }
    #pragma unroll
    for (int off = 16; off; off >>= 1) {
        s  += __shfl_xor_sync(0xffffffffu, s, off);
        s2 += __shfl_xor_sync(0xffffffffu, s2, off);
    }
    __shared__ float sh[18];
    int w = threadIdx.x >> 5;
    if ((threadIdx.x & 31) == 0) { sh[w] = s; sh[w + 8] = s2; }
    __syncthreads();
    if (threadIdx.x == 0) {
        float ts = 0.f, ts2 = 0.f;
        #pragma unroll
        for (int i = 0; i < 8; i++) { ts += sh[i]; ts2 += sh[i + 8]; }
        sh[16] = ts; sh[17] = ts2;
    }
    __syncthreads();
    float mean = sh[16] * (1.0f / Dm);
    float var  = sh[17] * (1.0f / Dm) - mean * mean;
    float rstd = rsqrtf(var + 1e-5f);
    for (int d = threadIdx.x; d < Dm; d += 256) {
        float v = (xr[d] - mean) * rstd * g[d] + b[d];
        __half h = __float2half_rn(v);
        float r = v - __half2float(h);
        ohi[(size_t)t * Dm + d] = h;
        olo[(size_t)t * Dm + d] = __float2half_rn(r);
    }
}

// ---------------------------------------------------------------------------
// Fused LN2 + gate + top-2 routing. One block per token.
// Writes h2 fp16 hi; gate logits in fp32 from un-rounded values.
// ---------------------------------------------------------------------------
__global__ void ln2_gate_kernel(const float* __restrict__ x,
                                const float* __restrict__ g,
                                const float* __restrict__ b,
                                const float* __restrict__ gw,
                                const float* __restrict__ gb,
                                __half* __restrict__ ohi,
                                int* __restrict__ cnt,
                                int* __restrict__ tok,
                                int* __restrict__ dst,
                                float* __restrict__ gw2)
{
    int t = blockIdx.x;
    const float* xr = x + (size_t)t * Dm;
    float s = 0.f, s2 = 0.f;
    for (int d = threadIdx.x; d < Dm; d += 256) {
        float v = xr[d];
        s += v; s2 += v * v;
    }
    #pragma unroll
    for (int off = 16; off; off >>= 1) {
        s  += __shfl_xor_sync(0xffffffffu, s, off);
        s2 += __shfl_xor_sync(0xffffffffu, s2, off);
    }
    __shared__ float sh[18];
    __shared__ float sl[8][8];
    int w = threadIdx.x >> 5;
    int lane = threadIdx.x & 31;
    if (lane == 0) { sh[w] = s; sh[w + 8] = s2; }
    __syncthreads();
    if (threadIdx.x == 0) {
        float ts = 0.f, ts2 = 0.f;
        #pragma unroll
        for (int i = 0; i < 8; i++) { ts += sh[i]; ts2 += sh[i + 8]; }
        sh[16] = ts; sh[17] = ts2;
    }
    __syncthreads();
    float mean = sh[16] * (1.0f / Dm);
    float var  = sh[17] * (1.0f / Dm) - mean * mean;
    float rstd = rsqrtf(var + 1e-5f);

    float logit[Ee] = {};
    for (int d = threadIdx.x; d < Dm; d += 256) {
        float v = (xr[d] - mean) * rstd * g[d] + b[d];
        ohi[(size_t)t * Dm + d] = __float2half_rn(v);
        #pragma unroll
        for (int e = 0; e < Ee; e++)
            logit[e] = fmaf(v, gw[d * Ee + e], logit[e]);
    }
    #pragma unroll
    for (int e = 0; e < Ee; e++)
        #pragma unroll
        for (int off = 16; off; off >>= 1)
            logit[e] += __shfl_xor_sync(0xffffffffu, logit[e], off);
    if (lane == 0)
        #pragma unroll
        for (int e = 0; e < Ee; e++) sl[w][e] = logit[e];
    __syncthreads();
    if (threadIdx.x == 0) {
        float lg[Ee];
        #pragma unroll
        for (int e = 0; e < Ee; e++) {
            float acc = gb[e];
            #pragma unroll
            for (int ww = 0; ww < 8; ww++) acc += sl[ww][e];
            lg[e] = acc;
        }
        int i0 = 0;
        #pragma unroll
        for (int e = 1; e < Ee; e++) if (lg[e] > lg[i0]) i0 = e;
        int i1 = -1;
        #pragma unroll
        for (int e = 0; e < Ee; e++) {
            if (e == i0) continue;
            if (i1 < 0 || lg[e] > lg[i1]) i1 = e;
        }
        float e1 = expf(lg[i1] - lg[i0]);
        float denom = 1.0f / (1.0f + e1);
        float g0 = denom, g1 = e1 * denom;
        int p0 = atomicAdd(&cnt[i0], 1);
        tok[i0 * LISTCAP + p0] = t;
        dst[i0 * LISTCAP + p0] = t * 2;
        int p1 = atomicAdd(&cnt[i1], 1);
        tok[i1 * LISTCAP + p1] = t;
        dst[i1 * LISTCAP + p1] = t * 2 + 1;
        gw2[t * 2]     = g0;
        gw2[t * 2 + 1] = g1;
    }
}

// ---------------------------------------------------------------------------
// fp16 split GEMM with multi-stage cp.async ring.
// NT=3: Ahi*Bhi + Ahi*Blo + Alo*Bhi (STAGES=2, 4 tiles/stage).
// NT=1: Ahi*Bhi (STAGES=4, 2 tiles/stage — deep latency hiding).
// WMODE: 0 = fp32 out, 1 = fp16 hi+lo out, 2 = fp16 hi-only out.
// ---------------------------------------------------------------------------
#define ASTR 40
#define TILE_BF (128 * ASTR)
#define ABYTES ((uint32_t)(TILE_BF * 2))   // 10,240 B per operand tile
#define GEMM_SMEM 81920                     // both NT cfgs use 81,920 B total

template<bool MOE, bool RELU, bool RESID, int WMODE, int NT>
__global__ __launch_bounds__(256, 2)
void gemm_split(const __half* __restrict__ Ahi,
                const __half* __restrict__ Alo,    // unused if NT==1
                const __half* __restrict__ BThi,   // [N,K]
                const __half* __restrict__ BTlo,   // unused if NT<3
                float* __restrict__ C,
                __half* __restrict__ Chi,
                __half* __restrict__ Clo,
                const float* __restrict__ bias,
                const float* __restrict__ resid,
                const int* __restrict__ a_idx,
                const int* __restrict__ c_idx,
                const int* __restrict__ cnt,
                int M, int K, int N)
{
    constexpr int STAGES = (NT == 1) ? 4 : 2;
    constexpr int NTILES = (NT == 3) ? 4 : ((NT == 2) ? 3 : 2);
    const uint32_t STAGE_B = NTILES * ABYTES;

    if (MOE) {
        int z = blockIdx.z;
        M = cnt[z];
        BThi += (size_t)z * K * N;
        if (NT == 3) BTlo += (size_t)z * K * N;
        bias += (size_t)z * N;
        a_idx += z * LISTCAP;
        c_idx += z * LISTCAP;
    }
    const int m0 = blockIdx.y * 128;
    if (m0 >= M) return;
    const int n0 = blockIdx.x * 128;

    extern __shared__ __half bsm[];

    const int tid = threadIdx.x;
    const int wid = tid >> 5;
    const int lane = tid & 31;
    const int g = lane >> 2;
    const int q = lane & 3;
    const int wm = wid & 1;
    const int wn = wid >> 1;

    const int kc = (tid & 3) * 8;
    int rl[2];
    rl[0] = tid >> 2;
    rl[1] = (tid >> 2) + 64;

    const __half* a_srchi[2];
    const __half* a_srclo[2];
    int a_bytes[2];
    #pragma unroll
    for (int i = 0; i < 2; i++) {
        int r = m0 + rl[i];
        bool valid = r < M;
        int gr = valid ? (MOE ? a_idx[r] : r) : 0;
        a_srchi[i] = Ahi + (size_t)gr * K + kc;
        a_srclo[i] = (NT >= 2) ? (Alo + (size_t)gr * K + kc) : a_srchi[i];
        a_bytes[i] = valid ? 16 : 0;
    }
    const __half* b_srchi[2];
    const __half* b_srclo[2];
    #pragma unroll
    for (int i = 0; i < 2; i++) {
        int n = n0 + rl[i];
        b_srchi[i] = BThi + (size_t)n * K + kc;
        b_srclo[i] = (NT == 3) ? (BTlo + (size_t)n * K + kc) : b_srchi[i];
    }

    const uint32_t sm_base = (uint32_t)__cvta_generic_to_shared(bsm);
    uint32_t dAoff[2], dBoff[2];
    #pragma unroll
    for (int i = 0; i < 2; i++) {
        dAoff[i] = (uint32_t)((rl[i] * ASTR + kc) * 2);
        dBoff[i] = dAoff[i] + (NT >= 2 ? 2 : 1) * ABYTES;
    }

    auto loadtile = [&](int stage, int kt) {
        uint32_t base = sm_base + stage * STAGE_B;
        int ko = kt * 32;
        #pragma unroll
        for (int i = 0; i < 2; i++) {
            cp16(base + dAoff[i], a_srchi[i] + ko, a_bytes[i]);
            if (NT >= 2) cp16(base + dAoff[i] + ABYTES, a_srclo[i] + ko, a_bytes[i]);
            cp16(base + dBoff[i], b_srchi[i] + ko, 16);
            if (NT == 3) cp16(base + dBoff[i] + ABYTES, b_srclo[i] + ko, 16);
        }
    };

    const int nk = K / 32;

    #pragma unroll
    for (int s = 0; s < STAGES - 1; s++) {
        loadtile(s, s);
        cp_commit();
    }

    float acc[4][4][4] = {};

    const uint32_t la_off = (uint32_t)(((wm * 64 + (lane & 15)) * ASTR
                                        + ((lane >> 4) << 3)) * 2);
    const uint32_t lb_off = (uint32_t)(((wn * 32 + (lane & 7) + ((lane >> 4) << 3)) * ASTR
                                        + (((lane >> 3) & 1) << 3)) * 2);

    for (int kt = 0; kt < nk; kt++) {
        int rem = nk - 1 - kt;
        if (STAGES == 2) {
            cp_wait<0>();
        } else {
            if (rem >= STAGES - 2)      cp_wait<STAGES - 2>();
            else if (rem == 1)          cp_wait<1>();
            else                        cp_wait<0>();
        }
        __syncthreads();   // tile kt visible to all; buffer (kt-1)%STAGES free

        int pf = kt + STAGES - 1;
        if (pf < nk) {
            loadtile(pf & (STAGES - 1), pf);
            cp_commit();
        }

        const uint32_t sA   = sm_base + (uint32_t)(kt & (STAGES - 1)) * STAGE_B;
        const uint32_t sAlo = sA + ABYTES;
        const uint32_t sB   = sA + (NT >= 2 ? 2 : 1) * ABYTES;
        const uint32_t sBlo = sB + ABYTES;

        #pragma unroll
        for (int ks = 0; ks < 2; ks++) {
            const uint32_t kbb = (uint32_t)(ks * 16 * 2);
            uint32_t bhi[2][4], blo[2][4];
            #pragma unroll
            for (int p = 0; p < 2; p++) {
                uint32_t po = (uint32_t)(p * 16 * ASTR * 2);
                ldmx4(bhi[p], sB + lb_off + kbb + po);
                if (NT == 3) ldmx4(blo[p], sBlo + lb_off + kbb + po);
            }
            #pragma unroll
            for (int mt = 0; mt < 4; mt++) {
                uint32_t mo = (uint32_t)(mt * 16 * ASTR * 2);
                uint32_t ah[4], al[4];
                ldmx4(ah, sA + la_off + kbb + mo);
                if (NT >= 2) ldmx4(al, sAlo + la_off + kbb + mo);
                #pragma unroll
                for (int nt = 0; nt < 4; nt++) {
                    const uint32_t* bh = &bhi[nt >> 1][(nt & 1) * 2];
                    mma_f16(acc[mt][nt], ah, bh);
                    if (NT >= 2) mma_f16(acc[mt][nt], al, bh);
                    if (NT == 3) {
                        const uint32_t* bl = &blo[nt >> 1][(nt & 1) * 2];
                        mma_f16(acc[mt][nt], ah, bl);
                    }
                }
            }
        }
    }

    #pragma unroll
    for (int mt = 0; mt < 4; mt++) {
        #pragma unroll
        for (int half = 0; half < 2; half++) {
            int r = m0 + wm * 64 + mt * 16 + g + half * 8;
            if (MOE && r >= M) continue;
            int cr = MOE ? c_idx[r] : r;
            #pragma unroll
            for (int nt = 0; nt < 4; nt++) {
                int c = n0 + wn * 32 + nt * 8 + 2 * q;
                float v0 = acc[mt][nt][half * 2 + 0] + bias[c];
                float v1 = acc[mt][nt][half * 2 + 1] + bias[c + 1];
                if (RELU) { v0 = fmaxf(v0, 0.f); v1 = fmaxf(v1, 0.f); }
                if (RESID) {
                    float2 rr = *(const float2*)(resid + (size_t)r * N + c);
                    v0 += rr.x; v1 += rr.y;
                }
                if (WMODE == 1) {
                    uint32_t h, l;
                    split2(v0, v1, h, l);
                    *(uint32_t*)&Chi[(size_t)cr * N + c] = h;
                    *(uint32_t*)&Clo[(size_t)cr * N + c] = l;
                } else if (WMODE == 2) {
                    __half2 h2v = __floats2half2_rn(v0, v1);
                    *(uint32_t*)&Chi[(size_t)cr * N + c] = *(uint32_t*)&h2v;
                } else {
                    *(float2*)(C + (size_t)cr * N + c) = make_float2(v0, v1);
                }
            }
        }
    }
}

// ---------------------------------------------------------------------------
// Tensor-core flash attention, fp16 3-term BOTH stages (gate-upstream):
//   S = Qhi*Khi + Qhi*Klo + Qlo*Khi
//   O = Phi*Vhi + Phi*Vlo + Plo*Vhi
// fp32 softmax. KV buffer: Khi, Klo, Vhi, Vlo.
// ---------------------------------------------------------------------------
#define AQS 72
#define AQ_ARR (64 * AQS * 2)
#define OFF_QHI 0
#define OFF_QLO AQ_ARR
#define OFF_KV  (2 * AQ_ARR)
#define KVBUF   (4 * AQ_ARR)
#define OFF_RED (OFF_KV + 2 * KVBUF)
#define ATT_SMEM (OFF_RED + 1024)

__global__ __launch_bounds__(256, 2)
void attn_tc(const __half* __restrict__ qkvhi,
             const __half* __restrict__ qkvlo,
             __half* __restrict__ ohi,
             __half* __restrict__ olo)
{
    extern __shared__ char asm_[];
    const uint32_t sb = (uint32_t)__cvta_generic_to_shared(asm_);
    const int qb = blockIdx.x, h = blockIdx.y, b = blockIdx.z;
    const int tid = threadIdx.x;
    const int wid = tid >> 5;
    const int lane = tid & 31;
    const int g = lane >> 2;
    const int q = lane & 3;
    const int wm = wid & 3;
    const int wn = wid >> 2;

    float* redmax = (float*)(asm_ + OFF_RED);
    float* redsum = (float*)(asm_ + OFF_RED + 512);

    {
        int row = tid >> 2;
        const __half* qh = qkvhi + (size_t)(b * Ss + qb * 64 + row) * (3 * Dm) + h * 64;
        const __half* ql = qkvlo + (size_t)(b * Ss + qb * 64 + row) * (3 * Dm) + h * 64;
        #pragma unroll
        for (int i = 0; i < 2; i++) {
            int c = (tid & 3) + 4 * i;
            cp16(sb + OFF_QHI + (row * AQS + c * 8) * 2, qh + c * 8, 16);
            cp16(sb + OFF_QLO + (row * AQS + c * 8) * 2, ql + c * 8, 16);
        }
    }
    const int kvrow = tid >> 2;
    const __half* kbase_hi = qkvhi + (size_t)(b * Ss) * (3 * Dm) + Dm + h * 64;
    const __half* kbase_lo = qkvlo + (size_t)(b * Ss) * (3 * Dm) + Dm + h * 64;
    auto load_kv = [&](int bufi, int kt) {
        uint32_t so = sb + OFF_KV + bufi * KVBUF;
        const __half* srch = kbase_hi + (size_t)(kt * 64 + kvrow) * (3 * Dm);
        const __half* srcl = kbase_lo + (size_t)(kt * 64 + kvrow) * (3 * Dm);
        #pragma unroll
        for (int i = 0; i < 2; i++) {
            int c = (tid & 3) + 4 * i;
            uint32_t sm = (uint32_t)((kvrow * AQS + c * 8) * 2);
            cp16(so + sm,              srch + c * 8, 16);           // K hi
            cp16(so + AQ_ARR + sm,     srcl + c * 8, 16);           // K lo
            cp16(so + 2 * AQ_ARR + sm, srch + Dm + c * 8, 16);      // V hi
            cp16(so + 3 * AQ_ARR + sm, srcl + Dm + c * 8, 16);      // V lo
        }
    };
    load_kv(0, 0);
    cp_commit();
    cp_wait<0>();
    __syncthreads();

    const uint32_t qa_off = (uint32_t)(((wm * 16 + (lane & 15)) * AQS
                                        + ((lane >> 4) << 3)) * 2);
    uint32_t qh[4][4], ql[4][4];
    #pragma unroll
    for (int ks = 0; ks < 4; ks++) {
        ldmx4(qh[ks], sb + OFF_QHI + qa_off + ks * 32);
        ldmx4(ql[ks], sb + OFF_QLO + qa_off + ks * 32);
    }

    const uint32_t kb_off = (uint32_t)(((wn * 32 + (lane & 7) + ((lane >> 4) << 3)) * AQS
                                        + (((lane >> 3) & 1) << 3)) * 2);
    const uint32_t vb_row = (uint32_t)(wn * 32 + ((lane >> 3) & 1) * 8 + (lane & 7));
    const uint32_t vb_col = (uint32_t)((lane >> 4) << 3);

    float m0 = -1e30f, m1 = -1e30f, l0 = 0.f, l1 = 0.f;
    float oacc[8][4] = {};

    const int NKV = Ss / 64;
    for (int kt = 0; kt < NKV; kt++) {
        const int bufi = kt & 1;
        if (kt + 1 < NKV) {
            load_kv(bufi ^ 1, kt + 1);
            cp_commit();
        }
        const uint32_t sK   = sb + OFF_KV + bufi * KVBUF;
        const uint32_t sKlo = sK + AQ_ARR;
        const uint32_t sV   = sK + 2 * AQ_ARR;
        const uint32_t sVlo = sK + 3 * AQ_ARR;

        float s[4][4] = {};
        #pragma unroll
        for (int ks = 0; ks < 4; ks++) {
            uint32_t bh[2][4], bl[2][4];
            #pragma unroll
            for (int p = 0; p < 2; p++) {
                uint32_t po = (uint32_t)(p * 16 * AQS * 2) + (uint32_t)(ks * 32);
                ldmx4(bh[p], sK   + kb_off + po);
                ldmx4(bl[p], sKlo + kb_off + po);
            }
            #pragma unroll
            for (int nt = 0; nt < 4; nt++) {
                const uint32_t* bhp = &bh[nt >> 1][(nt & 1) * 2];
                const uint32_t* blp = &bl[nt >> 1][(nt & 1) * 2];
                mma_f16(s[nt], qh[ks], bhp);
                mma_f16(s[nt], qh[ks], blp);
                mma_f16(s[nt], ql[ks], bhp);
            }
        }
        #pragma unroll
        for (int nt = 0; nt < 4; nt++)
            #pragma unroll
            for (int j = 0; j < 4; j++)
                s[nt][j] *= 0.125f;

        float mx0 = -1e30f, mx1 = -1e30f;
        #pragma unroll
        for (int nt = 0; nt < 4; nt++) {
            mx0 = fmaxf(mx0, fmaxf(s[nt][0], s[nt][1]));
            mx1 = fmaxf(mx1, fmaxf(s[nt][2], s[nt][3]));
        }
        #pragma unroll
        for (int off = 1; off < 4; off <<= 1) {
            mx0 = fmaxf(mx0, __shfl_xor_sync(0xffffffffu, mx0, off));
            mx1 = fmaxf(mx1, __shfl_xor_sync(0xffffffffu, mx1, off));
        }
        if (q == 0) {
            redmax[wn * 64 + wm * 16 + g]     = mx0;
            redmax[wn * 64 + wm * 16 + 8 + g] = mx1;
        }
        __syncthreads();
        float om0 = redmax[(wn ^ 1) * 64 + wm * 16 + g];
        float om1 = redmax[(wn ^ 1) * 64 + wm * 16 + 8 + g];
        float nm0 = fmaxf(m0, fmaxf(mx0, om0));
        float nm1 = fmaxf(m1, fmaxf(mx1, om1));

        float ps0 = 0.f, ps1 = 0.f;
        #pragma unroll
        for (int nt = 0; nt < 4; nt++) {
            s[nt][0] = __expf(s[nt][0] - nm0); ps0 += s[nt][0];
            s[nt][1] = __expf(s[nt][1] - nm0); ps0 += s[nt][1];
            s[nt][2] = __expf(s[nt][2] - nm1); ps1 += s[nt][2];
            s[nt][3] = __expf(s[nt][3] - nm1); ps1 += s[nt][3];
        }
        #pragma unroll
        for (int off = 1; off < 4; off <<= 1) {
            ps0 += __shfl_xor_sync(0xffffffffu, ps0, off);
            ps1 += __shfl_xor_sync(0xffffffffu, ps1, off);
        }
        if (q == 0) {
            redsum[wn * 64 + wm * 16 + g]     = ps0;
            redsum[wn * 64 + wm * 16 + 8 + g] = ps1;
        }
        __syncthreads();
        float os0 = redsum[(wn ^ 1) * 64 + wm * 16 + g];
        float os1 = redsum[(wn ^ 1) * 64 + wm * 16 + 8 + g];
        float corr0 = __expf(m0 - nm0);
        float corr1 = __expf(m1 - nm1);
        m0 = nm0; m1 = nm1;
        l0 = l0 * corr0 + ps0 + os0;
        l1 = l1 * corr1 + ps1 + os1;
        #pragma unroll
        for (int nt = 0; nt < 8; nt++) {
            oacc[nt][0] *= corr0; oacc[nt][1] *= corr0;
            oacc[nt][2] *= corr1; oacc[nt][3] *= corr1;
        }

        #pragma unroll
        for (int sstep = 0; sstep < 2; sstep++) {
            uint32_t ph[4], pl[4];
            split2(s[2 * sstep][0],     s[2 * sstep][1],     ph[0], pl[0]);
            split2(s[2 * sstep][2],     s[2 * sstep][3],     ph[1], pl[1]);
            split2(s[2 * sstep + 1][0], s[2 * sstep + 1][1], ph[2], pl[2]);
            split2(s[2 * sstep + 1][2], s[2 * sstep + 1][3], ph[3], pl[3]);
            #pragma unroll
            for (int dp = 0; dp < 4; dp++) {
                uint32_t vh[4], vl[4];
                uint32_t va = (uint32_t)(((vb_row + sstep * 16) * AQS
                                          + dp * 16 + vb_col) * 2);
                ldmx4t(vh, sV   + va);
                ldmx4t(vl, sVlo + va);
                #pragma unroll
                for (int half = 0; half < 2; half++) {
                    int nt = dp * 2 + half;
                    const uint32_t* vhp = &vh[half * 2];
                    const uint32_t* vlp = &vl[half * 2];
                    mma_f16(oacc[nt], ph, vhp);
                    mma_f16(oacc[nt], ph, vlp);
                    mma_f16(oacc[nt], pl, vhp);
                }
            }
        }

        if (kt + 1 < NKV) {
            cp_wait<0>();
            __syncthreads();
        }
    }

    float* ob = (float*)asm_;
    __syncthreads();
    if (wn == 1) {
        #pragma unroll
        for (int nt = 0; nt < 8; nt++)
            #pragma unroll
            for (int j = 0; j < 4; j++) {
                int row = wm * 16 + g + ((j >> 1) << 3);
                int col = nt * 8 + 2 * q + (j & 1);
                ob[row * 64 + col] = oacc[nt][j];
            }
    }
    __syncthreads();
    if (wn == 0) {
        float inv0 = 1.0f / l0, inv1 = 1.0f / l1;
        #pragma unroll
        for (int nt = 0; nt < 8; nt++) {
            int col = nt * 8 + 2 * q;
            #pragma unroll
            for (int hrow = 0; hrow < 2; hrow++) {
                int row = wm * 16 + g + hrow * 8;
                float inv = hrow ? inv1 : inv0;
                float v0 = (oacc[nt][hrow * 2 + 0] + ob[row * 64 + col])     * inv;
                float v1 = (oacc[nt][hrow * 2 + 1] + ob[row * 64 + col + 1]) * inv;
                uint32_t hh, ll;
                split2(v0, v1, hh, ll);
                size_t t = (size_t)(b * Ss + qb * 64 + row);
                size_t o = t * Dm + h * 64 + col;
                *(uint32_t*)&ohi[o] = hh;
                *(uint32_t*)&olo[o] = ll;
            }
        }
    }
}

// ---------------------------------------------------------------------------
// Final combine
// ---------------------------------------------------------------------------
__global__ void combine_kernel(float* __restrict__ out,
                               const float* __restrict__ moeo,
                               const float* __restrict__ gw2)
{
    int t = blockIdx.x;
    float g0 = gw2[t * 2], g1 = gw2[t * 2 + 1];
    const float* r0 = moeo + (size_t)(t * 2) * Dm;
    const float* r1 = r0 + Dm;
    float* orow = out + (size_t)t * Dm;
    for (int d = threadIdx.x; d < Dm; d += 256)
        orow[d] += g0 * r0[d] + g1 * r1[d];
}

// ---------------------------------------------------------------------------
// Launch
// ---------------------------------------------------------------------------
extern "C" void kernel_launch(void* const* d_in, const int* in_sizes, int n_in,
                              void* d_out, int out_size)
{
    const float* x      = (const float*)d_in[0];
    const float* ln1_g  = (const float*)d_in[1];
    const float* ln1_b  = (const float*)d_in[2];
    const float* w_qkv  = (const float*)d_in[3];
    const float* b_qkv  = (const float*)d_in[4];
    const float* w_o    = (const float*)d_in[5];
    const float* b_o    = (const float*)d_in[6];
    const float* ln2_g  = (const float*)d_in[7];
    const float* ln2_b  = (const float*)d_in[8];
    const float* gate_w = (const float*)d_in[9];
    const float* gate_b = (const float*)d_in[10];
    const float* W1     = (const float*)d_in[11];
    const float* b1     = (const float*)d_in[12];
    const float* W2     = (const float*)d_in[13];
    const float* b2     = (const float*)d_in[14];
    float* out = (float*)d_out;

    float *moeo, *gwp;
    int *cnt, *tok, *dst;
    __half *h1hi, *h1lo, *qkvhi, *qkvlo, *atthi, *attlo, *h2hi, *hidhi;
    __half *wqkvThi, *wqkvTlo, *woThi, *woTlo, *W1Thi, *W2Thi;
    cudaGetSymbolAddress((void**)&moeo,  g_moeo);
    cudaGetSymbolAddress((void**)&cnt,   g_cnt);
    cudaGetSymbolAddress((void**)&tok,   g_tok);
    cudaGetSymbolAddress((void**)&dst,   g_dst);
    cudaGetSymbolAddress((void**)&gwp,   g_gw);
    cudaGetSymbolAddress((void**)&h1hi,  g_h1hi);
    cudaGetSymbolAddress((void**)&h1lo,  g_h1lo);
    cudaGetSymbolAddress((void**)&qkvhi, g_qkvhi);
    cudaGetSymbolAddress((void**)&qkvlo, g_qkvlo);
    cudaGetSymbolAddress((void**)&atthi, g_atthi);
    cudaGetSymbolAddress((void**)&attlo, g_attlo);
    cudaGetSymbolAddress((void**)&h2hi,  g_h2hi);
    cudaGetSymbolAddress((void**)&hidhi, g_hidhi);
    cudaGetSymbolAddress((void**)&wqkvThi, g_wqkvThi);
    cudaGetSymbolAddress((void**)&wqkvTlo, g_wqkvTlo);
    cudaGetSymbolAddress((void**)&woThi, g_woThi);
    cudaGetSymbolAddress((void**)&woTlo, g_woTlo);
    cudaGetSymbolAddress((void**)&W1Thi, g_W1Thi);
    cudaGetSymbolAddress((void**)&W2Thi, g_W2Thi);

    static bool attr_done = false;
    if (!attr_done) {
        cudaFuncSetAttribute(attn_tc,
                             cudaFuncAttributeMaxDynamicSharedMemorySize, ATT_SMEM);
        cudaFuncSetAttribute(gemm_split<false, false, false, 1, 3>,
                             cudaFuncAttributeMaxDynamicSharedMemorySize, GEMM_SMEM);
        cudaFuncSetAttribute(gemm_split<false, false, true, 0, 3>,
                             cudaFuncAttributeMaxDynamicSharedMemorySize, GEMM_SMEM);
        cudaFuncSetAttribute(gemm_split<true, true, false, 2, 1>,
                             cudaFuncAttributeMaxDynamicSharedMemorySize, GEMM_SMEM);
        cudaFuncSetAttribute(gemm_split<true, false, false, 0, 1>,
                             cudaFuncAttributeMaxDynamicSharedMemorySize, GEMM_SMEM);
        attr_done = true;
    }

    cudaMemsetAsync(cnt, 0, Ee * sizeof(int));

    // 0) weight transpose + split (wqkv & wo: hi+lo for 3-term; W1/W2 hi only)
    convT_kernel<<<dim3(3 * Dm / 32, Dm / 64, 1), 256>>>(w_qkv, wqkvThi, wqkvTlo, Dm, 3 * Dm);
    convT_kernel<<<dim3(Dm / 32, Dm / 64, 1), 256>>>(w_o, woThi, woTlo, Dm, Dm);
    convT_kernel<<<dim3(DFFf / 32, Dm / 64, Ee), 256>>>(W1, W1Thi, nullptr, Dm, DFFf);
    convT_kernel<<<dim3(Dm / 32, DFFf / 64, Ee), 256>>>(W2, W2Thi, nullptr, DFFf, Dm);

    // 1) LN1 -> fp16 hi/lo
    ln_kernel<<<Tt, 256>>>(x, ln1_g, ln1_b, h1hi, h1lo);

    // 2) QKV (3-term, gate-upstream) -> fp16 hi/lo
    gemm_split<false, false, false, 1, 3><<<dim3(3 * Dm / 128, Tt / 128), 256, GEMM_SMEM>>>(
        h1hi, h1lo, wqkvThi, wqkvTlo, nullptr, qkvhi, qkvlo,
        b_qkv, nullptr, nullptr, nullptr, nullptr, Tt, Dm, 3 * Dm);

    // 3) attention (3-term both stages, gate-upstream) -> fp16 hi/lo
    attn_tc<<<dim3(Ss / 64, Hh, Bb), 256, ATT_SMEM>>>(qkvhi, qkvlo, atthi, attlo);

    // 4) x1 = x + attno @ w_o + b_o (3-term, gate-upstream, fp32 -> d_out)
    gemm_split<false, false, true, 0, 3><<<dim3(Dm / 128, Tt / 128), 256, GEMM_SMEM>>>(
        atthi, attlo, woThi, woTlo, out, nullptr, nullptr,
        b_o, x, nullptr, nullptr, nullptr, Tt, Dm, Dm);

    // 5+6) fused LN2 + gate + routing (logits fp32-exact)
    ln2_gate_kernel<<<Tt, 256>>>(out, ln2_g, ln2_b, gate_w, gate_b,
                                 h2hi, cnt, tok, dst, gwp);

    // 7) MoE FFN1 (1-term plain fp16, 4-stage pipeline) -> fp16 hi
    gemm_split<true, true, false, 2, 1><<<dim3(DFFf / 128, LISTCAP / 128, Ee), 256, GEMM_SMEM>>>(
        h2hi, nullptr, W1Thi, nullptr, nullptr, hidhi, nullptr,
        b1, nullptr, tok, dst, cnt, 0, Dm, DFFf);

    // 8) MoE FFN2 (1-term plain fp16, 4-stage pipeline, fp32 out)
    gemm_split<true, false, false, 0, 1><<<dim3(Dm / 128, LISTCAP / 128, Ee), 256, GEMM_SMEM>>>(
        hidhi, nullptr, W2Thi, nullptr, moeo, nullptr, nullptr,
        b2, nullptr, dst, dst, cnt, 0, DFFf, Dm);

    // 9) combine
    combine_kernel<<<Tt, 256>>>(out, moeo, gwp);
}